// round 8
// baseline (speedup 1.0000x reference)
#include <cuda_runtime.h>
#include <math.h>
#include <stdint.h>

// Problem constants
#define Bb   16
#define Tt   512
#define Dd   2048
#define Hh   4
#define HDd  512
#define BT   8192          // B*T rows
#define NQKV 6144          // 3*D
#define DFF  8192          // 4*D
#define LNEPS 1e-5f

// ---------------------------------------------------------------------------
// Scratch (static __device__ arrays; no allocation allowed)
// ---------------------------------------------------------------------------
__device__ __align__(128) float g_Wqkv[(size_t)Dd * NQKV];
__device__ __align__(128) float g_ln[(size_t)BT * Dd];
__device__ __align__(128) float g_qkv[(size_t)BT * NQKV];
__device__ __align__(128) float g_scores[(size_t)Bb * Hh * Tt * Tt];
__device__ __align__(128) float g_ctx[(size_t)BT * Dd];
__device__ __align__(128) float g_ffn[(size_t)BT * DFF];
__device__ __align__(128) float g_Wot[(size_t)Dd * Dd];
__device__ __align__(128) float g_W1t[(size_t)Dd * DFF];
__device__ __align__(128) float g_W2t[(size_t)DFF * Dd];

// ---------------------------------------------------------------------------
// PTX helpers
// ---------------------------------------------------------------------------
__device__ __forceinline__ void cp_async16(void* smem_dst, const void* gmem_src) {
    uint32_t dst = (uint32_t)__cvta_generic_to_shared(smem_dst);
    asm volatile("cp.async.cg.shared.global [%0], [%1], 16;\n" :: "r"(dst), "l"(gmem_src));
}
__device__ __forceinline__ void cp_commit() {
    asm volatile("cp.async.commit_group;\n");
}
template<int N>
__device__ __forceinline__ void cp_wait() {
    asm volatile("cp.async.wait_group %0;\n" :: "n"(N));
}
__device__ __forceinline__ float roundtf(float f) {
    uint32_t r;
    asm("cvt.rna.tf32.f32 %0, %1;" : "=r"(r) : "f"(f));
    return __uint_as_float(r);
}
__device__ __forceinline__ void mma_tf32(float* c, const uint32_t* a, const uint32_t* b) {
    asm volatile(
        "mma.sync.aligned.m16n8k8.row.col.f32.tf32.tf32.f32 "
        "{%0,%1,%2,%3}, {%4,%5,%6,%7}, {%8,%9}, {%0,%1,%2,%3};"
        : "+f"(c[0]), "+f"(c[1]), "+f"(c[2]), "+f"(c[3])
        : "r"(a[0]), "r"(a[1]), "r"(a[2]), "r"(a[3]), "r"(b[0]), "r"(b[1]));
}

// ---------------------------------------------------------------------------
// Round-to-tf32 copy (for raw weight matrices)
// ---------------------------------------------------------------------------
__global__ void round_copy_kernel(const float4* __restrict__ in,
                                  float4* __restrict__ out, int n4) {
    int i = blockIdx.x * 256 + threadIdx.x;
    if (i >= n4) return;
    float4 v = in[i];
    v.x = roundtf(v.x); v.y = roundtf(v.y);
    v.z = roundtf(v.z); v.w = roundtf(v.w);
    out[i] = v;
}

// ---------------------------------------------------------------------------
// Repack Wq/Wk/Wv [H,D,HD] into one row-major [D, 3*D] matrix (tf32-rounded)
// ---------------------------------------------------------------------------
__global__ void repack_qkv_kernel(const float* __restrict__ Wq,
                                  const float* __restrict__ Wk,
                                  const float* __restrict__ Wv,
                                  float* __restrict__ out) {
    int idx = blockIdx.x * 256 + threadIdx.x;
    int k = idx / NQKV;
    int n = idx - k * NQKV;
    int sel = n >> 11;
    int nn  = n & 2047;
    int h   = nn >> 9;
    int c   = nn & 511;
    const float* W = (sel == 0) ? Wq : (sel == 1) ? Wk : Wv;
    out[idx] = roundtf(W[((size_t)h * Dd + k) * HDd + c]);
}

// ---------------------------------------------------------------------------
// LayerNorm: one block per row (D=2048), 256 threads. Output tf32-rounded
// (consumed only as a tf32 GEMM A operand).
// ---------------------------------------------------------------------------
__global__ void ln_kernel(const float* __restrict__ x,
                          const float* __restrict__ g,
                          const float* __restrict__ b,
                          float* __restrict__ out) {
    int row = blockIdx.x;
    int t   = threadIdx.x;
    const float4* xr = (const float4*)(x + (size_t)row * Dd);
    float4 v0 = xr[t];
    float4 v1 = xr[t + 256];
    float s  = v0.x + v0.y + v0.z + v0.w + v1.x + v1.y + v1.z + v1.w;
    float sq = v0.x*v0.x + v0.y*v0.y + v0.z*v0.z + v0.w*v0.w
             + v1.x*v1.x + v1.y*v1.y + v1.z*v1.z + v1.w*v1.w;
    #pragma unroll
    for (int o = 16; o; o >>= 1) {
        s  += __shfl_xor_sync(0xffffffffu, s,  o);
        sq += __shfl_xor_sync(0xffffffffu, sq, o);
    }
    __shared__ float ss[8], ssq[8];
    int w = t >> 5;
    if ((t & 31) == 0) { ss[w] = s; ssq[w] = sq; }
    __syncthreads();
    float S = 0.f, SQ = 0.f;
    #pragma unroll
    for (int i = 0; i < 8; i++) { S += ss[i]; SQ += ssq[i]; }
    float mean = S * (1.f / Dd);
    float var  = SQ * (1.f / Dd) - mean * mean;
    float rstd = rsqrtf(var + LNEPS);

    const float4* gr = (const float4*)g;
    const float4* br = (const float4*)b;
    float4* o4 = (float4*)(out + (size_t)row * Dd);
    float4 gv = gr[t], bv = br[t], r;
    r.x = roundtf((v0.x - mean) * rstd * gv.x + bv.x);
    r.y = roundtf((v0.y - mean) * rstd * gv.y + bv.y);
    r.z = roundtf((v0.z - mean) * rstd * gv.z + bv.z);
    r.w = roundtf((v0.w - mean) * rstd * gv.w + bv.w);
    o4[t] = r;
    gv = gr[t + 256]; bv = br[t + 256];
    r.x = roundtf((v1.x - mean) * rstd * gv.x + bv.x);
    r.y = roundtf((v1.y - mean) * rstd * gv.y + bv.y);
    r.z = roundtf((v1.z - mean) * rstd * gv.z + bv.z);
    r.w = roundtf((v1.w - mean) * rstd * gv.w + bv.w);
    o4[t + 256] = r;
}

// ---------------------------------------------------------------------------
// tf32 tensor-core NN GEMM: C = A@B (+bias)(+resid)(relu)(round_out)
// CTA tile 128x256x16, 256 threads = 8 warps (2m x 4n), warp tile 64x64.
// Per warp-ktile: 64 LDS + 64 MMA (1.0 LDS/MMA vs 1.5 in the 64x32 version).
// Inputs MUST already be tf32-rounded fp32 — no cvt in the hot loop.
// 3-stage cp.async pipeline, one __syncthreads per k-tile.
// round_out: 0 = fp32 out, 1 = tf32-round all, 2 = tf32-round cols >= 4096
// (the V block of the packed QKV output; q,k stay fp32 for the scores kernel).
// Batched over blockIdx.z with offsets sX1*(z/4) + sX2*(z%4).
// ---------------------------------------------------------------------------
#define APAD 20    // As row stride in floats
#define BPAD 264   // Bs row stride in floats (256 + 8)
#define STAGES 3

__global__ void __launch_bounds__(256)
tgemm_nn(const float* __restrict__ A, int lda, long long sA1, long long sA2,
         const float* __restrict__ B, int ldb, long long sB1, long long sB2,
         float* __restrict__ C, int ldc, long long sC1, long long sC2,
         int K,
         const float* __restrict__ bias,
         const float* __restrict__ resid, int ldr,
         int relu, int round_out) {
    int z  = blockIdx.z;
    int zb = z >> 2, zh = z & 3;
    A += sA1 * zb + sA2 * zh;
    B += sB1 * zb + sB2 * zh;
    C += sC1 * zb + sC2 * zh;

    const int m0 = blockIdx.y * 128;
    const int n0 = blockIdx.x * 256;
    const int tid  = threadIdx.x;
    const int lane = tid & 31;
    const int wid  = tid >> 5;
    const int g  = lane >> 2;        // groupID
    const int t4 = lane & 3;         // threadID in group
    const int mw = (wid >> 2) * 64;  // warp m offset (2 rows of warps)
    const int nw = (wid & 3) * 64;   // warp n offset (4 cols of warps)

    __shared__ __align__(16) float As[STAGES][128 * APAD];
    __shared__ __align__(16) float Bs[STAGES][16 * BPAD];

    // A tile 128x16: 512 16B-chunks, 2 per thread
    const int a_row0 = tid >> 2;          // 0..63
    const int a_ch0  = (tid & 3) * 4;
    const int a_row1 = a_row0 + 64;
    // B tile 16x256: 1024 16B-chunks, 4 per thread (rows r, r+4, r+8, r+12)
    const int b_row0 = tid >> 6;          // 0..3
    const int b_ch0  = (tid & 63) * 4;    // 0..252

    auto issue = [&](int kt, int buf) {
        cp_async16(&As[buf][a_row0 * APAD + a_ch0],
                   A + (size_t)(m0 + a_row0) * lda + kt * 16 + a_ch0);
        cp_async16(&As[buf][a_row1 * APAD + a_ch0],
                   A + (size_t)(m0 + a_row1) * lda + kt * 16 + a_ch0);
        #pragma unroll
        for (int p = 0; p < 4; p++) {
            int br = b_row0 + p * 4;
            cp_async16(&Bs[buf][br * BPAD + b_ch0],
                       B + (size_t)(kt * 16 + br) * ldb + n0 + b_ch0);
        }
        cp_commit();
    };

    float acc[4][8][4];
    #pragma unroll
    for (int mi = 0; mi < 4; mi++)
        #pragma unroll
        for (int ni = 0; ni < 8; ni++)
            #pragma unroll
            for (int q = 0; q < 4; q++) acc[mi][ni][q] = 0.f;

    const int nk = K >> 4;   // all call sites have nk >= 32
    issue(0, 0);
    issue(1, 1);

    for (int kt = 0; kt < nk; kt++) {
        const int cur = kt % STAGES;
        cp_wait<STAGES - 2>();     // tile kt resident (kt+1 may be in flight)
        __syncthreads();           // all warps done with buffer (kt+2)%3
        if (kt + 2 < nk) issue(kt + 2, (kt + 2) % STAGES);

        const float* __restrict__ Asc = As[cur];
        const float* __restrict__ Bsc = Bs[cur];
        #pragma unroll
        for (int ks = 0; ks < 2; ks++) {
            uint32_t af[4][4], bf[8][2];
            const int col = ks * 8 + t4;
            #pragma unroll
            for (int mi = 0; mi < 4; mi++) {
                const int r = mw + mi * 16 + g;
                af[mi][0] = __float_as_uint(Asc[r * APAD + col]);
                af[mi][1] = __float_as_uint(Asc[(r + 8) * APAD + col]);
                af[mi][2] = __float_as_uint(Asc[r * APAD + col + 4]);
                af[mi][3] = __float_as_uint(Asc[(r + 8) * APAD + col + 4]);
            }
            #pragma unroll
            for (int ni = 0; ni < 8; ni++) {
                const int cc = nw + ni * 8 + g;
                bf[ni][0] = __float_as_uint(Bsc[col * BPAD + cc]);
                bf[ni][1] = __float_as_uint(Bsc[(col + 4) * BPAD + cc]);
            }
            #pragma unroll
            for (int mi = 0; mi < 4; mi++)
                #pragma unroll
                for (int ni = 0; ni < 8; ni++)
                    mma_tf32(acc[mi][ni], af[mi], bf[ni]);
        }
    }

    // Epilogue
    #pragma unroll
    for (int mi = 0; mi < 4; mi++) {
        const int r0 = m0 + mw + mi * 16 + g;
        #pragma unroll
        for (int ni = 0; ni < 8; ni++) {
            const int c0 = n0 + nw + ni * 8 + t4 * 2;
            float bb0 = 0.f, bb1 = 0.f;
            if (bias) { bb0 = bias[c0]; bb1 = bias[c0 + 1]; }
            float v0 = acc[mi][ni][0] + bb0;
            float v1 = acc[mi][ni][1] + bb1;
            float v2 = acc[mi][ni][2] + bb0;
            float v3 = acc[mi][ni][3] + bb1;
            if (resid) {
                const float* R0 = resid + (size_t)r0 * ldr + c0;
                const float* R1 = resid + (size_t)(r0 + 8) * ldr + c0;
                v0 += R0[0]; v1 += R0[1];
                v2 += R1[0]; v3 += R1[1];
            }
            if (relu) {
                v0 = fmaxf(v0, 0.f); v1 = fmaxf(v1, 0.f);
                v2 = fmaxf(v2, 0.f); v3 = fmaxf(v3, 0.f);
            }
            if (round_out == 1 || (round_out == 2 && c0 >= 4096)) {
                v0 = roundtf(v0); v1 = roundtf(v1);
                v2 = roundtf(v2); v3 = roundtf(v3);
            }
            *(float2*)&C[(size_t)r0 * ldc + c0]       = make_float2(v0, v1);
            *(float2*)&C[(size_t)(r0 + 8) * ldc + c0] = make_float2(v2, v3);
        }
    }
}

// ---------------------------------------------------------------------------
// Scores (fp32): S = scale * q k^T, causal mask. 64x64 tiles, NT.
// q,k arrive in full fp32 precision (QKV GEMM does NOT round them).
// ---------------------------------------------------------------------------
__global__ void __launch_bounds__(256)
scores_nt_kernel(const float* __restrict__ QKV, float* __restrict__ S) {
    int z = blockIdx.z;
    int bb = z >> 2, hh = z & 3;
    const float* Aq = QKV + (size_t)bb * Tt * NQKV + hh * HDd;
    const float* Ak = Aq + Dd;
    float* Cs = S + (size_t)z * Tt * Tt;

    const int m0 = blockIdx.y * 64;
    const int n0 = blockIdx.x * 64;
    const int tid = threadIdx.x;
    const int ty = tid >> 4, tx = tid & 15;

    if (n0 > m0) {
        #pragma unroll
        for (int i = 0; i < 4; i++) {
            int gi = m0 + ty * 4 + i;
            float4 mm; mm.x = mm.y = mm.z = mm.w = -1e30f;
            *(float4*)&Cs[(size_t)gi * Tt + n0 + tx * 4] = mm;
        }
        return;
    }

    __shared__ __align__(16) float As[2][16][64];
    __shared__ __align__(16) float Bs[2][16][64];

    const int lrow = tid >> 2;
    const int lcol = (tid & 3) * 4;

    float4 ra, rb;
    auto loadT = [&](int kt) {
        ra = *(const float4*)(Aq + (size_t)(m0 + lrow) * NQKV + kt * 16 + lcol);
        rb = *(const float4*)(Ak + (size_t)(n0 + lrow) * NQKV + kt * 16 + lcol);
    };
    auto storeT = [&](int buf) {
        As[buf][lcol + 0][lrow] = ra.x; As[buf][lcol + 1][lrow] = ra.y;
        As[buf][lcol + 2][lrow] = ra.z; As[buf][lcol + 3][lrow] = ra.w;
        Bs[buf][lcol + 0][lrow] = rb.x; Bs[buf][lcol + 1][lrow] = rb.y;
        Bs[buf][lcol + 2][lrow] = rb.z; Bs[buf][lcol + 3][lrow] = rb.w;
    };

    float acc[4][4];
    #pragma unroll
    for (int i = 0; i < 4; i++)
        #pragma unroll
        for (int j = 0; j < 4; j++) acc[i][j] = 0.f;

    loadT(0); storeT(0);
    __syncthreads();

    const int nk = HDd / 16;
    for (int kt = 0; kt < nk; kt++) {
        int cur = kt & 1;
        if (kt + 1 < nk) loadT(kt + 1);
        #pragma unroll
        for (int kk = 0; kk < 16; kk++) {
            float a[4], bvv[4];
            *(float4*)a   = *(const float4*)&As[cur][kk][ty * 4];
            *(float4*)bvv = *(const float4*)&Bs[cur][kk][tx * 4];
            #pragma unroll
            for (int i = 0; i < 4; i++)
                #pragma unroll
                for (int j = 0; j < 4; j++)
                    acc[i][j] += a[i] * bvv[j];
        }
        if (kt + 1 < nk) {
            storeT(cur ^ 1);
            __syncthreads();
        }
    }

    const float scale = 0.044194173824159216f;
    #pragma unroll
    for (int i = 0; i < 4; i++) {
        int gi = m0 + ty * 4 + i;
        float v[4];
        #pragma unroll
        for (int j = 0; j < 4; j++) {
            int gj = n0 + tx * 4 + j;
            v[j] = (gj > gi) ? -1e30f : acc[i][j] * scale;
        }
        float4 o; o.x = v[0]; o.y = v[1]; o.z = v[2]; o.w = v[3];
        *(float4*)&Cs[(size_t)gi * Tt + n0 + tx * 4] = o;
    }
}

// ---------------------------------------------------------------------------
// Row softmax over T=512 entries. Output tf32-rounded (GEMM A operand only).
// ---------------------------------------------------------------------------
__global__ void softmax_kernel(float* __restrict__ S) {
    int row = blockIdx.x;
    int t = threadIdx.x;
    float4* p = (float4*)(S + (size_t)row * Tt);
    float4 v = p[t];
    float m = fmaxf(fmaxf(v.x, v.y), fmaxf(v.z, v.w));
    #pragma unroll
    for (int o = 16; o; o >>= 1) m = fmaxf(m, __shfl_xor_sync(0xffffffffu, m, o));
    __shared__ float sm[4], ssum[4];
    int w = t >> 5;
    if ((t & 31) == 0) sm[w] = m;
    __syncthreads();
    m = fmaxf(fmaxf(sm[0], sm[1]), fmaxf(sm[2], sm[3]));
    v.x = expf(v.x - m); v.y = expf(v.y - m);
    v.z = expf(v.z - m); v.w = expf(v.w - m);
    float s = v.x + v.y + v.z + v.w;
    #pragma unroll
    for (int o = 16; o; o >>= 1) s += __shfl_xor_sync(0xffffffffu, s, o);
    if ((t & 31) == 0) ssum[w] = s;
    __syncthreads();
    s = ssum[0] + ssum[1] + ssum[2] + ssum[3];
    float inv = 1.f / s;
    v.x = roundtf(v.x * inv); v.y = roundtf(v.y * inv);
    v.z = roundtf(v.z * inv); v.w = roundtf(v.w * inv);
    p[t] = v;
}

// ---------------------------------------------------------------------------
// Host launcher
// ---------------------------------------------------------------------------
extern "C" void kernel_launch(void* const* d_in, const int* in_sizes, int n_in,
                              void* d_out, int out_size) {
    const float* x   = (const float*)d_in[0];
    const float* Wq  = (const float*)d_in[1];
    const float* Wk  = (const float*)d_in[2];
    const float* Wv  = (const float*)d_in[3];
    const float* Wo  = (const float*)d_in[4];
    const float* bo  = (const float*)d_in[5];
    const float* W1  = (const float*)d_in[6];
    const float* b1  = (const float*)d_in[7];
    const float* W2  = (const float*)d_in[8];
    const float* b2  = (const float*)d_in[9];
    const float* g1  = (const float*)d_in[10];
    const float* be1 = (const float*)d_in[11];
    const float* g2  = (const float*)d_in[12];
    const float* be2 = (const float*)d_in[13];
    float* out = (float*)d_out;

    float *p_wqkv, *p_ln, *p_qkv, *p_sc, *p_ctx, *p_ffn, *p_wot, *p_w1t, *p_w2t;
    cudaGetSymbolAddress((void**)&p_wqkv, g_Wqkv);
    cudaGetSymbolAddress((void**)&p_ln,   g_ln);
    cudaGetSymbolAddress((void**)&p_qkv,  g_qkv);
    cudaGetSymbolAddress((void**)&p_sc,   g_scores);
    cudaGetSymbolAddress((void**)&p_ctx,  g_ctx);
    cudaGetSymbolAddress((void**)&p_ffn,  g_ffn);
    cudaGetSymbolAddress((void**)&p_wot,  g_Wot);
    cudaGetSymbolAddress((void**)&p_w1t,  g_W1t);
    cudaGetSymbolAddress((void**)&p_w2t,  g_W2t);

    // 0) tf32-round weight copies
    round_copy_kernel<<<(Dd * Dd / 4 + 255) / 256, 256>>>(
        (const float4*)Wo, (float4*)p_wot, Dd * Dd / 4);
    round_copy_kernel<<<(Dd * DFF / 4 + 255) / 256, 256>>>(
        (const float4*)W1, (float4*)p_w1t, Dd * DFF / 4);
    round_copy_kernel<<<(DFF * Dd / 4 + 255) / 256, 256>>>(
        (const float4*)W2, (float4*)p_w2t, DFF * Dd / 4);

    // 1) repack QKV weights -> [D, 3D] (tf32-rounded)
    repack_qkv_kernel<<<(Dd * NQKV) / 256, 256>>>(Wq, Wk, Wv, p_wqkv);

    // 2) h = LN(x) (tf32-rounded)
    ln_kernel<<<BT, 256>>>(x, g1, be1, p_ln);

    // 3) QKV = h @ Wqkv. round_out=2: round ONLY the v block (cols >= 4096);
    //    q,k stay fp32 for the scores kernel.
    tgemm_nn<<<dim3(NQKV / 256, BT / 128, 1), 256>>>(
        p_ln, Dd, 0, 0,
        p_wqkv, NQKV, 0, 0,
        p_qkv, NQKV, 0, 0,
        Dd, nullptr, nullptr, 0, 0, 2);

    // 4) scores = scale * q k^T with causal mask (full fp32)
    scores_nt_kernel<<<dim3(Tt / 64, Tt / 64, Bb * Hh), 256>>>(p_qkv, p_sc);

    // 5) softmax rows (tf32-rounded probs)
    softmax_kernel<<<Bb * Hh * Tt, 128>>>(p_sc);

    // 6) ctx_cat = attn @ v (round_out: feeds Wo GEMM)
    tgemm_nn<<<dim3(HDd / 256, Tt / 128, Bb * Hh), 256>>>(
        p_sc, Tt, (long long)Hh * Tt * Tt, (long long)Tt * Tt,
        p_qkv + 2 * Dd, NQKV, (long long)Tt * NQKV, HDd,
        p_ctx, Dd, (long long)Tt * Dd, HDd,
        HDd, nullptr, nullptr, 0, 0, 1);

    // 7) x2 = x + ctx_cat @ Wo + bo -> d_out (full fp32 output)
    tgemm_nn<<<dim3(Dd / 256, BT / 128, 1), 256>>>(
        p_ctx, Dd, 0, 0,
        p_wot, Dd, 0, 0,
        out, Dd, 0, 0,
        Dd, bo, x, Dd, 0, 0);

    // 8) h2 = LN(x2) (tf32-rounded)
    ln_kernel<<<BT, 256>>>(out, g2, be2, p_ln);

    // 9) u = relu(h2 @ W1 + b1) (round_out: feeds W2 GEMM)
    tgemm_nn<<<dim3(DFF / 256, BT / 128, 1), 256>>>(
        p_ln, Dd, 0, 0,
        p_w1t, DFF, 0, 0,
        p_ffn, DFF, 0, 0,
        Dd, b1, nullptr, 0, 1, 1);

    // 10) out = x2 + u @ W2 + b2 (resid = d_out in place, fp32 output)
    tgemm_nn<<<dim3(Dd / 256, BT / 128, 1), 256>>>(
        p_ffn, DFF, 0, 0,
        p_w2t, Dd, 0, 0,
        out, Dd, 0, 0,
        DFF, b2, out, Dd, 0, 0);
}

// round 9
// speedup vs baseline: 1.0869x; 1.0869x over previous
#include <cuda_runtime.h>
#include <math.h>
#include <stdint.h>

// Problem constants
#define Bb   16
#define Tt   512
#define Dd   2048
#define Hh   4
#define HDd  512
#define BT   8192          // B*T rows
#define NQKV 6144          // 3*D
#define DFF  8192          // 4*D
#define LNEPS 1e-5f

// ---------------------------------------------------------------------------
// Scratch (static __device__ arrays; no allocation allowed)
// ---------------------------------------------------------------------------
__device__ __align__(128) float g_Wqkv[(size_t)Dd * NQKV];
__device__ __align__(128) float g_ln[(size_t)BT * Dd];
__device__ __align__(128) float g_qkv[(size_t)BT * NQKV];
__device__ __align__(128) float g_scores[(size_t)Bb * Hh * Tt * Tt];
__device__ __align__(128) float g_ctx[(size_t)BT * Dd];
__device__ __align__(128) float g_ffn[(size_t)BT * DFF];
__device__ __align__(128) float g_Wot[(size_t)Dd * Dd];
__device__ __align__(128) float g_W1t[(size_t)Dd * DFF];
__device__ __align__(128) float g_W2t[(size_t)DFF * Dd];

// ---------------------------------------------------------------------------
// PTX helpers
// ---------------------------------------------------------------------------
__device__ __forceinline__ void cp_async16(void* smem_dst, const void* gmem_src) {
    uint32_t dst = (uint32_t)__cvta_generic_to_shared(smem_dst);
    asm volatile("cp.async.cg.shared.global [%0], [%1], 16;\n" :: "r"(dst), "l"(gmem_src));
}
__device__ __forceinline__ void cp_commit() {
    asm volatile("cp.async.commit_group;\n");
}
template<int N>
__device__ __forceinline__ void cp_wait() {
    asm volatile("cp.async.wait_group %0;\n" :: "n"(N));
}
__device__ __forceinline__ float roundtf(float f) {
    uint32_t r;
    asm("cvt.rna.tf32.f32 %0, %1;" : "=r"(r) : "f"(f));
    return __uint_as_float(r);
}
__device__ __forceinline__ void mma_tf32(float* c, const uint32_t* a, const uint32_t* b) {
    asm volatile(
        "mma.sync.aligned.m16n8k8.row.col.f32.tf32.tf32.f32 "
        "{%0,%1,%2,%3}, {%4,%5,%6,%7}, {%8,%9}, {%0,%1,%2,%3};"
        : "+f"(c[0]), "+f"(c[1]), "+f"(c[2]), "+f"(c[3])
        : "r"(a[0]), "r"(a[1]), "r"(a[2]), "r"(a[3]), "r"(b[0]), "r"(b[1]));
}
// ldmatrix x4 on fp32 data viewed as b16: loads one m16k8 tf32 A-fragment.
__device__ __forceinline__ void ldsm_x4(uint32_t& r0, uint32_t& r1,
                                        uint32_t& r2, uint32_t& r3,
                                        uint32_t smem_addr) {
    asm volatile(
        "ldmatrix.sync.aligned.m8n8.x4.shared.b16 {%0,%1,%2,%3}, [%4];"
        : "=r"(r0), "=r"(r1), "=r"(r2), "=r"(r3) : "r"(smem_addr));
}

// ---------------------------------------------------------------------------
// Round-to-tf32 copy (for raw weight matrices)
// ---------------------------------------------------------------------------
__global__ void round_copy_kernel(const float4* __restrict__ in,
                                  float4* __restrict__ out, int n4) {
    int i = blockIdx.x * 256 + threadIdx.x;
    if (i >= n4) return;
    float4 v = in[i];
    v.x = roundtf(v.x); v.y = roundtf(v.y);
    v.z = roundtf(v.z); v.w = roundtf(v.w);
    out[i] = v;
}

// ---------------------------------------------------------------------------
// Repack Wq/Wk/Wv [H,D,HD] into one row-major [D, 3*D] matrix (tf32-rounded)
// ---------------------------------------------------------------------------
__global__ void repack_qkv_kernel(const float* __restrict__ Wq,
                                  const float* __restrict__ Wk,
                                  const float* __restrict__ Wv,
                                  float* __restrict__ out) {
    int idx = blockIdx.x * 256 + threadIdx.x;
    int k = idx / NQKV;
    int n = idx - k * NQKV;
    int sel = n >> 11;
    int nn  = n & 2047;
    int h   = nn >> 9;
    int c   = nn & 511;
    const float* W = (sel == 0) ? Wq : (sel == 1) ? Wk : Wv;
    out[idx] = roundtf(W[((size_t)h * Dd + k) * HDd + c]);
}

// ---------------------------------------------------------------------------
// LayerNorm: one block per row (D=2048), 256 threads. Output tf32-rounded
// (consumed only as a tf32 GEMM A operand).
// ---------------------------------------------------------------------------
__global__ void ln_kernel(const float* __restrict__ x,
                          const float* __restrict__ g,
                          const float* __restrict__ b,
                          float* __restrict__ out) {
    int row = blockIdx.x;
    int t   = threadIdx.x;
    const float4* xr = (const float4*)(x + (size_t)row * Dd);
    float4 v0 = xr[t];
    float4 v1 = xr[t + 256];
    float s  = v0.x + v0.y + v0.z + v0.w + v1.x + v1.y + v1.z + v1.w;
    float sq = v0.x*v0.x + v0.y*v0.y + v0.z*v0.z + v0.w*v0.w
             + v1.x*v1.x + v1.y*v1.y + v1.z*v1.z + v1.w*v1.w;
    #pragma unroll
    for (int o = 16; o; o >>= 1) {
        s  += __shfl_xor_sync(0xffffffffu, s,  o);
        sq += __shfl_xor_sync(0xffffffffu, sq, o);
    }
    __shared__ float ss[8], ssq[8];
    int w = t >> 5;
    if ((t & 31) == 0) { ss[w] = s; ssq[w] = sq; }
    __syncthreads();
    float S = 0.f, SQ = 0.f;
    #pragma unroll
    for (int i = 0; i < 8; i++) { S += ss[i]; SQ += ssq[i]; }
    float mean = S * (1.f / Dd);
    float var  = SQ * (1.f / Dd) - mean * mean;
    float rstd = rsqrtf(var + LNEPS);

    const float4* gr = (const float4*)g;
    const float4* br = (const float4*)b;
    float4* o4 = (float4*)(out + (size_t)row * Dd);
    float4 gv = gr[t], bv = br[t], r;
    r.x = roundtf((v0.x - mean) * rstd * gv.x + bv.x);
    r.y = roundtf((v0.y - mean) * rstd * gv.y + bv.y);
    r.z = roundtf((v0.z - mean) * rstd * gv.z + bv.z);
    r.w = roundtf((v0.w - mean) * rstd * gv.w + bv.w);
    o4[t] = r;
    gv = gr[t + 256]; bv = br[t + 256];
    r.x = roundtf((v1.x - mean) * rstd * gv.x + bv.x);
    r.y = roundtf((v1.y - mean) * rstd * gv.y + bv.y);
    r.z = roundtf((v1.z - mean) * rstd * gv.z + bv.z);
    r.w = roundtf((v1.w - mean) * rstd * gv.w + bv.w);
    o4[t + 256] = r;
}

// ---------------------------------------------------------------------------
// tf32 tensor-core NN GEMM: C = A@B (+bias)(+resid)(relu)(round_out)
// CTA tile 128x128x16, 256 threads = 8 warps (2m x 4n), warp tile 64x32
// (Round-7 proven config: 2 CTAs/SM). A-fragments via ldmatrix.x4 (tf32
// viewed as b16): 8 LDSM + 16 LDS per warp-ktile instead of 48 LDS.
// APAD=20 makes the 8 LDSM row addresses hit distinct banks.
// Inputs MUST already be tf32-rounded fp32 — no cvt in the hot loop.
// 3-stage cp.async pipeline, one __syncthreads per k-tile.
// round_out: 0 = fp32 out, 1 = tf32-round all, 2 = tf32-round cols >= 4096.
// Batched over blockIdx.z with offsets sX1*(z/4) + sX2*(z%4).
// ---------------------------------------------------------------------------
#define APAD 20    // As row stride in floats
#define BPAD 136   // Bs row stride in floats
#define STAGES 3

__global__ void __launch_bounds__(256, 2)
tgemm_nn(const float* __restrict__ A, int lda, long long sA1, long long sA2,
         const float* __restrict__ B, int ldb, long long sB1, long long sB2,
         float* __restrict__ C, int ldc, long long sC1, long long sC2,
         int K,
         const float* __restrict__ bias,
         const float* __restrict__ resid, int ldr,
         int relu, int round_out) {
    int z  = blockIdx.z;
    int zb = z >> 2, zh = z & 3;
    A += sA1 * zb + sA2 * zh;
    B += sB1 * zb + sB2 * zh;
    C += sC1 * zb + sC2 * zh;

    const int m0 = blockIdx.y * 128;
    const int n0 = blockIdx.x * 128;
    const int tid  = threadIdx.x;
    const int lane = tid & 31;
    const int wid  = tid >> 5;
    const int g  = lane >> 2;        // groupID
    const int t4 = lane & 3;         // threadID in group
    const int mw = (wid >> 2) * 64;  // warp m offset
    const int nw = (wid & 3) * 32;   // warp n offset

    __shared__ __align__(16) float As[STAGES][128 * APAD];
    __shared__ __align__(16) float Bs[STAGES][16 * BPAD];

    const int a_row0 = tid >> 2;
    const int a_ch0  = (tid & 3) * 4;
    const int a_row1 = a_row0 + 64;
    const int b_row0 = tid >> 5;
    const int b_ch0  = (tid & 31) * 4;
    const int b_row1 = b_row0 + 8;

    auto issue = [&](int kt, int buf) {
        cp_async16(&As[buf][a_row0 * APAD + a_ch0],
                   A + (size_t)(m0 + a_row0) * lda + kt * 16 + a_ch0);
        cp_async16(&As[buf][a_row1 * APAD + a_ch0],
                   A + (size_t)(m0 + a_row1) * lda + kt * 16 + a_ch0);
        cp_async16(&Bs[buf][b_row0 * BPAD + b_ch0],
                   B + (size_t)(kt * 16 + b_row0) * ldb + n0 + b_ch0);
        cp_async16(&Bs[buf][b_row1 * BPAD + b_ch0],
                   B + (size_t)(kt * 16 + b_row1) * ldb + n0 + b_ch0);
        cp_commit();
    };

    // Per-lane ldmatrix source offset within an A fragment block:
    // lanes 0-7 -> rows 0-7 (a0 block), 8-15 -> rows 8-15 (a1),
    // 16-23 -> rows 0-7 cols +4 (a2), 24-31 -> rows 8-15 cols +4 (a3).
    const int lrow_off = (lane & 7) + ((lane & 8) ? 8 : 0);
    const int lcol_off = (lane & 16) ? 4 : 0;
    const uint32_t asU = (uint32_t)__cvta_generic_to_shared(&As[0][0]);
    const uint32_t a_lane_base =
        asU + 4u * ((mw + lrow_off) * APAD + lcol_off);

    float acc[4][4][4];
    #pragma unroll
    for (int mi = 0; mi < 4; mi++)
        #pragma unroll
        for (int ni = 0; ni < 4; ni++)
            #pragma unroll
            for (int q = 0; q < 4; q++) acc[mi][ni][q] = 0.f;

    const int nk = K >> 4;   // all call sites have nk >= 32
    issue(0, 0);
    issue(1, 1);

    for (int kt = 0; kt < nk; kt++) {
        const int cur = kt % STAGES;
        cp_wait<STAGES - 2>();     // tile kt resident (kt+1 may be in flight)
        __syncthreads();           // all warps done with buffer (kt+2)%3
        if (kt + 2 < nk) issue(kt + 2, (kt + 2) % STAGES);

        const float* __restrict__ Bsc = Bs[cur];
        const uint32_t a_stage = a_lane_base + 4u * (cur * (128 * APAD));
        #pragma unroll
        for (int ks = 0; ks < 2; ks++) {
            uint32_t af[4][4], bf[4][2];
            const int col = ks * 8 + t4;
            #pragma unroll
            for (int mi = 0; mi < 4; mi++) {
                ldsm_x4(af[mi][0], af[mi][1], af[mi][2], af[mi][3],
                        a_stage + 4u * (mi * 16 * APAD + ks * 8));
            }
            #pragma unroll
            for (int ni = 0; ni < 4; ni++) {
                const int cc = nw + ni * 8 + g;
                bf[ni][0] = __float_as_uint(Bsc[col * BPAD + cc]);
                bf[ni][1] = __float_as_uint(Bsc[(col + 4) * BPAD + cc]);
            }
            #pragma unroll
            for (int mi = 0; mi < 4; mi++)
                #pragma unroll
                for (int ni = 0; ni < 4; ni++)
                    mma_tf32(acc[mi][ni], af[mi], bf[ni]);
        }
    }

    // Epilogue
    #pragma unroll
    for (int mi = 0; mi < 4; mi++) {
        const int r0 = m0 + mw + mi * 16 + g;
        #pragma unroll
        for (int ni = 0; ni < 4; ni++) {
            const int c0 = n0 + nw + ni * 8 + t4 * 2;
            float bb0 = 0.f, bb1 = 0.f;
            if (bias) { bb0 = bias[c0]; bb1 = bias[c0 + 1]; }
            float v0 = acc[mi][ni][0] + bb0;
            float v1 = acc[mi][ni][1] + bb1;
            float v2 = acc[mi][ni][2] + bb0;
            float v3 = acc[mi][ni][3] + bb1;
            if (resid) {
                const float* R0 = resid + (size_t)r0 * ldr + c0;
                const float* R1 = resid + (size_t)(r0 + 8) * ldr + c0;
                v0 += R0[0]; v1 += R0[1];
                v2 += R1[0]; v3 += R1[1];
            }
            if (relu) {
                v0 = fmaxf(v0, 0.f); v1 = fmaxf(v1, 0.f);
                v2 = fmaxf(v2, 0.f); v3 = fmaxf(v3, 0.f);
            }
            if (round_out == 1 || (round_out == 2 && c0 >= 4096)) {
                v0 = roundtf(v0); v1 = roundtf(v1);
                v2 = roundtf(v2); v3 = roundtf(v3);
            }
            *(float2*)&C[(size_t)r0 * ldc + c0]       = make_float2(v0, v1);
            *(float2*)&C[(size_t)(r0 + 8) * ldc + c0] = make_float2(v2, v3);
        }
    }
}

// ---------------------------------------------------------------------------
// Scores (fp32): S = scale * q k^T, causal mask. 64x64 tiles, NT.
// q,k arrive in full fp32 precision (QKV GEMM does NOT round them).
// ---------------------------------------------------------------------------
__global__ void __launch_bounds__(256)
scores_nt_kernel(const float* __restrict__ QKV, float* __restrict__ S) {
    int z = blockIdx.z;
    int bb = z >> 2, hh = z & 3;
    const float* Aq = QKV + (size_t)bb * Tt * NQKV + hh * HDd;
    const float* Ak = Aq + Dd;
    float* Cs = S + (size_t)z * Tt * Tt;

    const int m0 = blockIdx.y * 64;
    const int n0 = blockIdx.x * 64;
    const int tid = threadIdx.x;
    const int ty = tid >> 4, tx = tid & 15;

    if (n0 > m0) {
        #pragma unroll
        for (int i = 0; i < 4; i++) {
            int gi = m0 + ty * 4 + i;
            float4 mm; mm.x = mm.y = mm.z = mm.w = -1e30f;
            *(float4*)&Cs[(size_t)gi * Tt + n0 + tx * 4] = mm;
        }
        return;
    }

    __shared__ __align__(16) float As[2][16][64];
    __shared__ __align__(16) float Bs[2][16][64];

    const int lrow = tid >> 2;
    const int lcol = (tid & 3) * 4;

    float4 ra, rb;
    auto loadT = [&](int kt) {
        ra = *(const float4*)(Aq + (size_t)(m0 + lrow) * NQKV + kt * 16 + lcol);
        rb = *(const float4*)(Ak + (size_t)(n0 + lrow) * NQKV + kt * 16 + lcol);
    };
    auto storeT = [&](int buf) {
        As[buf][lcol + 0][lrow] = ra.x; As[buf][lcol + 1][lrow] = ra.y;
        As[buf][lcol + 2][lrow] = ra.z; As[buf][lcol + 3][lrow] = ra.w;
        Bs[buf][lcol + 0][lrow] = rb.x; Bs[buf][lcol + 1][lrow] = rb.y;
        Bs[buf][lcol + 2][lrow] = rb.z; Bs[buf][lcol + 3][lrow] = rb.w;
    };

    float acc[4][4];
    #pragma unroll
    for (int i = 0; i < 4; i++)
        #pragma unroll
        for (int j = 0; j < 4; j++) acc[i][j] = 0.f;

    loadT(0); storeT(0);
    __syncthreads();

    const int nk = HDd / 16;
    for (int kt = 0; kt < nk; kt++) {
        int cur = kt & 1;
        if (kt + 1 < nk) loadT(kt + 1);
        #pragma unroll
        for (int kk = 0; kk < 16; kk++) {
            float a[4], bvv[4];
            *(float4*)a   = *(const float4*)&As[cur][kk][ty * 4];
            *(float4*)bvv = *(const float4*)&Bs[cur][kk][tx * 4];
            #pragma unroll
            for (int i = 0; i < 4; i++)
                #pragma unroll
                for (int j = 0; j < 4; j++)
                    acc[i][j] += a[i] * bvv[j];
        }
        if (kt + 1 < nk) {
            storeT(cur ^ 1);
            __syncthreads();
        }
    }

    const float scale = 0.044194173824159216f;
    #pragma unroll
    for (int i = 0; i < 4; i++) {
        int gi = m0 + ty * 4 + i;
        float v[4];
        #pragma unroll
        for (int j = 0; j < 4; j++) {
            int gj = n0 + tx * 4 + j;
            v[j] = (gj > gi) ? -1e30f : acc[i][j] * scale;
        }
        float4 o; o.x = v[0]; o.y = v[1]; o.z = v[2]; o.w = v[3];
        *(float4*)&Cs[(size_t)gi * Tt + n0 + tx * 4] = o;
    }
}

// ---------------------------------------------------------------------------
// Row softmax over T=512 entries. Output tf32-rounded (GEMM A operand only).
// ---------------------------------------------------------------------------
__global__ void softmax_kernel(float* __restrict__ S) {
    int row = blockIdx.x;
    int t = threadIdx.x;
    float4* p = (float4*)(S + (size_t)row * Tt);
    float4 v = p[t];
    float m = fmaxf(fmaxf(v.x, v.y), fmaxf(v.z, v.w));
    #pragma unroll
    for (int o = 16; o; o >>= 1) m = fmaxf(m, __shfl_xor_sync(0xffffffffu, m, o));
    __shared__ float sm[4], ssum[4];
    int w = t >> 5;
    if ((t & 31) == 0) sm[w] = m;
    __syncthreads();
    m = fmaxf(fmaxf(sm[0], sm[1]), fmaxf(sm[2], sm[3]));
    v.x = expf(v.x - m); v.y = expf(v.y - m);
    v.z = expf(v.z - m); v.w = expf(v.w - m);
    float s = v.x + v.y + v.z + v.w;
    #pragma unroll
    for (int o = 16; o; o >>= 1) s += __shfl_xor_sync(0xffffffffu, s, o);
    if ((t & 31) == 0) ssum[w] = s;
    __syncthreads();
    s = ssum[0] + ssum[1] + ssum[2] + ssum[3];
    float inv = 1.f / s;
    v.x = roundtf(v.x * inv); v.y = roundtf(v.y * inv);
    v.z = roundtf(v.z * inv); v.w = roundtf(v.w * inv);
    p[t] = v;
}

// ---------------------------------------------------------------------------
// Host launcher
// ---------------------------------------------------------------------------
extern "C" void kernel_launch(void* const* d_in, const int* in_sizes, int n_in,
                              void* d_out, int out_size) {
    const float* x   = (const float*)d_in[0];
    const float* Wq  = (const float*)d_in[1];
    const float* Wk  = (const float*)d_in[2];
    const float* Wv  = (const float*)d_in[3];
    const float* Wo  = (const float*)d_in[4];
    const float* bo  = (const float*)d_in[5];
    const float* W1  = (const float*)d_in[6];
    const float* b1  = (const float*)d_in[7];
    const float* W2  = (const float*)d_in[8];
    const float* b2  = (const float*)d_in[9];
    const float* g1  = (const float*)d_in[10];
    const float* be1 = (const float*)d_in[11];
    const float* g2  = (const float*)d_in[12];
    const float* be2 = (const float*)d_in[13];
    float* out = (float*)d_out;

    float *p_wqkv, *p_ln, *p_qkv, *p_sc, *p_ctx, *p_ffn, *p_wot, *p_w1t, *p_w2t;
    cudaGetSymbolAddress((void**)&p_wqkv, g_Wqkv);
    cudaGetSymbolAddress((void**)&p_ln,   g_ln);
    cudaGetSymbolAddress((void**)&p_qkv,  g_qkv);
    cudaGetSymbolAddress((void**)&p_sc,   g_scores);
    cudaGetSymbolAddress((void**)&p_ctx,  g_ctx);
    cudaGetSymbolAddress((void**)&p_ffn,  g_ffn);
    cudaGetSymbolAddress((void**)&p_wot,  g_Wot);
    cudaGetSymbolAddress((void**)&p_w1t,  g_W1t);
    cudaGetSymbolAddress((void**)&p_w2t,  g_W2t);

    // 0) tf32-round weight copies
    round_copy_kernel<<<(Dd * Dd / 4 + 255) / 256, 256>>>(
        (const float4*)Wo, (float4*)p_wot, Dd * Dd / 4);
    round_copy_kernel<<<(Dd * DFF / 4 + 255) / 256, 256>>>(
        (const float4*)W1, (float4*)p_w1t, Dd * DFF / 4);
    round_copy_kernel<<<(DFF * Dd / 4 + 255) / 256, 256>>>(
        (const float4*)W2, (float4*)p_w2t, DFF * Dd / 4);

    // 1) repack QKV weights -> [D, 3D] (tf32-rounded)
    repack_qkv_kernel<<<(Dd * NQKV) / 256, 256>>>(Wq, Wk, Wv, p_wqkv);

    // 2) h = LN(x) (tf32-rounded)
    ln_kernel<<<BT, 256>>>(x, g1, be1, p_ln);

    // 3) QKV = h @ Wqkv. round_out=2: round ONLY the v block (cols >= 4096);
    //    q,k stay fp32 for the scores kernel.
    tgemm_nn<<<dim3(NQKV / 128, BT / 128, 1), 256>>>(
        p_ln, Dd, 0, 0,
        p_wqkv, NQKV, 0, 0,
        p_qkv, NQKV, 0, 0,
        Dd, nullptr, nullptr, 0, 0, 2);

    // 4) scores = scale * q k^T with causal mask (full fp32)
    scores_nt_kernel<<<dim3(Tt / 64, Tt / 64, Bb * Hh), 256>>>(p_qkv, p_sc);

    // 5) softmax rows (tf32-rounded probs)
    softmax_kernel<<<Bb * Hh * Tt, 128>>>(p_sc);

    // 6) ctx_cat = attn @ v (round_out: feeds Wo GEMM)
    tgemm_nn<<<dim3(HDd / 128, Tt / 128, Bb * Hh), 256>>>(
        p_sc, Tt, (long long)Hh * Tt * Tt, (long long)Tt * Tt,
        p_qkv + 2 * Dd, NQKV, (long long)Tt * NQKV, HDd,
        p_ctx, Dd, (long long)Tt * Dd, HDd,
        HDd, nullptr, nullptr, 0, 0, 1);

    // 7) x2 = x + ctx_cat @ Wo + bo -> d_out (full fp32 output)
    tgemm_nn<<<dim3(Dd / 128, BT / 128, 1), 256>>>(
        p_ctx, Dd, 0, 0,
        p_wot, Dd, 0, 0,
        out, Dd, 0, 0,
        Dd, bo, x, Dd, 0, 0);

    // 8) h2 = LN(x2) (tf32-rounded)
    ln_kernel<<<BT, 256>>>(out, g2, be2, p_ln);

    // 9) u = relu(h2 @ W1 + b1) (round_out: feeds W2 GEMM)
    tgemm_nn<<<dim3(DFF / 128, BT / 128, 1), 256>>>(
        p_ln, Dd, 0, 0,
        p_w1t, DFF, 0, 0,
        p_ffn, DFF, 0, 0,
        Dd, b1, nullptr, 0, 1, 1);

    // 10) out = x2 + u @ W2 + b2 (resid = d_out in place, fp32 output)
    tgemm_nn<<<dim3(Dd / 128, BT / 128, 1), 256>>>(
        p_ffn, DFF, 0, 0,
        p_w2t, Dd, 0, 0,
        out, Dd, 0, 0,
        DFF, b2, out, Dd, 0, 0);
}

// round 11
// speedup vs baseline: 1.7868x; 1.6440x over previous
#include <cuda_runtime.h>
#include <cuda_fp16.h>
#include <math.h>
#include <stdint.h>

// Problem constants
#define Bb   16
#define Tt   512
#define Dd   2048
#define Hh   4
#define HDd  512
#define BT   8192          // B*T rows
#define NQKV 6144          // 3*D
#define DFF  8192          // 4*D
#define LNEPS 1e-5f

// ---------------------------------------------------------------------------
// Scratch (static __device__ arrays; no allocation allowed)
// ---------------------------------------------------------------------------
__device__ __align__(128) __half g_lnh[(size_t)BT * Dd];          // LN out fp16
__device__ __align__(128) __half g_wqkvh[(size_t)NQKV * Dd];      // [6144][2048] K-major
__device__ __align__(128) float  g_qkv[(size_t)BT * NQKV];        // fp32 q,k,v
__device__ __align__(128) float  g_scores[(size_t)Bb * Hh * Tt * Tt];
__device__ __align__(128) __half g_probs[(size_t)Bb * Hh * Tt * Tt];
__device__ __align__(128) __half g_vt[(size_t)Bb * Hh * HDd * Tt]; // [b,h][c][s]
__device__ __align__(128) __half g_ctxh[(size_t)BT * Dd];
__device__ __align__(128) __half g_ffnh[(size_t)BT * DFF];
__device__ __align__(128) __half g_woth[(size_t)Dd * Dd];         // [2048][2048] K-major
__device__ __align__(128) __half g_w1th[(size_t)DFF * Dd];        // [8192][2048] K-major
__device__ __align__(128) __half g_w2th[(size_t)Dd * DFF];        // [2048][8192] K-major

// ---------------------------------------------------------------------------
// PTX helpers
// ---------------------------------------------------------------------------
__device__ __forceinline__ uint32_t smem_u32(const void* p) {
    uint32_t a;
    asm("{ .reg .u64 t; cvta.to.shared.u64 t, %1; cvt.u32.u64 %0, t; }"
        : "=r"(a) : "l"(p));
    return a;
}
__device__ __forceinline__ void cp_async16(uint32_t smem_dst, const void* gmem_src) {
    asm volatile("cp.async.cg.shared.global [%0], [%1], 16;\n" :: "r"(smem_dst), "l"(gmem_src));
}
__device__ __forceinline__ void cp_commit() {
    asm volatile("cp.async.commit_group;\n");
}
template<int N>
__device__ __forceinline__ void cp_wait() {
    asm volatile("cp.async.wait_group %0;\n" :: "n"(N));
}
// fp16 tensor-core mma: D(f32) += A(f16,m16k16,row) * B(f16,n8k16,col)
__device__ __forceinline__ void mma_f16(float* c, const uint32_t* a, const uint32_t* b) {
    asm volatile(
        "mma.sync.aligned.m16n8k16.row.col.f32.f16.f16.f32 "
        "{%0,%1,%2,%3}, {%4,%5,%6,%7}, {%8,%9}, {%0,%1,%2,%3};"
        : "+f"(c[0]), "+f"(c[1]), "+f"(c[2]), "+f"(c[3])
        : "r"(a[0]), "r"(a[1]), "r"(a[2]), "r"(a[3]), "r"(b[0]), "r"(b[1]));
}

// ---------------------------------------------------------------------------
// Weight transpose + fp16 convert:  out[N][K] = half(in[K][N])
// ---------------------------------------------------------------------------
__global__ void transpose_h(const float* __restrict__ in,
                            __half* __restrict__ out, int K, int N) {
    __shared__ float t[32][33];
    int n0 = blockIdx.x * 32, k0 = blockIdx.y * 32;
    int lx = threadIdx.x, ly = threadIdx.y;
    #pragma unroll
    for (int i = 0; i < 32; i += 8)
        t[ly + i][lx] = in[(size_t)(k0 + ly + i) * N + n0 + lx];
    __syncthreads();
    #pragma unroll
    for (int i = 0; i < 32; i += 8)
        out[(size_t)(n0 + ly + i) * K + k0 + lx] = __float2half_rn(t[lx][ly + i]);
}

// Repack+transpose Wq/Wk/Wv [H,D,HD] -> half [3D][D] K-major.
__global__ void repack_qkv_t_h(const float* __restrict__ Wq,
                               const float* __restrict__ Wk,
                               const float* __restrict__ Wv,
                               __half* __restrict__ out) {
    __shared__ float t[32][33];
    int z = blockIdx.z;
    int sel = z >> 2, h = z & 3;
    const float* W = (sel == 0 ? Wq : sel == 1 ? Wk : Wv) + (size_t)h * Dd * HDd;
    int c0 = blockIdx.x * 32, k0 = blockIdx.y * 32;
    int lx = threadIdx.x, ly = threadIdx.y;
    #pragma unroll
    for (int i = 0; i < 32; i += 8)
        t[ly + i][lx] = W[(size_t)(k0 + ly + i) * HDd + c0 + lx];
    __syncthreads();
    int nbase = sel * 2048 + h * 512 + c0;
    #pragma unroll
    for (int i = 0; i < 32; i += 8)
        out[(size_t)(nbase + ly + i) * Dd + k0 + lx] = __float2half_rn(t[lx][ly + i]);
}

// v block of packed QKV (fp32) -> vt half [b,h][c=512][s=512]
__global__ void vt_kernel(const float* __restrict__ qkv, __half* __restrict__ vt) {
    __shared__ float t[32][33];
    int z = blockIdx.z;
    int bb = z >> 2, hh = z & 3;
    int s0 = blockIdx.x * 32;   // token
    int c0 = blockIdx.y * 32;   // channel
    int lx = threadIdx.x, ly = threadIdx.y;
    const float* src = qkv + (size_t)(bb * Tt) * NQKV + 4096 + hh * HDd;
    #pragma unroll
    for (int i = 0; i < 32; i += 8)
        t[ly + i][lx] = src[(size_t)(s0 + ly + i) * NQKV + c0 + lx];  // [s][c]
    __syncthreads();
    __half* dst = vt + (size_t)z * HDd * Tt;
    #pragma unroll
    for (int i = 0; i < 32; i += 8)
        dst[(size_t)(c0 + ly + i) * Tt + s0 + lx] = __float2half_rn(t[lx][ly + i]);
}

// ---------------------------------------------------------------------------
// LayerNorm: one block per row (D=2048), 256 threads. fp16 output.
// ---------------------------------------------------------------------------
__global__ void ln_kernel_h(const float* __restrict__ x,
                            const float* __restrict__ g,
                            const float* __restrict__ b,
                            __half* __restrict__ out) {
    int row = blockIdx.x;
    int t   = threadIdx.x;
    const float4* xr = (const float4*)(x + (size_t)row * Dd);
    float4 v0 = xr[t];
    float4 v1 = xr[t + 256];
    float s  = v0.x + v0.y + v0.z + v0.w + v1.x + v1.y + v1.z + v1.w;
    float sq = v0.x*v0.x + v0.y*v0.y + v0.z*v0.z + v0.w*v0.w
             + v1.x*v1.x + v1.y*v1.y + v1.z*v1.z + v1.w*v1.w;
    #pragma unroll
    for (int o = 16; o; o >>= 1) {
        s  += __shfl_xor_sync(0xffffffffu, s,  o);
        sq += __shfl_xor_sync(0xffffffffu, sq, o);
    }
    __shared__ float ss[8], ssq[8];
    int w = t >> 5;
    if ((t & 31) == 0) { ss[w] = s; ssq[w] = sq; }
    __syncthreads();
    float S = 0.f, SQ = 0.f;
    #pragma unroll
    for (int i = 0; i < 8; i++) { S += ss[i]; SQ += ssq[i]; }
    float mean = S * (1.f / Dd);
    float var  = SQ * (1.f / Dd) - mean * mean;
    float rstd = rsqrtf(var + LNEPS);

    const float4* gr = (const float4*)g;
    const float4* br = (const float4*)b;
    __half2* o2 = (__half2*)(out + (size_t)row * Dd);
    float4 gv = gr[t], bv = br[t];
    o2[2 * t]     = __floats2half2_rn((v0.x - mean) * rstd * gv.x + bv.x,
                                      (v0.y - mean) * rstd * gv.y + bv.y);
    o2[2 * t + 1] = __floats2half2_rn((v0.z - mean) * rstd * gv.z + bv.z,
                                      (v0.w - mean) * rstd * gv.w + bv.w);
    gv = gr[t + 256]; bv = br[t + 256];
    o2[2 * (t + 256)]     = __floats2half2_rn((v1.x - mean) * rstd * gv.x + bv.x,
                                              (v1.y - mean) * rstd * gv.y + bv.y);
    o2[2 * (t + 256) + 1] = __floats2half2_rn((v1.z - mean) * rstd * gv.z + bv.z,
                                              (v1.w - mean) * rstd * gv.w + bv.w);
}

// ---------------------------------------------------------------------------
// fp16 tensor-core GEMM: C[M,N] = A[M,K] @ Bt[N,K]^T (+bias)(+resid)(relu)
// A half [M][K] row-major (lda), Bt half [N][K] K-major (ldb).
// CTA 128x128x32, 256 threads = 8 warps (2m x 4n), warp tile 64x32,
// mma.sync.m16n8k16 f16->f32. 3-stage cp.async, dyn smem 60KB, 2 CTAs/SM.
// out_half: 1 = write fp16 C, 0 = write fp32 C.
// Batched over blockIdx.z with offsets sX1*(z>>2) + sX2*(z&3).
// ---------------------------------------------------------------------------
#define H_STAGES 3
#define H_ROWH 40                       // halves per smem row (32 + 8 pad)
#define H_TILE_BYTES (128 * H_ROWH * 2) // 10240 per operand
#define H_STAGE_BYTES (2 * H_TILE_BYTES)
#define H_SMEM_BYTES (H_STAGES * H_STAGE_BYTES)  // 61440

__global__ void __launch_bounds__(256, 2)
hgemm(const __half* __restrict__ A, int lda, long long sA1, long long sA2,
      const __half* __restrict__ B, int ldb, long long sB1, long long sB2,
      void* __restrict__ Cvoid, int ldc, long long sC1, long long sC2,
      int K,
      const float* __restrict__ bias,
      const float* __restrict__ resid, int ldr,
      int relu, int out_half) {
    extern __shared__ __align__(16) char sm_[];
    const uint32_t smem_u = smem_u32(sm_);

    int z  = blockIdx.z;
    int zb = z >> 2, zh = z & 3;
    A += sA1 * zb + sA2 * zh;
    B += sB1 * zb + sB2 * zh;

    const int m0 = blockIdx.y * 128;
    const int n0 = blockIdx.x * 128;
    const int tid  = threadIdx.x;
    const int lane = tid & 31;
    const int wid  = tid >> 5;
    const int g  = lane >> 2;        // groupID
    const int t4 = lane & 3;         // thread-in-group
    const int mw = (wid >> 2) * 64;  // warp m offset
    const int nw = (wid & 3) * 32;   // warp n offset

    // cp.async indices: tile = 128 rows x 32 halves (64B) = 512 16B chunks;
    // 256 threads x 2 chunks per operand.
    const int c_row0 = tid >> 2;          // 0..63
    const int c_row1 = c_row0 + 64;
    const int c_off  = (tid & 3) * 8;     // halves offset (16B chunks)

    auto issue = [&](int kt, int s) {
        const uint32_t sa = smem_u + s * H_STAGE_BYTES;
        const uint32_t sb = sa + H_TILE_BYTES;
        const __half* ap = A + (size_t)(m0) * lda + kt * 32 + c_off;
        const __half* bp = B + (size_t)(n0) * ldb + kt * 32 + c_off;
        cp_async16(sa + (uint32_t)(c_row0 * H_ROWH + c_off) * 2,
                   ap + (size_t)c_row0 * lda);
        cp_async16(sa + (uint32_t)(c_row1 * H_ROWH + c_off) * 2,
                   ap + (size_t)c_row1 * lda);
        cp_async16(sb + (uint32_t)(c_row0 * H_ROWH + c_off) * 2,
                   bp + (size_t)c_row0 * ldb);
        cp_async16(sb + (uint32_t)(c_row1 * H_ROWH + c_off) * 2,
                   bp + (size_t)c_row1 * ldb);
        cp_commit();
    };

    float acc[4][4][4];
    #pragma unroll
    for (int mi = 0; mi < 4; mi++)
        #pragma unroll
        for (int ni = 0; ni < 4; ni++)
            #pragma unroll
            for (int q = 0; q < 4; q++) acc[mi][ni][q] = 0.f;

    const int nk = K >> 5;   // K-chunks of 32 (all call sites: nk >= 16)
    issue(0, 0);
    issue(1, 1);

    for (int kt = 0; kt < nk; kt++) {
        const int cur = kt % H_STAGES;
        cp_wait<H_STAGES - 2>();
        __syncthreads();
        if (kt + 2 < nk) issue(kt + 2, (kt + 2) % H_STAGES);

        const __half* Asc = (const __half*)(sm_ + cur * H_STAGE_BYTES);
        const __half* Bsc = Asc + 128 * H_ROWH;
        #pragma unroll
        for (int ks = 0; ks < 2; ks++) {
            const int kc = ks * 16 + 2 * t4;
            uint32_t af[4][4], bf[4][2];
            #pragma unroll
            for (int mi = 0; mi < 4; mi++) {
                const int r = mw + mi * 16 + g;
                af[mi][0] = *(const uint32_t*)(Asc + r * H_ROWH + kc);
                af[mi][1] = *(const uint32_t*)(Asc + (r + 8) * H_ROWH + kc);
                af[mi][2] = *(const uint32_t*)(Asc + r * H_ROWH + kc + 8);
                af[mi][3] = *(const uint32_t*)(Asc + (r + 8) * H_ROWH + kc + 8);
            }
            #pragma unroll
            for (int ni = 0; ni < 4; ni++) {
                const int nn = nw + ni * 8 + g;
                bf[ni][0] = *(const uint32_t*)(Bsc + nn * H_ROWH + kc);
                bf[ni][1] = *(const uint32_t*)(Bsc + nn * H_ROWH + kc + 8);
            }
            #pragma unroll
            for (int mi = 0; mi < 4; mi++)
                #pragma unroll
                for (int ni = 0; ni < 4; ni++)
                    mma_f16(acc[mi][ni], af[mi], bf[ni]);
        }
    }

    // Epilogue: c0,c1 -> (row g, cols 2t4, 2t4+1); c2,c3 -> row g+8.
    float* Cf = (float*)Cvoid + sC1 * zb + sC2 * zh;
    __half* Ch = (__half*)Cvoid + sC1 * zb + sC2 * zh;
    #pragma unroll
    for (int mi = 0; mi < 4; mi++) {
        const int r0 = m0 + mw + mi * 16 + g;
        #pragma unroll
        for (int ni = 0; ni < 4; ni++) {
            const int c0 = n0 + nw + ni * 8 + t4 * 2;
            float bb0 = 0.f, bb1 = 0.f;
            if (bias) { bb0 = bias[c0]; bb1 = bias[c0 + 1]; }
            float v0 = acc[mi][ni][0] + bb0;
            float v1 = acc[mi][ni][1] + bb1;
            float v2 = acc[mi][ni][2] + bb0;
            float v3 = acc[mi][ni][3] + bb1;
            if (resid) {
                const float* R0 = resid + (size_t)r0 * ldr + c0;
                const float* R1 = resid + (size_t)(r0 + 8) * ldr + c0;
                v0 += R0[0]; v1 += R0[1];
                v2 += R1[0]; v3 += R1[1];
            }
            if (relu) {
                v0 = fmaxf(v0, 0.f); v1 = fmaxf(v1, 0.f);
                v2 = fmaxf(v2, 0.f); v3 = fmaxf(v3, 0.f);
            }
            if (out_half) {
                *(__half2*)&Ch[(size_t)r0 * ldc + c0]       = __floats2half2_rn(v0, v1);
                *(__half2*)&Ch[(size_t)(r0 + 8) * ldc + c0] = __floats2half2_rn(v2, v3);
            } else {
                *(float2*)&Cf[(size_t)r0 * ldc + c0]       = make_float2(v0, v1);
                *(float2*)&Cf[(size_t)(r0 + 8) * ldc + c0] = make_float2(v2, v3);
            }
        }
    }
}

// ---------------------------------------------------------------------------
// Scores (fp32): S = scale * q k^T, causal mask. 64x64 tiles, NT.
// q,k arrive in full fp32 precision from the QKV GEMM (fp32 accumulators).
// ---------------------------------------------------------------------------
__global__ void __launch_bounds__(256)
scores_nt_kernel(const float* __restrict__ QKV, float* __restrict__ S) {
    int z = blockIdx.z;
    int bb = z >> 2, hh = z & 3;
    const float* Aq = QKV + (size_t)bb * Tt * NQKV + hh * HDd;
    const float* Ak = Aq + Dd;
    float* Cs = S + (size_t)z * Tt * Tt;

    const int m0 = blockIdx.y * 64;
    const int n0 = blockIdx.x * 64;
    const int tid = threadIdx.x;
    const int ty = tid >> 4, tx = tid & 15;

    if (n0 > m0) {
        #pragma unroll
        for (int i = 0; i < 4; i++) {
            int gi = m0 + ty * 4 + i;
            float4 mm; mm.x = mm.y = mm.z = mm.w = -1e30f;
            *(float4*)&Cs[(size_t)gi * Tt + n0 + tx * 4] = mm;
        }
        return;
    }

    __shared__ __align__(16) float As[2][16][64];
    __shared__ __align__(16) float Bs[2][16][64];

    const int lrow = tid >> 2;
    const int lcol = (tid & 3) * 4;

    float4 ra, rb;
    auto loadT = [&](int kt) {
        ra = *(const float4*)(Aq + (size_t)(m0 + lrow) * NQKV + kt * 16 + lcol);
        rb = *(const float4*)(Ak + (size_t)(n0 + lrow) * NQKV + kt * 16 + lcol);
    };
    auto storeT = [&](int buf) {
        As[buf][lcol + 0][lrow] = ra.x; As[buf][lcol + 1][lrow] = ra.y;
        As[buf][lcol + 2][lrow] = ra.z; As[buf][lcol + 3][lrow] = ra.w;
        Bs[buf][lcol + 0][lrow] = rb.x; Bs[buf][lcol + 1][lrow] = rb.y;
        Bs[buf][lcol + 2][lrow] = rb.z; Bs[buf][lcol + 3][lrow] = rb.w;
    };

    float acc[4][4];
    #pragma unroll
    for (int i = 0; i < 4; i++)
        #pragma unroll
        for (int j = 0; j < 4; j++) acc[i][j] = 0.f;

    loadT(0); storeT(0);
    __syncthreads();

    const int nk = HDd / 16;
    for (int kt = 0; kt < nk; kt++) {
        int cur = kt & 1;
        if (kt + 1 < nk) loadT(kt + 1);
        #pragma unroll
        for (int kk = 0; kk < 16; kk++) {
            float a[4], bvv[4];
            *(float4*)a   = *(const float4*)&As[cur][kk][ty * 4];
            *(float4*)bvv = *(const float4*)&Bs[cur][kk][tx * 4];
            #pragma unroll
            for (int i = 0; i < 4; i++)
                #pragma unroll
                for (int j = 0; j < 4; j++)
                    acc[i][j] += a[i] * bvv[j];
        }
        if (kt + 1 < nk) {
            storeT(cur ^ 1);
            __syncthreads();
        }
    }

    const float scale = 0.044194173824159216f;
    #pragma unroll
    for (int i = 0; i < 4; i++) {
        int gi = m0 + ty * 4 + i;
        float v[4];
        #pragma unroll
        for (int j = 0; j < 4; j++) {
            int gj = n0 + tx * 4 + j;
            v[j] = (gj > gi) ? -1e30f : acc[i][j] * scale;
        }
        float4 o; o.x = v[0]; o.y = v[1]; o.z = v[2]; o.w = v[3];
        *(float4*)&Cs[(size_t)gi * Tt + n0 + tx * 4] = o;
    }
}

// ---------------------------------------------------------------------------
// Row softmax over T=512 (fp32 in) -> fp16 probs out.
// ---------------------------------------------------------------------------
__global__ void softmax_h(const float* __restrict__ S, __half* __restrict__ P) {
    int row = blockIdx.x;
    int t = threadIdx.x;
    const float4* p = (const float4*)(S + (size_t)row * Tt);
    float4 v = p[t];
    float m = fmaxf(fmaxf(v.x, v.y), fmaxf(v.z, v.w));
    #pragma unroll
    for (int o = 16; o; o >>= 1) m = fmaxf(m, __shfl_xor_sync(0xffffffffu, m, o));
    __shared__ float sm[4], ssum[4];
    int w = t >> 5;
    if ((t & 31) == 0) sm[w] = m;
    __syncthreads();
    m = fmaxf(fmaxf(sm[0], sm[1]), fmaxf(sm[2], sm[3]));
    v.x = expf(v.x - m); v.y = expf(v.y - m);
    v.z = expf(v.z - m); v.w = expf(v.w - m);
    float s = v.x + v.y + v.z + v.w;
    #pragma unroll
    for (int o = 16; o; o >>= 1) s += __shfl_xor_sync(0xffffffffu, s, o);
    if ((t & 31) == 0) ssum[w] = s;
    __syncthreads();
    s = ssum[0] + ssum[1] + ssum[2] + ssum[3];
    float inv = 1.f / s;
    __half2* ph = (__half2*)(P + (size_t)row * Tt);
    ph[2 * t]     = __floats2half2_rn(v.x * inv, v.y * inv);
    ph[2 * t + 1] = __floats2half2_rn(v.z * inv, v.w * inv);
}

// ---------------------------------------------------------------------------
// Host launcher
// ---------------------------------------------------------------------------
extern "C" void kernel_launch(void* const* d_in, const int* in_sizes, int n_in,
                              void* d_out, int out_size) {
    const float* x   = (const float*)d_in[0];
    const float* Wq  = (const float*)d_in[1];
    const float* Wk  = (const float*)d_in[2];
    const float* Wv  = (const float*)d_in[3];
    const float* Wo  = (const float*)d_in[4];
    const float* bo  = (const float*)d_in[5];
    const float* W1  = (const float*)d_in[6];
    const float* b1  = (const float*)d_in[7];
    const float* W2  = (const float*)d_in[8];
    const float* b2  = (const float*)d_in[9];
    const float* g1  = (const float*)d_in[10];
    const float* be1 = (const float*)d_in[11];
    const float* g2  = (const float*)d_in[12];
    const float* be2 = (const float*)d_in[13];
    float* out = (float*)d_out;

    __half *p_lnh, *p_wqkvh, *p_probs, *p_vt, *p_ctxh, *p_ffnh, *p_woth, *p_w1th, *p_w2th;
    float *p_qkv, *p_sc;
    cudaGetSymbolAddress((void**)&p_lnh,   g_lnh);
    cudaGetSymbolAddress((void**)&p_wqkvh, g_wqkvh);
    cudaGetSymbolAddress((void**)&p_qkv,   g_qkv);
    cudaGetSymbolAddress((void**)&p_sc,    g_scores);
    cudaGetSymbolAddress((void**)&p_probs, g_probs);
    cudaGetSymbolAddress((void**)&p_vt,    g_vt);
    cudaGetSymbolAddress((void**)&p_ctxh,  g_ctxh);
    cudaGetSymbolAddress((void**)&p_ffnh,  g_ffnh);
    cudaGetSymbolAddress((void**)&p_woth,  g_woth);
    cudaGetSymbolAddress((void**)&p_w1th,  g_w1th);
    cudaGetSymbolAddress((void**)&p_w2th,  g_w2th);

    cudaFuncSetAttribute(hgemm, cudaFuncAttributeMaxDynamicSharedMemorySize,
                         H_SMEM_BYTES);

    // 0) weight transposes -> fp16 K-major [N][K]
    transpose_h<<<dim3(Dd / 32, Dd / 32), dim3(32, 8)>>>(Wo, p_woth, Dd, Dd);
    transpose_h<<<dim3(DFF / 32, Dd / 32), dim3(32, 8)>>>(W1, p_w1th, Dd, DFF);
    transpose_h<<<dim3(Dd / 32, DFF / 32), dim3(32, 8)>>>(W2, p_w2th, DFF, Dd);
    repack_qkv_t_h<<<dim3(HDd / 32, Dd / 32, 12), dim3(32, 8)>>>(Wq, Wk, Wv, p_wqkvh);

    // 1) h = LN(x) -> fp16
    ln_kernel_h<<<BT, 256>>>(x, g1, be1, p_lnh);

    // 2) QKV = h @ Wqkv^T -> fp32 (q,k,v all full precision)
    hgemm<<<dim3(NQKV / 128, BT / 128), 256, H_SMEM_BYTES>>>(
        p_lnh, Dd, 0, 0, p_wqkvh, Dd, 0, 0,
        p_qkv, NQKV, 0, 0, Dd, nullptr, nullptr, 0, 0, 0);

    // 3) scores = scale * q k^T with causal mask (fp32)
    scores_nt_kernel<<<dim3(Tt / 64, Tt / 64, Bb * Hh), 256>>>(p_qkv, p_sc);

    // 4) softmax -> fp16 probs
    softmax_h<<<Bb * Hh * Tt, 128>>>(p_sc, p_probs);

    // 5) v -> vt fp16 [b,h][c][s]
    vt_kernel<<<dim3(Tt / 32, HDd / 32, Bb * Hh), dim3(32, 8)>>>(p_qkv, p_vt);

    // 6) ctx = probs @ vt^T -> fp16 head-concat [BT][2048]
    hgemm<<<dim3(HDd / 128, Tt / 128, Bb * Hh), 256, H_SMEM_BYTES>>>(
        p_probs, Tt, 4LL * Tt * Tt, (long long)Tt * Tt,
        p_vt, Tt, 4LL * HDd * Tt, (long long)HDd * Tt,
        p_ctxh, Dd, (long long)Tt * Dd, (long long)HDd,
        Tt, nullptr, nullptr, 0, 0, 1);

    // 7) x2 = x + ctx @ Wo^T + bo -> d_out (fp32)
    hgemm<<<dim3(Dd / 128, BT / 128), 256, H_SMEM_BYTES>>>(
        p_ctxh, Dd, 0, 0, p_woth, Dd, 0, 0,
        out, Dd, 0, 0, Dd, bo, x, Dd, 0, 0);

    // 8) h2 = LN(x2) -> fp16
    ln_kernel_h<<<BT, 256>>>(out, g2, be2, p_lnh);

    // 9) u = relu(h2 @ W1^T + b1) -> fp16
    hgemm<<<dim3(DFF / 128, BT / 128), 256, H_SMEM_BYTES>>>(
        p_lnh, Dd, 0, 0, p_w1th, Dd, 0, 0,
        p_ffnh, DFF, 0, 0, Dd, b1, nullptr, 0, 1, 1);

    // 10) out = x2 + u @ W2^T + b2 (fp32, resid in place)
    hgemm<<<dim3(Dd / 128, BT / 128), 256, H_SMEM_BYTES>>>(
        p_ffnh, DFF, 0, 0, p_w2th, DFF, 0, 0,
        out, Dd, 0, 0, DFF, b2, out, Dd, 0, 0);
}

// round 12
// speedup vs baseline: 1.8606x; 1.0413x over previous
#include <cuda_runtime.h>
#include <cuda_fp16.h>
#include <math.h>
#include <stdint.h>

// Problem constants
#define Bb   16
#define Tt   512
#define Dd   2048
#define Hh   4
#define HDd  512
#define BT   8192          // B*T rows
#define NQKV 6144          // 3*D
#define DFF  8192          // 4*D
#define LNEPS 1e-5f

// ---------------------------------------------------------------------------
// Scratch (static __device__ arrays; no allocation allowed)
// ---------------------------------------------------------------------------
__device__ __align__(128) __half g_lnh[(size_t)BT * Dd];          // LN out fp16
__device__ __align__(128) __half g_wqkvh[(size_t)NQKV * Dd];      // [6144][2048] K-major
__device__ __align__(128) float  g_qkv[(size_t)BT * NQKV];        // fp32 q,k,v
__device__ __align__(128) float  g_scores[(size_t)Bb * Hh * Tt * Tt];
__device__ __align__(128) __half g_probs[(size_t)Bb * Hh * Tt * Tt];
__device__ __align__(128) __half g_vt[(size_t)Bb * Hh * HDd * Tt]; // [b,h][c][s]
__device__ __align__(128) __half g_ctxh[(size_t)BT * Dd];
__device__ __align__(128) __half g_ffnh[(size_t)BT * DFF];
__device__ __align__(128) __half g_woth[(size_t)Dd * Dd];         // [2048][2048] K-major
__device__ __align__(128) __half g_w1th[(size_t)DFF * Dd];        // [8192][2048] K-major
__device__ __align__(128) __half g_w2th[(size_t)Dd * DFF];        // [2048][8192] K-major

// ---------------------------------------------------------------------------
// PTX helpers
// ---------------------------------------------------------------------------
__device__ __forceinline__ uint32_t smem_u32(const void* p) {
    uint32_t a;
    asm("{ .reg .u64 t; cvta.to.shared.u64 t, %1; cvt.u32.u64 %0, t; }"
        : "=r"(a) : "l"(p));
    return a;
}
__device__ __forceinline__ void cp_async16(uint32_t smem_dst, const void* gmem_src) {
    asm volatile("cp.async.cg.shared.global [%0], [%1], 16;\n" :: "r"(smem_dst), "l"(gmem_src));
}
__device__ __forceinline__ void cp_commit() {
    asm volatile("cp.async.commit_group;\n");
}
template<int N>
__device__ __forceinline__ void cp_wait() {
    asm volatile("cp.async.wait_group %0;\n" :: "n"(N));
}
// fp16 tensor-core mma: D(f32) += A(f16,m16k16,row) * B(f16,n8k16,col)
__device__ __forceinline__ void mma_f16(float* c, const uint32_t* a, const uint32_t* b) {
    asm volatile(
        "mma.sync.aligned.m16n8k16.row.col.f32.f16.f16.f32 "
        "{%0,%1,%2,%3}, {%4,%5,%6,%7}, {%8,%9}, {%0,%1,%2,%3};"
        : "+f"(c[0]), "+f"(c[1]), "+f"(c[2]), "+f"(c[3])
        : "r"(a[0]), "r"(a[1]), "r"(a[2]), "r"(a[3]), "r"(b[0]), "r"(b[1]));
}

// ---------------------------------------------------------------------------
// Weight transpose + fp16 convert:  out[N][K] = half(in[K][N])
// ---------------------------------------------------------------------------
__global__ void transpose_h(const float* __restrict__ in,
                            __half* __restrict__ out, int K, int N) {
    __shared__ float t[32][33];
    int n0 = blockIdx.x * 32, k0 = blockIdx.y * 32;
    int lx = threadIdx.x, ly = threadIdx.y;
    #pragma unroll
    for (int i = 0; i < 32; i += 8)
        t[ly + i][lx] = in[(size_t)(k0 + ly + i) * N + n0 + lx];
    __syncthreads();
    #pragma unroll
    for (int i = 0; i < 32; i += 8)
        out[(size_t)(n0 + ly + i) * K + k0 + lx] = __float2half_rn(t[lx][ly + i]);
}

// Repack+transpose Wq/Wk/Wv [H,D,HD] -> half [3D][D] K-major.
__global__ void repack_qkv_t_h(const float* __restrict__ Wq,
                               const float* __restrict__ Wk,
                               const float* __restrict__ Wv,
                               __half* __restrict__ out) {
    __shared__ float t[32][33];
    int z = blockIdx.z;
    int sel = z >> 2, h = z & 3;
    const float* W = (sel == 0 ? Wq : sel == 1 ? Wk : Wv) + (size_t)h * Dd * HDd;
    int c0 = blockIdx.x * 32, k0 = blockIdx.y * 32;
    int lx = threadIdx.x, ly = threadIdx.y;
    #pragma unroll
    for (int i = 0; i < 32; i += 8)
        t[ly + i][lx] = W[(size_t)(k0 + ly + i) * HDd + c0 + lx];
    __syncthreads();
    int nbase = sel * 2048 + h * 512 + c0;
    #pragma unroll
    for (int i = 0; i < 32; i += 8)
        out[(size_t)(nbase + ly + i) * Dd + k0 + lx] = __float2half_rn(t[lx][ly + i]);
}

// v block of packed QKV (fp32) -> vt half [b,h][c=512][s=512]
__global__ void vt_kernel(const float* __restrict__ qkv, __half* __restrict__ vt) {
    __shared__ float t[32][33];
    int z = blockIdx.z;
    int bb = z >> 2, hh = z & 3;
    int s0 = blockIdx.x * 32;   // token
    int c0 = blockIdx.y * 32;   // channel
    int lx = threadIdx.x, ly = threadIdx.y;
    const float* src = qkv + (size_t)(bb * Tt) * NQKV + 4096 + hh * HDd;
    #pragma unroll
    for (int i = 0; i < 32; i += 8)
        t[ly + i][lx] = src[(size_t)(s0 + ly + i) * NQKV + c0 + lx];  // [s][c]
    __syncthreads();
    __half* dst = vt + (size_t)z * HDd * Tt;
    #pragma unroll
    for (int i = 0; i < 32; i += 8)
        dst[(size_t)(c0 + ly + i) * Tt + s0 + lx] = __float2half_rn(t[lx][ly + i]);
}

// ---------------------------------------------------------------------------
// LayerNorm: one block per row (D=2048), 256 threads. fp16 output.
// ---------------------------------------------------------------------------
__global__ void ln_kernel_h(const float* __restrict__ x,
                            const float* __restrict__ g,
                            const float* __restrict__ b,
                            __half* __restrict__ out) {
    int row = blockIdx.x;
    int t   = threadIdx.x;
    const float4* xr = (const float4*)(x + (size_t)row * Dd);
    float4 v0 = xr[t];
    float4 v1 = xr[t + 256];
    float s  = v0.x + v0.y + v0.z + v0.w + v1.x + v1.y + v1.z + v1.w;
    float sq = v0.x*v0.x + v0.y*v0.y + v0.z*v0.z + v0.w*v0.w
             + v1.x*v1.x + v1.y*v1.y + v1.z*v1.z + v1.w*v1.w;
    #pragma unroll
    for (int o = 16; o; o >>= 1) {
        s  += __shfl_xor_sync(0xffffffffu, s,  o);
        sq += __shfl_xor_sync(0xffffffffu, sq, o);
    }
    __shared__ float ss[8], ssq[8];
    int w = t >> 5;
    if ((t & 31) == 0) { ss[w] = s; ssq[w] = sq; }
    __syncthreads();
    float S = 0.f, SQ = 0.f;
    #pragma unroll
    for (int i = 0; i < 8; i++) { S += ss[i]; SQ += ssq[i]; }
    float mean = S * (1.f / Dd);
    float var  = SQ * (1.f / Dd) - mean * mean;
    float rstd = rsqrtf(var + LNEPS);

    const float4* gr = (const float4*)g;
    const float4* br = (const float4*)b;
    __half2* o2 = (__half2*)(out + (size_t)row * Dd);
    float4 gv = gr[t], bv = br[t];
    o2[2 * t]     = __floats2half2_rn((v0.x - mean) * rstd * gv.x + bv.x,
                                      (v0.y - mean) * rstd * gv.y + bv.y);
    o2[2 * t + 1] = __floats2half2_rn((v0.z - mean) * rstd * gv.z + bv.z,
                                      (v0.w - mean) * rstd * gv.w + bv.w);
    gv = gr[t + 256]; bv = br[t + 256];
    o2[2 * (t + 256)]     = __floats2half2_rn((v1.x - mean) * rstd * gv.x + bv.x,
                                              (v1.y - mean) * rstd * gv.y + bv.y);
    o2[2 * (t + 256) + 1] = __floats2half2_rn((v1.z - mean) * rstd * gv.z + bv.z,
                                              (v1.w - mean) * rstd * gv.w + bv.w);
}

// ---------------------------------------------------------------------------
// fp16 tensor-core GEMM: C[M,N] = A[M,K] @ Bt[N,K]^T (+bias)(+resid)(relu)
// A half [M][K] row-major (lda), Bt half [N][K] K-major (ldb).
// CTA 128x128x32, 256 threads = 8 warps (2m x 4n), warp tile 64x32,
// mma.sync.m16n8k16 f16->f32. 4-stage cp.async, dyn smem 80KB, 2 CTAs/SM.
// out_half: 1 = write fp16 C, 0 = write fp32 C.
// Batched over blockIdx.z with offsets sX1*(z>>2) + sX2*(z&3).
// ---------------------------------------------------------------------------
#define H_STAGES 4
#define H_ROWH 40                       // halves per smem row (32 + 8 pad)
#define H_TILE_BYTES (128 * H_ROWH * 2) // 10240 per operand
#define H_STAGE_BYTES (2 * H_TILE_BYTES)
#define H_SMEM_BYTES (H_STAGES * H_STAGE_BYTES)  // 81920

__global__ void __launch_bounds__(256, 2)
hgemm(const __half* __restrict__ A, int lda, long long sA1, long long sA2,
      const __half* __restrict__ B, int ldb, long long sB1, long long sB2,
      void* __restrict__ Cvoid, int ldc, long long sC1, long long sC2,
      int K,
      const float* __restrict__ bias,
      const float* __restrict__ resid, int ldr,
      int relu, int out_half) {
    extern __shared__ __align__(16) char sm_[];
    const uint32_t smem_u = smem_u32(sm_);

    int z  = blockIdx.z;
    int zb = z >> 2, zh = z & 3;
    A += sA1 * zb + sA2 * zh;
    B += sB1 * zb + sB2 * zh;

    const int m0 = blockIdx.y * 128;
    const int n0 = blockIdx.x * 128;
    const int tid  = threadIdx.x;
    const int lane = tid & 31;
    const int wid  = tid >> 5;
    const int g  = lane >> 2;        // groupID
    const int t4 = lane & 3;         // thread-in-group
    const int mw = (wid >> 2) * 64;  // warp m offset
    const int nw = (wid & 3) * 32;   // warp n offset

    // cp.async indices: tile = 128 rows x 32 halves (64B) = 512 16B chunks;
    // 256 threads x 2 chunks per operand.
    const int c_row0 = tid >> 2;          // 0..63
    const int c_row1 = c_row0 + 64;
    const int c_off  = (tid & 3) * 8;     // halves offset (16B chunks)

    auto issue = [&](int kt, int s) {
        const uint32_t sa = smem_u + s * H_STAGE_BYTES;
        const uint32_t sb = sa + H_TILE_BYTES;
        const __half* ap = A + (size_t)(m0) * lda + kt * 32 + c_off;
        const __half* bp = B + (size_t)(n0) * ldb + kt * 32 + c_off;
        cp_async16(sa + (uint32_t)(c_row0 * H_ROWH + c_off) * 2,
                   ap + (size_t)c_row0 * lda);
        cp_async16(sa + (uint32_t)(c_row1 * H_ROWH + c_off) * 2,
                   ap + (size_t)c_row1 * lda);
        cp_async16(sb + (uint32_t)(c_row0 * H_ROWH + c_off) * 2,
                   bp + (size_t)c_row0 * ldb);
        cp_async16(sb + (uint32_t)(c_row1 * H_ROWH + c_off) * 2,
                   bp + (size_t)c_row1 * ldb);
        cp_commit();
    };

    float acc[4][4][4];
    #pragma unroll
    for (int mi = 0; mi < 4; mi++)
        #pragma unroll
        for (int ni = 0; ni < 4; ni++)
            #pragma unroll
            for (int q = 0; q < 4; q++) acc[mi][ni][q] = 0.f;

    const int nk = K >> 5;   // K-chunks of 32 (all call sites: nk >= 16)
    issue(0, 0);
    issue(1, 1);
    issue(2, 2);

    for (int kt = 0; kt < nk; kt++) {
        const int cur = kt % H_STAGES;
        // tile kt must be resident; up to 2 younger groups may stay in flight
        if (kt + 2 < nk)      cp_wait<2>();
        else if (kt + 1 < nk) cp_wait<1>();
        else                  cp_wait<0>();
        __syncthreads();
        if (kt + 3 < nk) issue(kt + 3, (kt + 3) % H_STAGES);

        const __half* Asc = (const __half*)(sm_ + cur * H_STAGE_BYTES);
        const __half* Bsc = Asc + 128 * H_ROWH;
        #pragma unroll
        for (int ks = 0; ks < 2; ks++) {
            const int kc = ks * 16 + 2 * t4;
            uint32_t af[4][4], bf[4][2];
            #pragma unroll
            for (int mi = 0; mi < 4; mi++) {
                const int r = mw + mi * 16 + g;
                af[mi][0] = *(const uint32_t*)(Asc + r * H_ROWH + kc);
                af[mi][1] = *(const uint32_t*)(Asc + (r + 8) * H_ROWH + kc);
                af[mi][2] = *(const uint32_t*)(Asc + r * H_ROWH + kc + 8);
                af[mi][3] = *(const uint32_t*)(Asc + (r + 8) * H_ROWH + kc + 8);
            }
            #pragma unroll
            for (int ni = 0; ni < 4; ni++) {
                const int nn = nw + ni * 8 + g;
                bf[ni][0] = *(const uint32_t*)(Bsc + nn * H_ROWH + kc);
                bf[ni][1] = *(const uint32_t*)(Bsc + nn * H_ROWH + kc + 8);
            }
            #pragma unroll
            for (int mi = 0; mi < 4; mi++)
                #pragma unroll
                for (int ni = 0; ni < 4; ni++)
                    mma_f16(acc[mi][ni], af[mi], bf[ni]);
        }
    }

    // Epilogue: c0,c1 -> (row g, cols 2t4, 2t4+1); c2,c3 -> row g+8.
    float* Cf = (float*)Cvoid + sC1 * zb + sC2 * zh;
    __half* Ch = (__half*)Cvoid + sC1 * zb + sC2 * zh;
    #pragma unroll
    for (int mi = 0; mi < 4; mi++) {
        const int r0 = m0 + mw + mi * 16 + g;
        #pragma unroll
        for (int ni = 0; ni < 4; ni++) {
            const int c0 = n0 + nw + ni * 8 + t4 * 2;
            float bb0 = 0.f, bb1 = 0.f;
            if (bias) { bb0 = bias[c0]; bb1 = bias[c0 + 1]; }
            float v0 = acc[mi][ni][0] + bb0;
            float v1 = acc[mi][ni][1] + bb1;
            float v2 = acc[mi][ni][2] + bb0;
            float v3 = acc[mi][ni][3] + bb1;
            if (resid) {
                const float* R0 = resid + (size_t)r0 * ldr + c0;
                const float* R1 = resid + (size_t)(r0 + 8) * ldr + c0;
                v0 += R0[0]; v1 += R0[1];
                v2 += R1[0]; v3 += R1[1];
            }
            if (relu) {
                v0 = fmaxf(v0, 0.f); v1 = fmaxf(v1, 0.f);
                v2 = fmaxf(v2, 0.f); v3 = fmaxf(v3, 0.f);
            }
            if (out_half) {
                *(__half2*)&Ch[(size_t)r0 * ldc + c0]       = __floats2half2_rn(v0, v1);
                *(__half2*)&Ch[(size_t)(r0 + 8) * ldc + c0] = __floats2half2_rn(v2, v3);
            } else {
                *(float2*)&Cf[(size_t)r0 * ldc + c0]       = make_float2(v0, v1);
                *(float2*)&Cf[(size_t)(r0 + 8) * ldc + c0] = make_float2(v2, v3);
            }
        }
    }
}

// ---------------------------------------------------------------------------
// Scores (fp32): S = scale * q k^T, causal mask. 128x128 tiles, NT,
// 8x8 per thread (8 smem floats per 64 FMA). Above-diagonal tiles filled.
// q,k arrive in full fp32 precision from the QKV GEMM.
// ---------------------------------------------------------------------------
__global__ void __launch_bounds__(256)
scores_nt_kernel(const float* __restrict__ QKV, float* __restrict__ S) {
    int z = blockIdx.z;
    int bb = z >> 2, hh = z & 3;
    const float* Aq = QKV + (size_t)bb * Tt * NQKV + hh * HDd;
    const float* Ak = Aq + Dd;
    float* Cs = S + (size_t)z * Tt * Tt;

    const int m0 = blockIdx.y * 128;
    const int n0 = blockIdx.x * 128;
    const int tid = threadIdx.x;
    const int ty = tid >> 4, tx = tid & 15;

    if (n0 > m0) {  // fully above diagonal: fill -1e30
        float4 mm; mm.x = mm.y = mm.z = mm.w = -1e30f;
        #pragma unroll
        for (int i = 0; i < 8; i++) {
            int gi = m0 + ty * 8 + i;
            *(float4*)&Cs[(size_t)gi * Tt + n0 + tx * 8]     = mm;
            *(float4*)&Cs[(size_t)gi * Tt + n0 + tx * 8 + 4] = mm;
        }
        return;
    }

    __shared__ __align__(16) float As[2][16][128];
    __shared__ __align__(16) float Bs[2][16][128];

    const int lrow = tid >> 2;          // 0..63
    const int lcol = (tid & 3) * 4;     // 0,4,8,12

    float4 ra[2], rb[2];
    auto loadT = [&](int kt) {
        ra[0] = *(const float4*)(Aq + (size_t)(m0 + lrow) * NQKV + kt * 16 + lcol);
        ra[1] = *(const float4*)(Aq + (size_t)(m0 + lrow + 64) * NQKV + kt * 16 + lcol);
        rb[0] = *(const float4*)(Ak + (size_t)(n0 + lrow) * NQKV + kt * 16 + lcol);
        rb[1] = *(const float4*)(Ak + (size_t)(n0 + lrow + 64) * NQKV + kt * 16 + lcol);
    };
    auto storeT = [&](int buf) {
        #pragma unroll
        for (int p = 0; p < 2; p++) {
            int r = lrow + p * 64;
            As[buf][lcol + 0][r] = ra[p].x; As[buf][lcol + 1][r] = ra[p].y;
            As[buf][lcol + 2][r] = ra[p].z; As[buf][lcol + 3][r] = ra[p].w;
            Bs[buf][lcol + 0][r] = rb[p].x; Bs[buf][lcol + 1][r] = rb[p].y;
            Bs[buf][lcol + 2][r] = rb[p].z; Bs[buf][lcol + 3][r] = rb[p].w;
        }
    };

    float acc[8][8];
    #pragma unroll
    for (int i = 0; i < 8; i++)
        #pragma unroll
        for (int j = 0; j < 8; j++) acc[i][j] = 0.f;

    loadT(0); storeT(0);
    __syncthreads();

    const int nk = HDd / 16;   // 32
    for (int kt = 0; kt < nk; kt++) {
        int cur = kt & 1;
        if (kt + 1 < nk) loadT(kt + 1);
        #pragma unroll
        for (int kk = 0; kk < 16; kk++) {
            float a[8], bvv[8];
            *(float4*)(a)       = *(const float4*)&As[cur][kk][ty * 8];
            *(float4*)(a + 4)   = *(const float4*)&As[cur][kk][ty * 8 + 4];
            *(float4*)(bvv)     = *(const float4*)&Bs[cur][kk][tx * 8];
            *(float4*)(bvv + 4) = *(const float4*)&Bs[cur][kk][tx * 8 + 4];
            #pragma unroll
            for (int i = 0; i < 8; i++)
                #pragma unroll
                for (int j = 0; j < 8; j++)
                    acc[i][j] += a[i] * bvv[j];
        }
        if (kt + 1 < nk) {
            storeT(cur ^ 1);
            __syncthreads();
        }
    }

    const float scale = 0.044194173824159216f;
    #pragma unroll
    for (int i = 0; i < 8; i++) {
        int gi = m0 + ty * 8 + i;
        float v[8];
        #pragma unroll
        for (int j = 0; j < 8; j++) {
            int gj = n0 + tx * 8 + j;
            v[j] = (gj > gi) ? -1e30f : acc[i][j] * scale;
        }
        float4 o0, o1;
        o0.x = v[0]; o0.y = v[1]; o0.z = v[2]; o0.w = v[3];
        o1.x = v[4]; o1.y = v[5]; o1.z = v[6]; o1.w = v[7];
        *(float4*)&Cs[(size_t)gi * Tt + n0 + tx * 8]     = o0;
        *(float4*)&Cs[(size_t)gi * Tt + n0 + tx * 8 + 4] = o1;
    }
}

// ---------------------------------------------------------------------------
// Row softmax over T=512 (fp32 in) -> fp16 probs out.
// ---------------------------------------------------------------------------
__global__ void softmax_h(const float* __restrict__ S, __half* __restrict__ P) {
    int row = blockIdx.x;
    int t = threadIdx.x;
    const float4* p = (const float4*)(S + (size_t)row * Tt);
    float4 v = p[t];
    float m = fmaxf(fmaxf(v.x, v.y), fmaxf(v.z, v.w));
    #pragma unroll
    for (int o = 16; o; o >>= 1) m = fmaxf(m, __shfl_xor_sync(0xffffffffu, m, o));
    __shared__ float sm[4], ssum[4];
    int w = t >> 5;
    if ((t & 31) == 0) sm[w] = m;
    __syncthreads();
    m = fmaxf(fmaxf(sm[0], sm[1]), fmaxf(sm[2], sm[3]));
    v.x = expf(v.x - m); v.y = expf(v.y - m);
    v.z = expf(v.z - m); v.w = expf(v.w - m);
    float s = v.x + v.y + v.z + v.w;
    #pragma unroll
    for (int o = 16; o; o >>= 1) s += __shfl_xor_sync(0xffffffffu, s, o);
    if ((t & 31) == 0) ssum[w] = s;
    __syncthreads();
    s = ssum[0] + ssum[1] + ssum[2] + ssum[3];
    float inv = 1.f / s;
    __half2* ph = (__half2*)(P + (size_t)row * Tt);
    ph[2 * t]     = __floats2half2_rn(v.x * inv, v.y * inv);
    ph[2 * t + 1] = __floats2half2_rn(v.z * inv, v.w * inv);
}

// ---------------------------------------------------------------------------
// Host launcher
// ---------------------------------------------------------------------------
extern "C" void kernel_launch(void* const* d_in, const int* in_sizes, int n_in,
                              void* d_out, int out_size) {
    const float* x   = (const float*)d_in[0];
    const float* Wq  = (const float*)d_in[1];
    const float* Wk  = (const float*)d_in[2];
    const float* Wv  = (const float*)d_in[3];
    const float* Wo  = (const float*)d_in[4];
    const float* bo  = (const float*)d_in[5];
    const float* W1  = (const float*)d_in[6];
    const float* b1  = (const float*)d_in[7];
    const float* W2  = (const float*)d_in[8];
    const float* b2  = (const float*)d_in[9];
    const float* g1  = (const float*)d_in[10];
    const float* be1 = (const float*)d_in[11];
    const float* g2  = (const float*)d_in[12];
    const float* be2 = (const float*)d_in[13];
    float* out = (float*)d_out;

    __half *p_lnh, *p_wqkvh, *p_probs, *p_vt, *p_ctxh, *p_ffnh, *p_woth, *p_w1th, *p_w2th;
    float *p_qkv, *p_sc;
    cudaGetSymbolAddress((void**)&p_lnh,   g_lnh);
    cudaGetSymbolAddress((void**)&p_wqkvh, g_wqkvh);
    cudaGetSymbolAddress((void**)&p_qkv,   g_qkv);
    cudaGetSymbolAddress((void**)&p_sc,    g_scores);
    cudaGetSymbolAddress((void**)&p_probs, g_probs);
    cudaGetSymbolAddress((void**)&p_vt,    g_vt);
    cudaGetSymbolAddress((void**)&p_ctxh,  g_ctxh);
    cudaGetSymbolAddress((void**)&p_ffnh,  g_ffnh);
    cudaGetSymbolAddress((void**)&p_woth,  g_woth);
    cudaGetSymbolAddress((void**)&p_w1th,  g_w1th);
    cudaGetSymbolAddress((void**)&p_w2th,  g_w2th);

    cudaFuncSetAttribute(hgemm, cudaFuncAttributeMaxDynamicSharedMemorySize,
                         H_SMEM_BYTES);

    // 0) weight transposes -> fp16 K-major [N][K]
    transpose_h<<<dim3(Dd / 32, Dd / 32), dim3(32, 8)>>>(Wo, p_woth, Dd, Dd);
    transpose_h<<<dim3(DFF / 32, Dd / 32), dim3(32, 8)>>>(W1, p_w1th, Dd, DFF);
    transpose_h<<<dim3(Dd / 32, DFF / 32), dim3(32, 8)>>>(W2, p_w2th, DFF, Dd);
    repack_qkv_t_h<<<dim3(HDd / 32, Dd / 32, 12), dim3(32, 8)>>>(Wq, Wk, Wv, p_wqkvh);

    // 1) h = LN(x) -> fp16
    ln_kernel_h<<<BT, 256>>>(x, g1, be1, p_lnh);

    // 2) QKV = h @ Wqkv^T -> fp32 (q,k,v all full precision)
    hgemm<<<dim3(NQKV / 128, BT / 128), 256, H_SMEM_BYTES>>>(
        p_lnh, Dd, 0, 0, p_wqkvh, Dd, 0, 0,
        p_qkv, NQKV, 0, 0, Dd, nullptr, nullptr, 0, 0, 0);

    // 3) scores = scale * q k^T with causal mask (fp32, 128x128 tiles)
    scores_nt_kernel<<<dim3(Tt / 128, Tt / 128, Bb * Hh), 256>>>(p_qkv, p_sc);

    // 4) softmax -> fp16 probs
    softmax_h<<<Bb * Hh * Tt, 128>>>(p_sc, p_probs);

    // 5) v -> vt fp16 [b,h][c][s]
    vt_kernel<<<dim3(Tt / 32, HDd / 32, Bb * Hh), dim3(32, 8)>>>(p_qkv, p_vt);

    // 6) ctx = probs @ vt^T -> fp16 head-concat [BT][2048]
    hgemm<<<dim3(HDd / 128, Tt / 128, Bb * Hh), 256, H_SMEM_BYTES>>>(
        p_probs, Tt, 4LL * Tt * Tt, (long long)Tt * Tt,
        p_vt, Tt, 4LL * HDd * Tt, (long long)HDd * Tt,
        p_ctxh, Dd, (long long)Tt * Dd, (long long)HDd,
        Tt, nullptr, nullptr, 0, 0, 1);

    // 7) x2 = x + ctx @ Wo^T + bo -> d_out (fp32)
    hgemm<<<dim3(Dd / 128, BT / 128), 256, H_SMEM_BYTES>>>(
        p_ctxh, Dd, 0, 0, p_woth, Dd, 0, 0,
        out, Dd, 0, 0, Dd, bo, x, Dd, 0, 0);

    // 8) h2 = LN(x2) -> fp16
    ln_kernel_h<<<BT, 256>>>(out, g2, be2, p_lnh);

    // 9) u = relu(h2 @ W1^T + b1) -> fp16
    hgemm<<<dim3(DFF / 128, BT / 128), 256, H_SMEM_BYTES>>>(
        p_lnh, Dd, 0, 0, p_w1th, Dd, 0, 0,
        p_ffnh, DFF, 0, 0, Dd, b1, nullptr, 0, 1, 1);

    // 10) out = x2 + u @ W2^T + b2 (fp32, resid in place)
    hgemm<<<dim3(Dd / 128, BT / 128), 256, H_SMEM_BYTES>>>(
        p_ffnh, DFF, 0, 0, p_w2th, DFF, 0, 0,
        out, Dd, 0, 0, DFF, b2, out, Dd, 0, 0);
}

// round 13
// speedup vs baseline: 1.9680x; 1.0578x over previous
#include <cuda_runtime.h>
#include <cuda_fp16.h>
#include <math.h>
#include <stdint.h>

// Problem constants
#define Bb   16
#define Tt   512
#define Dd   2048
#define Hh   4
#define HDd  512
#define BT   8192          // B*T rows
#define NQKV 6144          // 3*D
#define DFF  8192          // 4*D
#define LNEPS 1e-5f

// ---------------------------------------------------------------------------
// Scratch (static __device__ arrays; no allocation allowed)
// ---------------------------------------------------------------------------
__device__ __align__(128) __half g_lnh[(size_t)BT * Dd];          // LN out fp16
__device__ __align__(128) __half g_wqkvh[(size_t)NQKV * Dd];      // [6144][2048] K-major
__device__ __align__(128) __half g_qkvh[(size_t)BT * NQKV];       // fp16 q,k,v
__device__ __align__(128) float  g_scores[(size_t)Bb * Hh * Tt * Tt];
__device__ __align__(128) __half g_probs[(size_t)Bb * Hh * Tt * Tt];
__device__ __align__(128) __half g_vt[(size_t)Bb * Hh * HDd * Tt]; // [b,h][c][s]
__device__ __align__(128) __half g_ctxh[(size_t)BT * Dd];
__device__ __align__(128) __half g_ffnh[(size_t)BT * DFF];
__device__ __align__(128) __half g_woth[(size_t)Dd * Dd];         // [2048][2048] K-major
__device__ __align__(128) __half g_w1th[(size_t)DFF * Dd];        // [8192][2048] K-major
__device__ __align__(128) __half g_w2th[(size_t)Dd * DFF];        // [2048][8192] K-major

// ---------------------------------------------------------------------------
// PTX helpers
// ---------------------------------------------------------------------------
__device__ __forceinline__ uint32_t smem_u32(const void* p) {
    uint32_t a;
    asm("{ .reg .u64 t; cvta.to.shared.u64 t, %1; cvt.u32.u64 %0, t; }"
        : "=r"(a) : "l"(p));
    return a;
}
__device__ __forceinline__ void cp_async16(uint32_t smem_dst, const void* gmem_src) {
    asm volatile("cp.async.cg.shared.global [%0], [%1], 16;\n" :: "r"(smem_dst), "l"(gmem_src));
}
__device__ __forceinline__ void cp_commit() {
    asm volatile("cp.async.commit_group;\n");
}
template<int N>
__device__ __forceinline__ void cp_wait() {
    asm volatile("cp.async.wait_group %0;\n" :: "n"(N));
}
// fp16 tensor-core mma: D(f32) += A(f16,m16k16,row) * B(f16,n8k16,col)
__device__ __forceinline__ void mma_f16(float* c, const uint32_t* a, const uint32_t* b) {
    asm volatile(
        "mma.sync.aligned.m16n8k16.row.col.f32.f16.f16.f32 "
        "{%0,%1,%2,%3}, {%4,%5,%6,%7}, {%8,%9}, {%0,%1,%2,%3};"
        : "+f"(c[0]), "+f"(c[1]), "+f"(c[2]), "+f"(c[3])
        : "r"(a[0]), "r"(a[1]), "r"(a[2]), "r"(a[3]), "r"(b[0]), "r"(b[1]));
}

// ---------------------------------------------------------------------------
// Weight transpose + fp16 convert:  out[N][K] = half(in[K][N])
// ---------------------------------------------------------------------------
__global__ void transpose_h(const float* __restrict__ in,
                            __half* __restrict__ out, int K, int N) {
    __shared__ float t[32][33];
    int n0 = blockIdx.x * 32, k0 = blockIdx.y * 32;
    int lx = threadIdx.x, ly = threadIdx.y;
    #pragma unroll
    for (int i = 0; i < 32; i += 8)
        t[ly + i][lx] = in[(size_t)(k0 + ly + i) * N + n0 + lx];
    __syncthreads();
    #pragma unroll
    for (int i = 0; i < 32; i += 8)
        out[(size_t)(n0 + ly + i) * K + k0 + lx] = __float2half_rn(t[lx][ly + i]);
}

// Repack+transpose Wq/Wk/Wv [H,D,HD] -> half [3D][D] K-major.
__global__ void repack_qkv_t_h(const float* __restrict__ Wq,
                               const float* __restrict__ Wk,
                               const float* __restrict__ Wv,
                               __half* __restrict__ out) {
    __shared__ float t[32][33];
    int z = blockIdx.z;
    int sel = z >> 2, h = z & 3;
    const float* W = (sel == 0 ? Wq : sel == 1 ? Wk : Wv) + (size_t)h * Dd * HDd;
    int c0 = blockIdx.x * 32, k0 = blockIdx.y * 32;
    int lx = threadIdx.x, ly = threadIdx.y;
    #pragma unroll
    for (int i = 0; i < 32; i += 8)
        t[ly + i][lx] = W[(size_t)(k0 + ly + i) * HDd + c0 + lx];
    __syncthreads();
    int nbase = sel * 2048 + h * 512 + c0;
    #pragma unroll
    for (int i = 0; i < 32; i += 8)
        out[(size_t)(nbase + ly + i) * Dd + k0 + lx] = __float2half_rn(t[lx][ly + i]);
}

// v block of packed fp16 QKV -> vt half [b,h][c=512][s=512]
__global__ void vt_kernel(const __half* __restrict__ qkvh, __half* __restrict__ vt) {
    __shared__ float t[32][33];
    int z = blockIdx.z;
    int bb = z >> 2, hh = z & 3;
    int s0 = blockIdx.x * 32;   // token
    int c0 = blockIdx.y * 32;   // channel
    int lx = threadIdx.x, ly = threadIdx.y;
    const __half* src = qkvh + (size_t)(bb * Tt) * NQKV + 4096 + hh * HDd;
    #pragma unroll
    for (int i = 0; i < 32; i += 8)
        t[ly + i][lx] = __half2float(src[(size_t)(s0 + ly + i) * NQKV + c0 + lx]);
    __syncthreads();
    __half* dst = vt + (size_t)z * HDd * Tt;
    #pragma unroll
    for (int i = 0; i < 32; i += 8)
        dst[(size_t)(c0 + ly + i) * Tt + s0 + lx] = __float2half_rn(t[lx][ly + i]);
}

// ---------------------------------------------------------------------------
// LayerNorm: one block per row (D=2048), 256 threads. fp16 output.
// ---------------------------------------------------------------------------
__global__ void ln_kernel_h(const float* __restrict__ x,
                            const float* __restrict__ g,
                            const float* __restrict__ b,
                            __half* __restrict__ out) {
    int row = blockIdx.x;
    int t   = threadIdx.x;
    const float4* xr = (const float4*)(x + (size_t)row * Dd);
    float4 v0 = xr[t];
    float4 v1 = xr[t + 256];
    float s  = v0.x + v0.y + v0.z + v0.w + v1.x + v1.y + v1.z + v1.w;
    float sq = v0.x*v0.x + v0.y*v0.y + v0.z*v0.z + v0.w*v0.w
             + v1.x*v1.x + v1.y*v1.y + v1.z*v1.z + v1.w*v1.w;
    #pragma unroll
    for (int o = 16; o; o >>= 1) {
        s  += __shfl_xor_sync(0xffffffffu, s,  o);
        sq += __shfl_xor_sync(0xffffffffu, sq, o);
    }
    __shared__ float ss[8], ssq[8];
    int w = t >> 5;
    if ((t & 31) == 0) { ss[w] = s; ssq[w] = sq; }
    __syncthreads();
    float S = 0.f, SQ = 0.f;
    #pragma unroll
    for (int i = 0; i < 8; i++) { S += ss[i]; SQ += ssq[i]; }
    float mean = S * (1.f / Dd);
    float var  = SQ * (1.f / Dd) - mean * mean;
    float rstd = rsqrtf(var + LNEPS);

    const float4* gr = (const float4*)g;
    const float4* br = (const float4*)b;
    __half2* o2 = (__half2*)(out + (size_t)row * Dd);
    float4 gv = gr[t], bv = br[t];
    o2[2 * t]     = __floats2half2_rn((v0.x - mean) * rstd * gv.x + bv.x,
                                      (v0.y - mean) * rstd * gv.y + bv.y);
    o2[2 * t + 1] = __floats2half2_rn((v0.z - mean) * rstd * gv.z + bv.z,
                                      (v0.w - mean) * rstd * gv.w + bv.w);
    gv = gr[t + 256]; bv = br[t + 256];
    o2[2 * (t + 256)]     = __floats2half2_rn((v1.x - mean) * rstd * gv.x + bv.x,
                                              (v1.y - mean) * rstd * gv.y + bv.y);
    o2[2 * (t + 256) + 1] = __floats2half2_rn((v1.z - mean) * rstd * gv.z + bv.z,
                                              (v1.w - mean) * rstd * gv.w + bv.w);
}

// ---------------------------------------------------------------------------
// fp16 tensor-core GEMM: C[M,N] = A[M,K] @ Bt[N,K]^T (+bias)(+resid)(relu)
// A half [M][K] row-major (lda), Bt half [N][K] K-major (ldb).
// CTA 128x128x32, 256 threads = 8 warps (2m x 4n), warp tile 64x32,
// mma.sync.m16n8k16 f16->f32. 4-stage cp.async, dyn smem 80KB, 2 CTAs/SM.
// out_half: 1 = write fp16 C, 0 = write fp32 C.
// causal: if 1, limit K to m0+128 (valid when A cols >= m0+128 are zero).
// Batched over blockIdx.z with offsets sX1*(z>>2) + sX2*(z&3).
// ---------------------------------------------------------------------------
#define H_STAGES 4
#define H_ROWH 40                       // halves per smem row (32 + 8 pad)
#define H_TILE_BYTES (128 * H_ROWH * 2) // 10240 per operand
#define H_STAGE_BYTES (2 * H_TILE_BYTES)
#define H_SMEM_BYTES (H_STAGES * H_STAGE_BYTES)  // 81920

__global__ void __launch_bounds__(256, 2)
hgemm(const __half* __restrict__ A, int lda, long long sA1, long long sA2,
      const __half* __restrict__ B, int ldb, long long sB1, long long sB2,
      void* __restrict__ Cvoid, int ldc, long long sC1, long long sC2,
      int K,
      const float* __restrict__ bias,
      const float* __restrict__ resid, int ldr,
      int relu, int out_half, int causal) {
    extern __shared__ __align__(16) char sm_[];
    const uint32_t smem_u = smem_u32(sm_);

    int z  = blockIdx.z;
    int zb = z >> 2, zh = z & 3;
    A += sA1 * zb + sA2 * zh;
    B += sB1 * zb + sB2 * zh;

    const int m0 = blockIdx.y * 128;
    const int n0 = blockIdx.x * 128;
    const int tid  = threadIdx.x;
    const int lane = tid & 31;
    const int wid  = tid >> 5;
    const int g  = lane >> 2;        // groupID
    const int t4 = lane & 3;         // thread-in-group
    const int mw = (wid >> 2) * 64;  // warp m offset
    const int nw = (wid & 3) * 32;   // warp n offset

    if (causal && m0 + 128 < K) K = m0 + 128;   // zero prob cols: skip (exact)

    const int c_row0 = tid >> 2;          // 0..63
    const int c_row1 = c_row0 + 64;
    const int c_off  = (tid & 3) * 8;     // halves offset (16B chunks)

    auto issue = [&](int kt, int s) {
        const uint32_t sa = smem_u + s * H_STAGE_BYTES;
        const uint32_t sb = sa + H_TILE_BYTES;
        const __half* ap = A + (size_t)(m0) * lda + kt * 32 + c_off;
        const __half* bp = B + (size_t)(n0) * ldb + kt * 32 + c_off;
        cp_async16(sa + (uint32_t)(c_row0 * H_ROWH + c_off) * 2,
                   ap + (size_t)c_row0 * lda);
        cp_async16(sa + (uint32_t)(c_row1 * H_ROWH + c_off) * 2,
                   ap + (size_t)c_row1 * lda);
        cp_async16(sb + (uint32_t)(c_row0 * H_ROWH + c_off) * 2,
                   bp + (size_t)c_row0 * ldb);
        cp_async16(sb + (uint32_t)(c_row1 * H_ROWH + c_off) * 2,
                   bp + (size_t)c_row1 * ldb);
        cp_commit();
    };

    float acc[4][4][4];
    #pragma unroll
    for (int mi = 0; mi < 4; mi++)
        #pragma unroll
        for (int ni = 0; ni < 4; ni++)
            #pragma unroll
            for (int q = 0; q < 4; q++) acc[mi][ni][q] = 0.f;

    const int nk = K >> 5;   // K-chunks of 32 (all call sites: nk >= 4)
    issue(0, 0);
    issue(1, 1);
    issue(2, 2);

    for (int kt = 0; kt < nk; kt++) {
        const int cur = kt % H_STAGES;
        if (kt + 2 < nk)      cp_wait<2>();
        else if (kt + 1 < nk) cp_wait<1>();
        else                  cp_wait<0>();
        __syncthreads();
        if (kt + 3 < nk) issue(kt + 3, (kt + 3) % H_STAGES);

        const __half* Asc = (const __half*)(sm_ + cur * H_STAGE_BYTES);
        const __half* Bsc = Asc + 128 * H_ROWH;
        #pragma unroll
        for (int ks = 0; ks < 2; ks++) {
            const int kc = ks * 16 + 2 * t4;
            uint32_t af[4][4], bf[4][2];
            #pragma unroll
            for (int mi = 0; mi < 4; mi++) {
                const int r = mw + mi * 16 + g;
                af[mi][0] = *(const uint32_t*)(Asc + r * H_ROWH + kc);
                af[mi][1] = *(const uint32_t*)(Asc + (r + 8) * H_ROWH + kc);
                af[mi][2] = *(const uint32_t*)(Asc + r * H_ROWH + kc + 8);
                af[mi][3] = *(const uint32_t*)(Asc + (r + 8) * H_ROWH + kc + 8);
            }
            #pragma unroll
            for (int ni = 0; ni < 4; ni++) {
                const int nn = nw + ni * 8 + g;
                bf[ni][0] = *(const uint32_t*)(Bsc + nn * H_ROWH + kc);
                bf[ni][1] = *(const uint32_t*)(Bsc + nn * H_ROWH + kc + 8);
            }
            #pragma unroll
            for (int mi = 0; mi < 4; mi++)
                #pragma unroll
                for (int ni = 0; ni < 4; ni++)
                    mma_f16(acc[mi][ni], af[mi], bf[ni]);
        }
    }

    // Epilogue: c0,c1 -> (row g, cols 2t4, 2t4+1); c2,c3 -> row g+8.
    float* Cf = (float*)Cvoid + sC1 * zb + sC2 * zh;
    __half* Ch = (__half*)Cvoid + sC1 * zb + sC2 * zh;
    #pragma unroll
    for (int mi = 0; mi < 4; mi++) {
        const int r0 = m0 + mw + mi * 16 + g;
        #pragma unroll
        for (int ni = 0; ni < 4; ni++) {
            const int c0 = n0 + nw + ni * 8 + t4 * 2;
            float bb0 = 0.f, bb1 = 0.f;
            if (bias) { bb0 = bias[c0]; bb1 = bias[c0 + 1]; }
            float v0 = acc[mi][ni][0] + bb0;
            float v1 = acc[mi][ni][1] + bb1;
            float v2 = acc[mi][ni][2] + bb0;
            float v3 = acc[mi][ni][3] + bb1;
            if (resid) {
                const float* R0 = resid + (size_t)r0 * ldr + c0;
                const float* R1 = resid + (size_t)(r0 + 8) * ldr + c0;
                v0 += R0[0]; v1 += R0[1];
                v2 += R1[0]; v3 += R1[1];
            }
            if (relu) {
                v0 = fmaxf(v0, 0.f); v1 = fmaxf(v1, 0.f);
                v2 = fmaxf(v2, 0.f); v3 = fmaxf(v3, 0.f);
            }
            if (out_half) {
                *(__half2*)&Ch[(size_t)r0 * ldc + c0]       = __floats2half2_rn(v0, v1);
                *(__half2*)&Ch[(size_t)(r0 + 8) * ldc + c0] = __floats2half2_rn(v2, v3);
            } else {
                *(float2*)&Cf[(size_t)r0 * ldc + c0]       = make_float2(v0, v1);
                *(float2*)&Cf[(size_t)(r0 + 8) * ldc + c0] = make_float2(v2, v3);
            }
        }
    }
}

// ---------------------------------------------------------------------------
// Scores on tensor cores: S = scale * q k^T (fp16 in, fp32 accum/out),
// causal mask, above-diagonal tile skip. Same core as hgemm, batched over
// 64 (b,h). A = q rows, B = k rows (both in packed fp16 QKV, K-major).
// ---------------------------------------------------------------------------
__global__ void __launch_bounds__(256, 2)
scores_h(const __half* __restrict__ QKVh, float* __restrict__ S) {
    extern __shared__ __align__(16) char sm_[];
    const uint32_t smem_u = smem_u32(sm_);

    const int z = blockIdx.z;
    const int bb = z >> 2, hh = z & 3;
    const __half* A = QKVh + (size_t)(bb * Tt) * NQKV + hh * HDd;   // q
    const __half* B = A + Dd;                                       // k
    float* Cs = S + (size_t)z * Tt * Tt;

    const int m0 = blockIdx.y * 128;
    const int n0 = blockIdx.x * 128;
    const int tid  = threadIdx.x;
    const int lane = tid & 31;
    const int wid  = tid >> 5;
    const int g  = lane >> 2;
    const int t4 = lane & 3;
    const int mw = (wid >> 2) * 64;
    const int nw = (wid & 3) * 32;

    if (n0 > m0) {   // fully above diagonal
        #pragma unroll
        for (int mi = 0; mi < 4; mi++) {
            const int r0 = m0 + mw + mi * 16 + g;
            #pragma unroll
            for (int ni = 0; ni < 4; ni++) {
                const int c0 = n0 + nw + ni * 8 + t4 * 2;
                *(float2*)&Cs[(size_t)r0 * Tt + c0]       = make_float2(-1e30f, -1e30f);
                *(float2*)&Cs[(size_t)(r0 + 8) * Tt + c0] = make_float2(-1e30f, -1e30f);
            }
        }
        return;
    }

    const int c_row0 = tid >> 2;
    const int c_row1 = c_row0 + 64;
    const int c_off  = (tid & 3) * 8;

    auto issue = [&](int kt, int s) {
        const uint32_t sa = smem_u + s * H_STAGE_BYTES;
        const uint32_t sb = sa + H_TILE_BYTES;
        const __half* ap = A + (size_t)(m0) * NQKV + kt * 32 + c_off;
        const __half* bp = B + (size_t)(n0) * NQKV + kt * 32 + c_off;
        cp_async16(sa + (uint32_t)(c_row0 * H_ROWH + c_off) * 2,
                   ap + (size_t)c_row0 * NQKV);
        cp_async16(sa + (uint32_t)(c_row1 * H_ROWH + c_off) * 2,
                   ap + (size_t)c_row1 * NQKV);
        cp_async16(sb + (uint32_t)(c_row0 * H_ROWH + c_off) * 2,
                   bp + (size_t)c_row0 * NQKV);
        cp_async16(sb + (uint32_t)(c_row1 * H_ROWH + c_off) * 2,
                   bp + (size_t)c_row1 * NQKV);
        cp_commit();
    };

    float acc[4][4][4];
    #pragma unroll
    for (int mi = 0; mi < 4; mi++)
        #pragma unroll
        for (int ni = 0; ni < 4; ni++)
            #pragma unroll
            for (int q = 0; q < 4; q++) acc[mi][ni][q] = 0.f;

    const int nk = HDd >> 5;   // 16
    issue(0, 0);
    issue(1, 1);
    issue(2, 2);

    for (int kt = 0; kt < nk; kt++) {
        const int cur = kt % H_STAGES;
        if (kt + 2 < nk)      cp_wait<2>();
        else if (kt + 1 < nk) cp_wait<1>();
        else                  cp_wait<0>();
        __syncthreads();
        if (kt + 3 < nk) issue(kt + 3, (kt + 3) % H_STAGES);

        const __half* Asc = (const __half*)(sm_ + cur * H_STAGE_BYTES);
        const __half* Bsc = Asc + 128 * H_ROWH;
        #pragma unroll
        for (int ks = 0; ks < 2; ks++) {
            const int kc = ks * 16 + 2 * t4;
            uint32_t af[4][4], bf[4][2];
            #pragma unroll
            for (int mi = 0; mi < 4; mi++) {
                const int r = mw + mi * 16 + g;
                af[mi][0] = *(const uint32_t*)(Asc + r * H_ROWH + kc);
                af[mi][1] = *(const uint32_t*)(Asc + (r + 8) * H_ROWH + kc);
                af[mi][2] = *(const uint32_t*)(Asc + r * H_ROWH + kc + 8);
                af[mi][3] = *(const uint32_t*)(Asc + (r + 8) * H_ROWH + kc + 8);
            }
            #pragma unroll
            for (int ni = 0; ni < 4; ni++) {
                const int nn = nw + ni * 8 + g;
                bf[ni][0] = *(const uint32_t*)(Bsc + nn * H_ROWH + kc);
                bf[ni][1] = *(const uint32_t*)(Bsc + nn * H_ROWH + kc + 8);
            }
            #pragma unroll
            for (int mi = 0; mi < 4; mi++)
                #pragma unroll
                for (int ni = 0; ni < 4; ni++)
                    mma_f16(acc[mi][ni], af[mi], bf[ni]);
        }
    }

    const float scale = 0.044194173824159216f;  // 1/sqrt(512)
    #pragma unroll
    for (int mi = 0; mi < 4; mi++) {
        const int r0 = m0 + mw + mi * 16 + g;
        #pragma unroll
        for (int ni = 0; ni < 4; ni++) {
            const int c0 = n0 + nw + ni * 8 + t4 * 2;
            float v0 = (c0     > r0)     ? -1e30f : acc[mi][ni][0] * scale;
            float v1 = (c0 + 1 > r0)     ? -1e30f : acc[mi][ni][1] * scale;
            float v2 = (c0     > r0 + 8) ? -1e30f : acc[mi][ni][2] * scale;
            float v3 = (c0 + 1 > r0 + 8) ? -1e30f : acc[mi][ni][3] * scale;
            *(float2*)&Cs[(size_t)r0 * Tt + c0]       = make_float2(v0, v1);
            *(float2*)&Cs[(size_t)(r0 + 8) * Tt + c0] = make_float2(v2, v3);
        }
    }
}

// ---------------------------------------------------------------------------
// Row softmax over T=512 (fp32 in) -> fp16 probs out.
// ---------------------------------------------------------------------------
__global__ void softmax_h(const float* __restrict__ S, __half* __restrict__ P) {
    int row = blockIdx.x;
    int t = threadIdx.x;
    const float4* p = (const float4*)(S + (size_t)row * Tt);
    float4 v = p[t];
    float m = fmaxf(fmaxf(v.x, v.y), fmaxf(v.z, v.w));
    #pragma unroll
    for (int o = 16; o; o >>= 1) m = fmaxf(m, __shfl_xor_sync(0xffffffffu, m, o));
    __shared__ float sm[4], ssum[4];
    int w = t >> 5;
    if ((t & 31) == 0) sm[w] = m;
    __syncthreads();
    m = fmaxf(fmaxf(sm[0], sm[1]), fmaxf(sm[2], sm[3]));
    v.x = expf(v.x - m); v.y = expf(v.y - m);
    v.z = expf(v.z - m); v.w = expf(v.w - m);
    float s = v.x + v.y + v.z + v.w;
    #pragma unroll
    for (int o = 16; o; o >>= 1) s += __shfl_xor_sync(0xffffffffu, s, o);
    if ((t & 31) == 0) ssum[w] = s;
    __syncthreads();
    s = ssum[0] + ssum[1] + ssum[2] + ssum[3];
    float inv = 1.f / s;
    __half2* ph = (__half2*)(P + (size_t)row * Tt);
    ph[2 * t]     = __floats2half2_rn(v.x * inv, v.y * inv);
    ph[2 * t + 1] = __floats2half2_rn(v.z * inv, v.w * inv);
}

// ---------------------------------------------------------------------------
// Host launcher
// ---------------------------------------------------------------------------
extern "C" void kernel_launch(void* const* d_in, const int* in_sizes, int n_in,
                              void* d_out, int out_size) {
    const float* x   = (const float*)d_in[0];
    const float* Wq  = (const float*)d_in[1];
    const float* Wk  = (const float*)d_in[2];
    const float* Wv  = (const float*)d_in[3];
    const float* Wo  = (const float*)d_in[4];
    const float* bo  = (const float*)d_in[5];
    const float* W1  = (const float*)d_in[6];
    const float* b1  = (const float*)d_in[7];
    const float* W2  = (const float*)d_in[8];
    const float* b2  = (const float*)d_in[9];
    const float* g1  = (const float*)d_in[10];
    const float* be1 = (const float*)d_in[11];
    const float* g2  = (const float*)d_in[12];
    const float* be2 = (const float*)d_in[13];
    float* out = (float*)d_out;

    __half *p_lnh, *p_wqkvh, *p_qkvh, *p_probs, *p_vt, *p_ctxh, *p_ffnh,
           *p_woth, *p_w1th, *p_w2th;
    float *p_sc;
    cudaGetSymbolAddress((void**)&p_lnh,   g_lnh);
    cudaGetSymbolAddress((void**)&p_wqkvh, g_wqkvh);
    cudaGetSymbolAddress((void**)&p_qkvh,  g_qkvh);
    cudaGetSymbolAddress((void**)&p_sc,    g_scores);
    cudaGetSymbolAddress((void**)&p_probs, g_probs);
    cudaGetSymbolAddress((void**)&p_vt,    g_vt);
    cudaGetSymbolAddress((void**)&p_ctxh,  g_ctxh);
    cudaGetSymbolAddress((void**)&p_ffnh,  g_ffnh);
    cudaGetSymbolAddress((void**)&p_woth,  g_woth);
    cudaGetSymbolAddress((void**)&p_w1th,  g_w1th);
    cudaGetSymbolAddress((void**)&p_w2th,  g_w2th);

    cudaFuncSetAttribute(hgemm, cudaFuncAttributeMaxDynamicSharedMemorySize,
                         H_SMEM_BYTES);
    cudaFuncSetAttribute(scores_h, cudaFuncAttributeMaxDynamicSharedMemorySize,
                         H_SMEM_BYTES);

    // 0) weight transposes -> fp16 K-major [N][K]
    transpose_h<<<dim3(Dd / 32, Dd / 32), dim3(32, 8)>>>(Wo, p_woth, Dd, Dd);
    transpose_h<<<dim3(DFF / 32, Dd / 32), dim3(32, 8)>>>(W1, p_w1th, Dd, DFF);
    transpose_h<<<dim3(Dd / 32, DFF / 32), dim3(32, 8)>>>(W2, p_w2th, DFF, Dd);
    repack_qkv_t_h<<<dim3(HDd / 32, Dd / 32, 12), dim3(32, 8)>>>(Wq, Wk, Wv, p_wqkvh);

    // 1) h = LN(x) -> fp16
    ln_kernel_h<<<BT, 256>>>(x, g1, be1, p_lnh);

    // 2) QKV = h @ Wqkv^T -> fp16 (q,k,v)
    hgemm<<<dim3(NQKV / 128, BT / 128), 256, H_SMEM_BYTES>>>(
        p_lnh, Dd, 0, 0, p_wqkvh, Dd, 0, 0,
        p_qkvh, NQKV, 0, 0, Dd, nullptr, nullptr, 0, 0, 1, 0);

    // 3) scores = scale * q k^T, causal (fp16 TC, fp32 out)
    scores_h<<<dim3(Tt / 128, Tt / 128, Bb * Hh), 256, H_SMEM_BYTES>>>(
        p_qkvh, p_sc);

    // 4) softmax -> fp16 probs
    softmax_h<<<Bb * Hh * Tt, 128>>>(p_sc, p_probs);

    // 5) v -> vt fp16 [b,h][c][s]
    vt_kernel<<<dim3(Tt / 32, HDd / 32, Bb * Hh), dim3(32, 8)>>>(p_qkvh, p_vt);

    // 6) ctx = probs @ vt^T -> fp16 head-concat (causal K-limit: exact)
    hgemm<<<dim3(HDd / 128, Tt / 128, Bb * Hh), 256, H_SMEM_BYTES>>>(
        p_probs, Tt, 4LL * Tt * Tt, (long long)Tt * Tt,
        p_vt, Tt, 4LL * HDd * Tt, (long long)HDd * Tt,
        p_ctxh, Dd, (long long)Tt * Dd, (long long)HDd,
        Tt, nullptr, nullptr, 0, 0, 1, 1);

    // 7) x2 = x + ctx @ Wo^T + bo -> d_out (fp32)
    hgemm<<<dim3(Dd / 128, BT / 128), 256, H_SMEM_BYTES>>>(
        p_ctxh, Dd, 0, 0, p_woth, Dd, 0, 0,
        out, Dd, 0, 0, Dd, bo, x, Dd, 0, 0, 0);

    // 8) h2 = LN(x2) -> fp16
    ln_kernel_h<<<BT, 256>>>(out, g2, be2, p_lnh);

    // 9) u = relu(h2 @ W1^T + b1) -> fp16
    hgemm<<<dim3(DFF / 128, BT / 128), 256, H_SMEM_BYTES>>>(
        p_lnh, Dd, 0, 0, p_w1th, Dd, 0, 0,
        p_ffnh, DFF, 0, 0, Dd, b1, nullptr, 0, 1, 1, 0);

    // 10) out = x2 + u @ W2^T + b2 (fp32, resid in place)
    hgemm<<<dim3(Dd / 128, BT / 128), 256, H_SMEM_BYTES>>>(
        p_ffnh, DFF, 0, 0, p_w2th, DFF, 0, 0,
        out, Dd, 0, 0, DFF, b2, out, Dd, 0, 0, 0);
}

// round 14
// speedup vs baseline: 2.0436x; 1.0384x over previous
#include <cuda_runtime.h>
#include <cuda_fp16.h>
#include <math.h>
#include <stdint.h>

// Problem constants
#define Bb   16
#define Tt   512
#define Dd   2048
#define Hh   4
#define HDd  512
#define BT   8192          // B*T rows
#define NQKV 6144          // 3*D
#define DFF  8192          // 4*D
#define LNEPS 1e-5f

// ---------------------------------------------------------------------------
// Scratch (static __device__ arrays; no allocation allowed)
// ---------------------------------------------------------------------------
__device__ __align__(128) __half g_lnh[(size_t)BT * Dd];          // LN out fp16
__device__ __align__(128) __half g_wqkvh[(size_t)NQKV * Dd];      // [6144][2048] K-major
__device__ __align__(128) __half g_qkvh[(size_t)BT * NQKV];       // fp16 q,k,v
__device__ __align__(128) float  g_scores[(size_t)Bb * Hh * Tt * Tt];
__device__ __align__(128) __half g_probs[(size_t)Bb * Hh * Tt * Tt];
__device__ __align__(128) __half g_ctxh[(size_t)BT * Dd];
__device__ __align__(128) __half g_ffnh[(size_t)BT * DFF];
__device__ __align__(128) __half g_woth[(size_t)Dd * Dd];         // [2048][2048] K-major
__device__ __align__(128) __half g_w1th[(size_t)DFF * Dd];        // [8192][2048] K-major
__device__ __align__(128) __half g_w2th[(size_t)Dd * DFF];        // [2048][8192] K-major

// ---------------------------------------------------------------------------
// PTX helpers
// ---------------------------------------------------------------------------
__device__ __forceinline__ uint32_t smem_u32(const void* p) {
    uint32_t a;
    asm("{ .reg .u64 t; cvta.to.shared.u64 t, %1; cvt.u32.u64 %0, t; }"
        : "=r"(a) : "l"(p));
    return a;
}
__device__ __forceinline__ void cp_async16(uint32_t smem_dst, const void* gmem_src) {
    asm volatile("cp.async.cg.shared.global [%0], [%1], 16;\n" :: "r"(smem_dst), "l"(gmem_src));
}
__device__ __forceinline__ void cp_commit() {
    asm volatile("cp.async.commit_group;\n");
}
template<int N>
__device__ __forceinline__ void cp_wait() {
    asm volatile("cp.async.wait_group %0;\n" :: "n"(N));
}
// fp16 tensor-core mma: D(f32) += A(f16,m16k16,row) * B(f16,n8k16,col)
__device__ __forceinline__ void mma_f16(float* c, const uint32_t* a, const uint32_t* b) {
    asm volatile(
        "mma.sync.aligned.m16n8k16.row.col.f32.f16.f16.f32 "
        "{%0,%1,%2,%3}, {%4,%5,%6,%7}, {%8,%9}, {%0,%1,%2,%3};"
        : "+f"(c[0]), "+f"(c[1]), "+f"(c[2]), "+f"(c[3])
        : "r"(a[0]), "r"(a[1]), "r"(a[2]), "r"(a[3]), "r"(b[0]), "r"(b[1]));
}
// ldmatrix x4: one full m16k16 fp16 A fragment.
__device__ __forceinline__ void ldsm_x4(uint32_t& r0, uint32_t& r1,
                                        uint32_t& r2, uint32_t& r3,
                                        uint32_t addr) {
    asm volatile(
        "ldmatrix.sync.aligned.m8n8.x4.shared.b16 {%0,%1,%2,%3}, [%4];"
        : "=r"(r0), "=r"(r1), "=r"(r2), "=r"(r3) : "r"(addr));
}
// ldmatrix x2 transposed: one n8k16 fp16 B fragment from [k][n] row-major smem.
__device__ __forceinline__ void ldsm_x2t(uint32_t& r0, uint32_t& r1, uint32_t addr) {
    asm volatile(
        "ldmatrix.sync.aligned.m8n8.x2.trans.shared.b16 {%0,%1}, [%2];"
        : "=r"(r0), "=r"(r1) : "r"(addr));
}

// ---------------------------------------------------------------------------
// Weight transpose + fp16 convert:  out[N][K] = half(in[K][N])
// ---------------------------------------------------------------------------
__global__ void transpose_h(const float* __restrict__ in,
                            __half* __restrict__ out, int K, int N) {
    __shared__ float t[32][33];
    int n0 = blockIdx.x * 32, k0 = blockIdx.y * 32;
    int lx = threadIdx.x, ly = threadIdx.y;
    #pragma unroll
    for (int i = 0; i < 32; i += 8)
        t[ly + i][lx] = in[(size_t)(k0 + ly + i) * N + n0 + lx];
    __syncthreads();
    #pragma unroll
    for (int i = 0; i < 32; i += 8)
        out[(size_t)(n0 + ly + i) * K + k0 + lx] = __float2half_rn(t[lx][ly + i]);
}

// Repack+transpose Wq/Wk/Wv [H,D,HD] -> half [3D][D] K-major.
__global__ void repack_qkv_t_h(const float* __restrict__ Wq,
                               const float* __restrict__ Wk,
                               const float* __restrict__ Wv,
                               __half* __restrict__ out) {
    __shared__ float t[32][33];
    int z = blockIdx.z;
    int sel = z >> 2, h = z & 3;
    const float* W = (sel == 0 ? Wq : sel == 1 ? Wk : Wv) + (size_t)h * Dd * HDd;
    int c0 = blockIdx.x * 32, k0 = blockIdx.y * 32;
    int lx = threadIdx.x, ly = threadIdx.y;
    #pragma unroll
    for (int i = 0; i < 32; i += 8)
        t[ly + i][lx] = W[(size_t)(k0 + ly + i) * HDd + c0 + lx];
    __syncthreads();
    int nbase = sel * 2048 + h * 512 + c0;
    #pragma unroll
    for (int i = 0; i < 32; i += 8)
        out[(size_t)(nbase + ly + i) * Dd + k0 + lx] = __float2half_rn(t[lx][ly + i]);
}

// ---------------------------------------------------------------------------
// LayerNorm: one block per row (D=2048), 256 threads. fp16 output.
// ---------------------------------------------------------------------------
__global__ void ln_kernel_h(const float* __restrict__ x,
                            const float* __restrict__ g,
                            const float* __restrict__ b,
                            __half* __restrict__ out) {
    int row = blockIdx.x;
    int t   = threadIdx.x;
    const float4* xr = (const float4*)(x + (size_t)row * Dd);
    float4 v0 = xr[t];
    float4 v1 = xr[t + 256];
    float s  = v0.x + v0.y + v0.z + v0.w + v1.x + v1.y + v1.z + v1.w;
    float sq = v0.x*v0.x + v0.y*v0.y + v0.z*v0.z + v0.w*v0.w
             + v1.x*v1.x + v1.y*v1.y + v1.z*v1.z + v1.w*v1.w;
    #pragma unroll
    for (int o = 16; o; o >>= 1) {
        s  += __shfl_xor_sync(0xffffffffu, s,  o);
        sq += __shfl_xor_sync(0xffffffffu, sq, o);
    }
    __shared__ float ss[8], ssq[8];
    int w = t >> 5;
    if ((t & 31) == 0) { ss[w] = s; ssq[w] = sq; }
    __syncthreads();
    float S = 0.f, SQ = 0.f;
    #pragma unroll
    for (int i = 0; i < 8; i++) { S += ss[i]; SQ += ssq[i]; }
    float mean = S * (1.f / Dd);
    float var  = SQ * (1.f / Dd) - mean * mean;
    float rstd = rsqrtf(var + LNEPS);

    const float4* gr = (const float4*)g;
    const float4* br = (const float4*)b;
    __half2* o2 = (__half2*)(out + (size_t)row * Dd);
    float4 gv = gr[t], bv = br[t];
    o2[2 * t]     = __floats2half2_rn((v0.x - mean) * rstd * gv.x + bv.x,
                                      (v0.y - mean) * rstd * gv.y + bv.y);
    o2[2 * t + 1] = __floats2half2_rn((v0.z - mean) * rstd * gv.z + bv.z,
                                      (v0.w - mean) * rstd * gv.w + bv.w);
    gv = gr[t + 256]; bv = br[t + 256];
    o2[2 * (t + 256)]     = __floats2half2_rn((v1.x - mean) * rstd * gv.x + bv.x,
                                              (v1.y - mean) * rstd * gv.y + bv.y);
    o2[2 * (t + 256) + 1] = __floats2half2_rn((v1.z - mean) * rstd * gv.z + bv.z,
                                              (v1.w - mean) * rstd * gv.w + bv.w);
}

// ---------------------------------------------------------------------------
// fp16 tensor-core GEMM: C[M,N] = A[M,K] @ Bt[N,K]^T (+bias)(+resid)(relu)
// A half [M][K] row-major (lda), Bt half [N][K] K-major (ldb).
// CTA 128x128x32, 256 threads = 8 warps (2m x 4n), warp tile 64x32,
// mma.sync.m16n8k16. A-frags via ldmatrix.x4. 4-stage cp.async, 2 CTAs/SM.
// out_half: 1 = write fp16 C, 0 = write fp32 C.
// ---------------------------------------------------------------------------
#define H_STAGES 4
#define H_ROWH 40                       // halves per smem row (32 + 8 pad)
#define H_TILE_BYTES (128 * H_ROWH * 2) // 10240 per operand
#define H_STAGE_BYTES (2 * H_TILE_BYTES)
#define H_SMEM_BYTES (H_STAGES * H_STAGE_BYTES)  // 81920

__global__ void __launch_bounds__(256, 2)
hgemm(const __half* __restrict__ A, int lda,
      const __half* __restrict__ B, int ldb,
      void* __restrict__ Cvoid, int ldc,
      int K,
      const float* __restrict__ bias,
      const float* __restrict__ resid, int ldr,
      int relu, int out_half) {
    extern __shared__ __align__(16) char sm_[];
    const uint32_t smem_u = smem_u32(sm_);

    const int m0 = blockIdx.y * 128;
    const int n0 = blockIdx.x * 128;
    const int tid  = threadIdx.x;
    const int lane = tid & 31;
    const int wid  = tid >> 5;
    const int g  = lane >> 2;        // groupID
    const int t4 = lane & 3;         // thread-in-group
    const int mw = (wid >> 2) * 64;  // warp m offset
    const int nw = (wid & 3) * 32;   // warp n offset

    const int c_row0 = tid >> 2;          // 0..63
    const int c_row1 = c_row0 + 64;
    const int c_off  = (tid & 3) * 8;     // halves offset (16B chunks)

    auto issue = [&](int kt, int s) {
        const uint32_t sa = smem_u + s * H_STAGE_BYTES;
        const uint32_t sb = sa + H_TILE_BYTES;
        const __half* ap = A + (size_t)(m0) * lda + kt * 32 + c_off;
        const __half* bp = B + (size_t)(n0) * ldb + kt * 32 + c_off;
        cp_async16(sa + (uint32_t)(c_row0 * H_ROWH + c_off) * 2,
                   ap + (size_t)c_row0 * lda);
        cp_async16(sa + (uint32_t)(c_row1 * H_ROWH + c_off) * 2,
                   ap + (size_t)c_row1 * lda);
        cp_async16(sb + (uint32_t)(c_row0 * H_ROWH + c_off) * 2,
                   bp + (size_t)c_row0 * ldb);
        cp_async16(sb + (uint32_t)(c_row1 * H_ROWH + c_off) * 2,
                   bp + (size_t)c_row1 * ldb);
        cp_commit();
    };

    // ldmatrix per-lane offsets for A frags (halves)
    const int lrow = lane & 15;
    const int lcol = (lane >> 4) * 8;
    const uint32_t a_lane_off = (uint32_t)((mw + lrow) * H_ROWH + lcol);

    float acc[4][4][4];
    #pragma unroll
    for (int mi = 0; mi < 4; mi++)
        #pragma unroll
        for (int ni = 0; ni < 4; ni++)
            #pragma unroll
            for (int q = 0; q < 4; q++) acc[mi][ni][q] = 0.f;

    const int nk = K >> 5;   // K-chunks of 32
    issue(0, 0);
    issue(1, 1);
    issue(2, 2);

    for (int kt = 0; kt < nk; kt++) {
        const int cur = kt % H_STAGES;
        if (kt + 2 < nk)      cp_wait<2>();
        else if (kt + 1 < nk) cp_wait<1>();
        else                  cp_wait<0>();
        __syncthreads();
        if (kt + 3 < nk) issue(kt + 3, (kt + 3) % H_STAGES);

        const uint32_t sa_u = smem_u + cur * H_STAGE_BYTES;
        const __half* Bsc = (const __half*)(sm_ + cur * H_STAGE_BYTES) + 128 * H_ROWH;
        #pragma unroll
        for (int ks = 0; ks < 2; ks++) {
            const int kc = ks * 16 + 2 * t4;
            uint32_t af[4][4], bf[4][2];
            #pragma unroll
            for (int mi = 0; mi < 4; mi++)
                ldsm_x4(af[mi][0], af[mi][1], af[mi][2], af[mi][3],
                        sa_u + 2u * (a_lane_off + mi * 16 * H_ROWH + ks * 16));
            #pragma unroll
            for (int ni = 0; ni < 4; ni++) {
                const int nn = nw + ni * 8 + g;
                bf[ni][0] = *(const uint32_t*)(Bsc + nn * H_ROWH + kc);
                bf[ni][1] = *(const uint32_t*)(Bsc + nn * H_ROWH + kc + 8);
            }
            #pragma unroll
            for (int mi = 0; mi < 4; mi++)
                #pragma unroll
                for (int ni = 0; ni < 4; ni++)
                    mma_f16(acc[mi][ni], af[mi], bf[ni]);
        }
    }

    // Epilogue
    float* Cf = (float*)Cvoid;
    __half* Ch = (__half*)Cvoid;
    #pragma unroll
    for (int mi = 0; mi < 4; mi++) {
        const int r0 = m0 + mw + mi * 16 + g;
        #pragma unroll
        for (int ni = 0; ni < 4; ni++) {
            const int c0 = n0 + nw + ni * 8 + t4 * 2;
            float bb0 = 0.f, bb1 = 0.f;
            if (bias) { bb0 = bias[c0]; bb1 = bias[c0 + 1]; }
            float v0 = acc[mi][ni][0] + bb0;
            float v1 = acc[mi][ni][1] + bb1;
            float v2 = acc[mi][ni][2] + bb0;
            float v3 = acc[mi][ni][3] + bb1;
            if (resid) {
                const float* R0 = resid + (size_t)r0 * ldr + c0;
                const float* R1 = resid + (size_t)(r0 + 8) * ldr + c0;
                v0 += R0[0]; v1 += R0[1];
                v2 += R1[0]; v3 += R1[1];
            }
            if (relu) {
                v0 = fmaxf(v0, 0.f); v1 = fmaxf(v1, 0.f);
                v2 = fmaxf(v2, 0.f); v3 = fmaxf(v3, 0.f);
            }
            if (out_half) {
                *(__half2*)&Ch[(size_t)r0 * ldc + c0]       = __floats2half2_rn(v0, v1);
                *(__half2*)&Ch[(size_t)(r0 + 8) * ldc + c0] = __floats2half2_rn(v2, v3);
            } else {
                *(float2*)&Cf[(size_t)r0 * ldc + c0]       = make_float2(v0, v1);
                *(float2*)&Cf[(size_t)(r0 + 8) * ldc + c0] = make_float2(v2, v3);
            }
        }
    }
}

// ---------------------------------------------------------------------------
// Scores on tensor cores: S = scale * q k^T (fp16 in, fp32 out), causal.
// Above-diagonal tiles: NO work, NO writes (softmax never reads there).
// ---------------------------------------------------------------------------
__global__ void __launch_bounds__(256, 2)
scores_h(const __half* __restrict__ QKVh, float* __restrict__ S) {
    const int m0 = blockIdx.y * 128;
    const int n0 = blockIdx.x * 128;
    if (n0 > m0) return;   // skipped entirely

    extern __shared__ __align__(16) char sm_[];
    const uint32_t smem_u = smem_u32(sm_);

    const int z = blockIdx.z;
    const int bb = z >> 2, hh = z & 3;
    const __half* A = QKVh + (size_t)(bb * Tt) * NQKV + hh * HDd;   // q
    const __half* B = A + Dd;                                       // k
    float* Cs = S + (size_t)z * Tt * Tt;

    const int tid  = threadIdx.x;
    const int lane = tid & 31;
    const int wid  = tid >> 5;
    const int g  = lane >> 2;
    const int t4 = lane & 3;
    const int mw = (wid >> 2) * 64;
    const int nw = (wid & 3) * 32;

    const int c_row0 = tid >> 2;
    const int c_row1 = c_row0 + 64;
    const int c_off  = (tid & 3) * 8;

    auto issue = [&](int kt, int s) {
        const uint32_t sa = smem_u + s * H_STAGE_BYTES;
        const uint32_t sb = sa + H_TILE_BYTES;
        const __half* ap = A + (size_t)(m0) * NQKV + kt * 32 + c_off;
        const __half* bp = B + (size_t)(n0) * NQKV + kt * 32 + c_off;
        cp_async16(sa + (uint32_t)(c_row0 * H_ROWH + c_off) * 2,
                   ap + (size_t)c_row0 * NQKV);
        cp_async16(sa + (uint32_t)(c_row1 * H_ROWH + c_off) * 2,
                   ap + (size_t)c_row1 * NQKV);
        cp_async16(sb + (uint32_t)(c_row0 * H_ROWH + c_off) * 2,
                   bp + (size_t)c_row0 * NQKV);
        cp_async16(sb + (uint32_t)(c_row1 * H_ROWH + c_off) * 2,
                   bp + (size_t)c_row1 * NQKV);
        cp_commit();
    };

    const int lrow = lane & 15;
    const int lcol = (lane >> 4) * 8;
    const uint32_t a_lane_off = (uint32_t)((mw + lrow) * H_ROWH + lcol);

    float acc[4][4][4];
    #pragma unroll
    for (int mi = 0; mi < 4; mi++)
        #pragma unroll
        for (int ni = 0; ni < 4; ni++)
            #pragma unroll
            for (int q = 0; q < 4; q++) acc[mi][ni][q] = 0.f;

    const int nk = HDd >> 5;   // 16
    issue(0, 0);
    issue(1, 1);
    issue(2, 2);

    for (int kt = 0; kt < nk; kt++) {
        const int cur = kt % H_STAGES;
        if (kt + 2 < nk)      cp_wait<2>();
        else if (kt + 1 < nk) cp_wait<1>();
        else                  cp_wait<0>();
        __syncthreads();
        if (kt + 3 < nk) issue(kt + 3, (kt + 3) % H_STAGES);

        const uint32_t sa_u = smem_u + cur * H_STAGE_BYTES;
        const __half* Bsc = (const __half*)(sm_ + cur * H_STAGE_BYTES) + 128 * H_ROWH;
        #pragma unroll
        for (int ks = 0; ks < 2; ks++) {
            const int kc = ks * 16 + 2 * t4;
            uint32_t af[4][4], bf[4][2];
            #pragma unroll
            for (int mi = 0; mi < 4; mi++)
                ldsm_x4(af[mi][0], af[mi][1], af[mi][2], af[mi][3],
                        sa_u + 2u * (a_lane_off + mi * 16 * H_ROWH + ks * 16));
            #pragma unroll
            for (int ni = 0; ni < 4; ni++) {
                const int nn = nw + ni * 8 + g;
                bf[ni][0] = *(const uint32_t*)(Bsc + nn * H_ROWH + kc);
                bf[ni][1] = *(const uint32_t*)(Bsc + nn * H_ROWH + kc + 8);
            }
            #pragma unroll
            for (int mi = 0; mi < 4; mi++)
                #pragma unroll
                for (int ni = 0; ni < 4; ni++)
                    mma_f16(acc[mi][ni], af[mi], bf[ni]);
        }
    }

    const float scale = 0.044194173824159216f;  // 1/sqrt(512)
    #pragma unroll
    for (int mi = 0; mi < 4; mi++) {
        const int r0 = m0 + mw + mi * 16 + g;
        #pragma unroll
        for (int ni = 0; ni < 4; ni++) {
            const int c0 = n0 + nw + ni * 8 + t4 * 2;
            float v0 = (c0     > r0)     ? -1e30f : acc[mi][ni][0] * scale;
            float v1 = (c0 + 1 > r0)     ? -1e30f : acc[mi][ni][1] * scale;
            float v2 = (c0     > r0 + 8) ? -1e30f : acc[mi][ni][2] * scale;
            float v3 = (c0 + 1 > r0 + 8) ? -1e30f : acc[mi][ni][3] * scale;
            *(float2*)&Cs[(size_t)r0 * Tt + c0]       = make_float2(v0, v1);
            *(float2*)&Cs[(size_t)(r0 + 8) * Tt + c0] = make_float2(v2, v3);
        }
    }
}

// ---------------------------------------------------------------------------
// ctx GEMM: C = probs @ V. A = probs fp16 [Tt][Tt] (per b,h). B = v read
// DIRECTLY from packed fp16 QKV in [k=s][n=c] layout (ldb = NQKV); B-frags
// via ldmatrix.x2.trans. Causal K-limit (exact: probs cols >= m0+128 are 0).
// ---------------------------------------------------------------------------
#define CB_ROWH 136                       // halves per B smem row (128 + 8)
#define CB_TILE_BYTES (32 * CB_ROWH * 2)  // 8704
#define C_STAGE_BYTES (H_TILE_BYTES + CB_TILE_BYTES)   // 18944
#define C_SMEM_BYTES (H_STAGES * C_STAGE_BYTES)        // 75776

__global__ void __launch_bounds__(256, 2)
ctx_hgemm(const __half* __restrict__ P,      // probs
          const __half* __restrict__ QKVh,
          __half* __restrict__ C) {          // ctx head-concat [BT][Dd]
    extern __shared__ __align__(16) char sm_[];
    const uint32_t smem_u = smem_u32(sm_);

    const int z = blockIdx.z;
    const int bb = z >> 2, hh = z & 3;
    const __half* A = P + (size_t)z * Tt * Tt;
    const __half* B = QKVh + (size_t)(bb * Tt) * NQKV + 4096 + hh * HDd; // v [s][c]
    __half* Cc = C + (size_t)(bb * Tt) * Dd + hh * HDd;

    const int m0 = blockIdx.y * 128;
    const int n0 = blockIdx.x * 128;
    const int tid  = threadIdx.x;
    const int lane = tid & 31;
    const int wid  = tid >> 5;
    const int g  = lane >> 2;
    const int t4 = lane & 3;
    const int mw = (wid >> 2) * 64;
    const int nw = (wid & 3) * 32;

    const int K = m0 + 128;         // causal: probs cols >= m0+128 are exactly 0

    // A fill (same as hgemm)
    const int c_row0 = tid >> 2;
    const int c_row1 = c_row0 + 64;
    const int c_off  = (tid & 3) * 8;
    // B fill: 32 k-rows x 128 n-halves; thread t: rows t>>4 and (t>>4)+16
    const int b_row0 = tid >> 4;          // 0..15
    const int b_row1 = b_row0 + 16;
    const int b_c8   = (tid & 15) * 8;    // halves

    auto issue = [&](int kt, int s) {
        const uint32_t sa = smem_u + s * C_STAGE_BYTES;
        const uint32_t sb = sa + H_TILE_BYTES;
        const __half* ap = A + (size_t)(m0) * Tt + kt * 32 + c_off;
        cp_async16(sa + (uint32_t)(c_row0 * H_ROWH + c_off) * 2,
                   ap + (size_t)c_row0 * Tt);
        cp_async16(sa + (uint32_t)(c_row1 * H_ROWH + c_off) * 2,
                   ap + (size_t)c_row1 * Tt);
        const __half* bp = B + (size_t)(kt * 32) * NQKV + n0 + b_c8;
        cp_async16(sb + (uint32_t)(b_row0 * CB_ROWH + b_c8) * 2,
                   bp + (size_t)b_row0 * NQKV);
        cp_async16(sb + (uint32_t)(b_row1 * CB_ROWH + b_c8) * 2,
                   bp + (size_t)b_row1 * NQKV);
        cp_commit();
    };

    const int lrow = lane & 15;
    const int lcol = (lane >> 4) * 8;
    const uint32_t a_lane_off = (uint32_t)((mw + lrow) * H_ROWH + lcol);
    const uint32_t b_lane_row = (uint32_t)(lane & 15);   // rows for ldsm.x2.trans

    float acc[4][4][4];
    #pragma unroll
    for (int mi = 0; mi < 4; mi++)
        #pragma unroll
        for (int ni = 0; ni < 4; ni++)
            #pragma unroll
            for (int q = 0; q < 4; q++) acc[mi][ni][q] = 0.f;

    const int nk = K >> 5;   // 4..16
    issue(0, 0);
    issue(1, 1);
    issue(2, 2);

    for (int kt = 0; kt < nk; kt++) {
        const int cur = kt % H_STAGES;
        if (kt + 2 < nk)      cp_wait<2>();
        else if (kt + 1 < nk) cp_wait<1>();
        else                  cp_wait<0>();
        __syncthreads();
        if (kt + 3 < nk) issue(kt + 3, (kt + 3) % H_STAGES);

        const uint32_t sa_u = smem_u + cur * C_STAGE_BYTES;
        const uint32_t sb_u = sa_u + H_TILE_BYTES;
        #pragma unroll
        for (int ks = 0; ks < 2; ks++) {
            uint32_t af[4][4], bf[4][2];
            #pragma unroll
            for (int mi = 0; mi < 4; mi++)
                ldsm_x4(af[mi][0], af[mi][1], af[mi][2], af[mi][3],
                        sa_u + 2u * (a_lane_off + mi * 16 * H_ROWH + ks * 16));
            #pragma unroll
            for (int ni = 0; ni < 4; ni++)
                ldsm_x2t(bf[ni][0], bf[ni][1],
                         sb_u + 2u * ((ks * 16 + b_lane_row) * CB_ROWH
                                      + nw + ni * 8));
            #pragma unroll
            for (int mi = 0; mi < 4; mi++)
                #pragma unroll
                for (int ni = 0; ni < 4; ni++)
                    mma_f16(acc[mi][ni], af[mi], bf[ni]);
        }
    }

    #pragma unroll
    for (int mi = 0; mi < 4; mi++) {
        const int r0 = m0 + mw + mi * 16 + g;
        #pragma unroll
        for (int ni = 0; ni < 4; ni++) {
            const int c0 = n0 + nw + ni * 8 + t4 * 2;
            *(__half2*)&Cc[(size_t)r0 * Dd + c0] =
                __floats2half2_rn(acc[mi][ni][0], acc[mi][ni][1]);
            *(__half2*)&Cc[(size_t)(r0 + 8) * Dd + c0] =
                __floats2half2_rn(acc[mi][ni][2], acc[mi][ni][3]);
        }
    }
}

// ---------------------------------------------------------------------------
// Row softmax (fp32 in) -> fp16 probs. Causal: cols > i are never read
// (skipped score tiles hold garbage); probs there are written as exact 0.
// ---------------------------------------------------------------------------
__global__ void softmax_h(const float* __restrict__ S, __half* __restrict__ P) {
    int row = blockIdx.x;
    int i = row & (Tt - 1);        // position within sequence
    int t = threadIdx.x;
    const float4* p = (const float4*)(S + (size_t)row * Tt);
    float4 v;
    if (4 * t <= i) {
        v = p[t];   // elements with gj>i inside this float4 are -1e30 (masked
                    // by the diagonal score tile), never from a skipped tile
    } else {
        v = make_float4(-1e30f, -1e30f, -1e30f, -1e30f);
    }
    float m = fmaxf(fmaxf(v.x, v.y), fmaxf(v.z, v.w));
    #pragma unroll
    for (int o = 16; o; o >>= 1) m = fmaxf(m, __shfl_xor_sync(0xffffffffu, m, o));
    __shared__ float sm[4], ssum[4];
    int w = t >> 5;
    if ((t & 31) == 0) sm[w] = m;
    __syncthreads();
    m = fmaxf(fmaxf(sm[0], sm[1]), fmaxf(sm[2], sm[3]));
    v.x = expf(v.x - m); v.y = expf(v.y - m);
    v.z = expf(v.z - m); v.w = expf(v.w - m);
    float s = v.x + v.y + v.z + v.w;
    #pragma unroll
    for (int o = 16; o; o >>= 1) s += __shfl_xor_sync(0xffffffffu, s, o);
    if ((t & 31) == 0) ssum[w] = s;
    __syncthreads();
    s = ssum[0] + ssum[1] + ssum[2] + ssum[3];
    float inv = 1.f / s;
    __half2* ph = (__half2*)(P + (size_t)row * Tt);
    ph[2 * t]     = __floats2half2_rn(v.x * inv, v.y * inv);
    ph[2 * t + 1] = __floats2half2_rn(v.z * inv, v.w * inv);
}

// ---------------------------------------------------------------------------
// Host launcher
// ---------------------------------------------------------------------------
extern "C" void kernel_launch(void* const* d_in, const int* in_sizes, int n_in,
                              void* d_out, int out_size) {
    const float* x   = (const float*)d_in[0];
    const float* Wq  = (const float*)d_in[1];
    const float* Wk  = (const float*)d_in[2];
    const float* Wv  = (const float*)d_in[3];
    const float* Wo  = (const float*)d_in[4];
    const float* bo  = (const float*)d_in[5];
    const float* W1  = (const float*)d_in[6];
    const float* b1  = (const float*)d_in[7];
    const float* W2  = (const float*)d_in[8];
    const float* b2  = (const float*)d_in[9];
    const float* g1  = (const float*)d_in[10];
    const float* be1 = (const float*)d_in[11];
    const float* g2  = (const float*)d_in[12];
    const float* be2 = (const float*)d_in[13];
    float* out = (float*)d_out;

    __half *p_lnh, *p_wqkvh, *p_qkvh, *p_probs, *p_ctxh, *p_ffnh,
           *p_woth, *p_w1th, *p_w2th;
    float *p_sc;
    cudaGetSymbolAddress((void**)&p_lnh,   g_lnh);
    cudaGetSymbolAddress((void**)&p_wqkvh, g_wqkvh);
    cudaGetSymbolAddress((void**)&p_qkvh,  g_qkvh);
    cudaGetSymbolAddress((void**)&p_sc,    g_scores);
    cudaGetSymbolAddress((void**)&p_probs, g_probs);
    cudaGetSymbolAddress((void**)&p_ctxh,  g_ctxh);
    cudaGetSymbolAddress((void**)&p_ffnh,  g_ffnh);
    cudaGetSymbolAddress((void**)&p_woth,  g_woth);
    cudaGetSymbolAddress((void**)&p_w1th,  g_w1th);
    cudaGetSymbolAddress((void**)&p_w2th,  g_w2th);

    cudaFuncSetAttribute(hgemm, cudaFuncAttributeMaxDynamicSharedMemorySize,
                         H_SMEM_BYTES);
    cudaFuncSetAttribute(scores_h, cudaFuncAttributeMaxDynamicSharedMemorySize,
                         H_SMEM_BYTES);
    cudaFuncSetAttribute(ctx_hgemm, cudaFuncAttributeMaxDynamicSharedMemorySize,
                         C_SMEM_BYTES);

    // 0) weight transposes -> fp16 K-major [N][K]
    transpose_h<<<dim3(Dd / 32, Dd / 32), dim3(32, 8)>>>(Wo, p_woth, Dd, Dd);
    transpose_h<<<dim3(DFF / 32, Dd / 32), dim3(32, 8)>>>(W1, p_w1th, Dd, DFF);
    transpose_h<<<dim3(Dd / 32, DFF / 32), dim3(32, 8)>>>(W2, p_w2th, DFF, Dd);
    repack_qkv_t_h<<<dim3(HDd / 32, Dd / 32, 12), dim3(32, 8)>>>(Wq, Wk, Wv, p_wqkvh);

    // 1) h = LN(x) -> fp16
    ln_kernel_h<<<BT, 256>>>(x, g1, be1, p_lnh);

    // 2) QKV = h @ Wqkv^T -> fp16
    hgemm<<<dim3(NQKV / 128, BT / 128), 256, H_SMEM_BYTES>>>(
        p_lnh, Dd, p_wqkvh, Dd,
        p_qkvh, NQKV, Dd, nullptr, nullptr, 0, 0, 1);

    // 3) scores = scale * q k^T, causal (skipped tiles not written)
    scores_h<<<dim3(Tt / 128, Tt / 128, Bb * Hh), 256, H_SMEM_BYTES>>>(
        p_qkvh, p_sc);

    // 4) softmax -> fp16 probs (causal reads)
    softmax_h<<<Bb * Hh * Tt, 128>>>(p_sc, p_probs);

    // 5) ctx = probs @ v (v read from packed QKV via trans-ldmatrix)
    ctx_hgemm<<<dim3(HDd / 128, Tt / 128, Bb * Hh), 256, C_SMEM_BYTES>>>(
        p_probs, p_qkvh, p_ctxh);

    // 6) x2 = x + ctx @ Wo^T + bo -> d_out (fp32)
    hgemm<<<dim3(Dd / 128, BT / 128), 256, H_SMEM_BYTES>>>(
        p_ctxh, Dd, p_woth, Dd,
        out, Dd, Dd, bo, x, Dd, 0, 0);

    // 7) h2 = LN(x2) -> fp16
    ln_kernel_h<<<BT, 256>>>(out, g2, be2, p_lnh);

    // 8) u = relu(h2 @ W1^T + b1) -> fp16
    hgemm<<<dim3(DFF / 128, BT / 128), 256, H_SMEM_BYTES>>>(
        p_lnh, Dd, p_w1th, Dd,
        p_ffnh, DFF, Dd, b1, nullptr, 0, 1, 1);

    // 9) out = x2 + u @ W2^T + b2 (fp32, resid in place)
    hgemm<<<dim3(Dd / 128, BT / 128), 256, H_SMEM_BYTES>>>(
        p_ffnh, DFF, p_w2th, DFF,
        out, Dd, DFF, b2, out, Dd, 0, 0);
}

// round 15
// speedup vs baseline: 2.1402x; 1.0473x over previous
#include <cuda_runtime.h>
#include <cuda_fp16.h>
#include <math.h>
#include <stdint.h>

// Problem constants
#define Bb   16
#define Tt   512
#define Dd   2048
#define Hh   4
#define HDd  512
#define BT   8192          // B*T rows
#define NQKV 6144          // 3*D
#define DFF  8192          // 4*D
#define LNEPS 1e-5f

// ---------------------------------------------------------------------------
// Scratch (static __device__ arrays; no allocation allowed)
// ---------------------------------------------------------------------------
__device__ __align__(128) __half g_lnh[(size_t)BT * Dd];          // LN out fp16
__device__ __align__(128) __half g_wqkvh[(size_t)NQKV * Dd];      // [6144][2048] K-major
__device__ __align__(128) __half g_qkvh[(size_t)BT * NQKV];       // fp16 q,k,v
__device__ __align__(128) float  g_scores[(size_t)Bb * Hh * Tt * Tt];
__device__ __align__(128) __half g_probs[(size_t)Bb * Hh * Tt * Tt];
__device__ __align__(128) __half g_ctxh[(size_t)BT * Dd];
__device__ __align__(128) __half g_ffnh[(size_t)BT * DFF];
__device__ __align__(128) __half g_woth[(size_t)Dd * Dd];         // [2048][2048] K-major
__device__ __align__(128) __half g_w1th[(size_t)DFF * Dd];        // [8192][2048] K-major
__device__ __align__(128) __half g_w2th[(size_t)Dd * DFF];        // [2048][8192] K-major

// ---------------------------------------------------------------------------
// PTX helpers
// ---------------------------------------------------------------------------
__device__ __forceinline__ uint32_t smem_u32(const void* p) {
    uint32_t a;
    asm("{ .reg .u64 t; cvta.to.shared.u64 t, %1; cvt.u32.u64 %0, t; }"
        : "=r"(a) : "l"(p));
    return a;
}
__device__ __forceinline__ void cp_async16(uint32_t smem_dst, const void* gmem_src) {
    asm volatile("cp.async.cg.shared.global [%0], [%1], 16;\n" :: "r"(smem_dst), "l"(gmem_src));
}
__device__ __forceinline__ void cp_commit() {
    asm volatile("cp.async.commit_group;\n");
}
template<int N>
__device__ __forceinline__ void cp_wait() {
    asm volatile("cp.async.wait_group %0;\n" :: "n"(N));
}
// fp16 tensor-core mma: D(f32) += A(f16,m16k16,row) * B(f16,n8k16,col)
__device__ __forceinline__ void mma_f16(float* c, const uint32_t* a, const uint32_t* b) {
    asm volatile(
        "mma.sync.aligned.m16n8k16.row.col.f32.f16.f16.f32 "
        "{%0,%1,%2,%3}, {%4,%5,%6,%7}, {%8,%9}, {%0,%1,%2,%3};"
        : "+f"(c[0]), "+f"(c[1]), "+f"(c[2]), "+f"(c[3])
        : "r"(a[0]), "r"(a[1]), "r"(a[2]), "r"(a[3]), "r"(b[0]), "r"(b[1]));
}
// ldmatrix x4: one full m16k16 fp16 A fragment.
__device__ __forceinline__ void ldsm_x4(uint32_t& r0, uint32_t& r1,
                                        uint32_t& r2, uint32_t& r3,
                                        uint32_t addr) {
    asm volatile(
        "ldmatrix.sync.aligned.m8n8.x4.shared.b16 {%0,%1,%2,%3}, [%4];"
        : "=r"(r0), "=r"(r1), "=r"(r2), "=r"(r3) : "r"(addr));
}
// ldmatrix x2 (non-trans): one n8k16 fp16 B fragment from K-major [n][k] smem.
__device__ __forceinline__ void ldsm_x2(uint32_t& r0, uint32_t& r1, uint32_t addr) {
    asm volatile(
        "ldmatrix.sync.aligned.m8n8.x2.shared.b16 {%0,%1}, [%2];"
        : "=r"(r0), "=r"(r1) : "r"(addr));
}
// ldmatrix x2 transposed: one n8k16 fp16 B fragment from [k][n] row-major smem.
__device__ __forceinline__ void ldsm_x2t(uint32_t& r0, uint32_t& r1, uint32_t addr) {
    asm volatile(
        "ldmatrix.sync.aligned.m8n8.x2.trans.shared.b16 {%0,%1}, [%2];"
        : "=r"(r0), "=r"(r1) : "r"(addr));
}

// ---------------------------------------------------------------------------
// Weight transpose + fp16 convert:  out[N][K] = half(in[K][N])
// ---------------------------------------------------------------------------
__global__ void transpose_h(const float* __restrict__ in,
                            __half* __restrict__ out, int K, int N) {
    __shared__ float t[32][33];
    int n0 = blockIdx.x * 32, k0 = blockIdx.y * 32;
    int lx = threadIdx.x, ly = threadIdx.y;
    #pragma unroll
    for (int i = 0; i < 32; i += 8)
        t[ly + i][lx] = in[(size_t)(k0 + ly + i) * N + n0 + lx];
    __syncthreads();
    #pragma unroll
    for (int i = 0; i < 32; i += 8)
        out[(size_t)(n0 + ly + i) * K + k0 + lx] = __float2half_rn(t[lx][ly + i]);
}

// Repack+transpose Wq/Wk/Wv [H,D,HD] -> half [3D][D] K-major.
__global__ void repack_qkv_t_h(const float* __restrict__ Wq,
                               const float* __restrict__ Wk,
                               const float* __restrict__ Wv,
                               __half* __restrict__ out) {
    __shared__ float t[32][33];
    int z = blockIdx.z;
    int sel = z >> 2, h = z & 3;
    const float* W = (sel == 0 ? Wq : sel == 1 ? Wk : Wv) + (size_t)h * Dd * HDd;
    int c0 = blockIdx.x * 32, k0 = blockIdx.y * 32;
    int lx = threadIdx.x, ly = threadIdx.y;
    #pragma unroll
    for (int i = 0; i < 32; i += 8)
        t[ly + i][lx] = W[(size_t)(k0 + ly + i) * HDd + c0 + lx];
    __syncthreads();
    int nbase = sel * 2048 + h * 512 + c0;
    #pragma unroll
    for (int i = 0; i < 32; i += 8)
        out[(size_t)(nbase + ly + i) * Dd + k0 + lx] = __float2half_rn(t[lx][ly + i]);
}

// ---------------------------------------------------------------------------
// LayerNorm: one block per row (D=2048), 256 threads. fp16 output.
// ---------------------------------------------------------------------------
__global__ void ln_kernel_h(const float* __restrict__ x,
                            const float* __restrict__ g,
                            const float* __restrict__ b,
                            __half* __restrict__ out) {
    int row = blockIdx.x;
    int t   = threadIdx.x;
    const float4* xr = (const float4*)(x + (size_t)row * Dd);
    float4 v0 = xr[t];
    float4 v1 = xr[t + 256];
    float s  = v0.x + v0.y + v0.z + v0.w + v1.x + v1.y + v1.z + v1.w;
    float sq = v0.x*v0.x + v0.y*v0.y + v0.z*v0.z + v0.w*v0.w
             + v1.x*v1.x + v1.y*v1.y + v1.z*v1.z + v1.w*v1.w;
    #pragma unroll
    for (int o = 16; o; o >>= 1) {
        s  += __shfl_xor_sync(0xffffffffu, s,  o);
        sq += __shfl_xor_sync(0xffffffffu, sq, o);
    }
    __shared__ float ss[8], ssq[8];
    int w = t >> 5;
    if ((t & 31) == 0) { ss[w] = s; ssq[w] = sq; }
    __syncthreads();
    float S = 0.f, SQ = 0.f;
    #pragma unroll
    for (int i = 0; i < 8; i++) { S += ss[i]; SQ += ssq[i]; }
    float mean = S * (1.f / Dd);
    float var  = SQ * (1.f / Dd) - mean * mean;
    float rstd = rsqrtf(var + LNEPS);

    const float4* gr = (const float4*)g;
    const float4* br = (const float4*)b;
    __half2* o2 = (__half2*)(out + (size_t)row * Dd);
    float4 gv = gr[t], bv = br[t];
    o2[2 * t]     = __floats2half2_rn((v0.x - mean) * rstd * gv.x + bv.x,
                                      (v0.y - mean) * rstd * gv.y + bv.y);
    o2[2 * t + 1] = __floats2half2_rn((v0.z - mean) * rstd * gv.z + bv.z,
                                      (v0.w - mean) * rstd * gv.w + bv.w);
    gv = gr[t + 256]; bv = br[t + 256];
    o2[2 * (t + 256)]     = __floats2half2_rn((v1.x - mean) * rstd * gv.x + bv.x,
                                              (v1.y - mean) * rstd * gv.y + bv.y);
    o2[2 * (t + 256) + 1] = __floats2half2_rn((v1.z - mean) * rstd * gv.z + bv.z,
                                              (v1.w - mean) * rstd * gv.w + bv.w);
}

// ---------------------------------------------------------------------------
// fp16 tensor-core GEMM: C[M,N] = A[M,K] @ Bt[N,K]^T (+bias)(+resid)(relu)
// A half [M][K] row-major (lda), Bt half [N][K] K-major (ldb).
// CTA 128x128x32, 256 threads = 8 warps (2m x 4n), warp tile 64x32,
// mma.sync.m16n8k16. A-frags ldmatrix.x4, B-frags ldmatrix.x2 (non-trans).
// 5-stage cp.async, dyn smem 100KB, 2 CTAs/SM.
// out_half: 1 = write fp16 C, 0 = write fp32 C.
// ---------------------------------------------------------------------------
#define H_STAGES 5
#define H_ROWH 40                       // halves per smem row (32 + 8 pad)
#define H_TILE_BYTES (128 * H_ROWH * 2) // 10240 per operand
#define H_STAGE_BYTES (2 * H_TILE_BYTES)
#define H_SMEM_BYTES (H_STAGES * H_STAGE_BYTES)  // 102400

__global__ void __launch_bounds__(256, 2)
hgemm(const __half* __restrict__ A, int lda,
      const __half* __restrict__ B, int ldb,
      void* __restrict__ Cvoid, int ldc,
      int K,
      const float* __restrict__ bias,
      const float* __restrict__ resid, int ldr,
      int relu, int out_half) {
    extern __shared__ __align__(16) char sm_[];
    const uint32_t smem_u = smem_u32(sm_);

    const int m0 = blockIdx.y * 128;
    const int n0 = blockIdx.x * 128;
    const int tid  = threadIdx.x;
    const int lane = tid & 31;
    const int wid  = tid >> 5;
    const int g  = lane >> 2;        // groupID
    const int t4 = lane & 3;         // thread-in-group
    const int mw = (wid >> 2) * 64;  // warp m offset
    const int nw = (wid & 3) * 32;   // warp n offset

    const int c_row0 = tid >> 2;          // 0..63
    const int c_row1 = c_row0 + 64;
    const int c_off  = (tid & 3) * 8;     // halves offset (16B chunks)

    auto issue = [&](int kt, int s) {
        const uint32_t sa = smem_u + s * H_STAGE_BYTES;
        const uint32_t sb = sa + H_TILE_BYTES;
        const __half* ap = A + (size_t)(m0) * lda + kt * 32 + c_off;
        const __half* bp = B + (size_t)(n0) * ldb + kt * 32 + c_off;
        cp_async16(sa + (uint32_t)(c_row0 * H_ROWH + c_off) * 2,
                   ap + (size_t)c_row0 * lda);
        cp_async16(sa + (uint32_t)(c_row1 * H_ROWH + c_off) * 2,
                   ap + (size_t)c_row1 * lda);
        cp_async16(sb + (uint32_t)(c_row0 * H_ROWH + c_off) * 2,
                   bp + (size_t)c_row0 * ldb);
        cp_async16(sb + (uint32_t)(c_row1 * H_ROWH + c_off) * 2,
                   bp + (size_t)c_row1 * ldb);
        cp_commit();
    };

    // ldmatrix per-lane offsets (halves)
    const int lrow = lane & 15;
    const int lcol = (lane >> 4) * 8;
    const uint32_t a_lane_off = (uint32_t)((mw + lrow) * H_ROWH + lcol);
    // B frag (x2): lanes 0-7 -> rows n+0..7 col ks*16; lanes 8-15 -> col +8
    const uint32_t b_lane_off =
        (uint32_t)((nw + (lane & 7)) * H_ROWH + ((lane >> 3) & 1) * 8);

    float acc[4][4][4];
    #pragma unroll
    for (int mi = 0; mi < 4; mi++)
        #pragma unroll
        for (int ni = 0; ni < 4; ni++)
            #pragma unroll
            for (int q = 0; q < 4; q++) acc[mi][ni][q] = 0.f;

    const int nk = K >> 5;   // K-chunks of 32 (all call sites: nk >= 16)
    issue(0, 0);
    issue(1, 1);
    issue(2, 2);
    issue(3, 3);

    for (int kt = 0; kt < nk; kt++) {
        const int cur = kt % H_STAGES;
        if (kt + 3 < nk)      cp_wait<3>();
        else if (kt + 2 < nk) cp_wait<2>();
        else if (kt + 1 < nk) cp_wait<1>();
        else                  cp_wait<0>();
        __syncthreads();
        if (kt + 4 < nk) issue(kt + 4, (kt + 4) % H_STAGES);

        const uint32_t sa_u = smem_u + cur * H_STAGE_BYTES;
        const uint32_t sb_u = sa_u + H_TILE_BYTES;
        #pragma unroll
        for (int ks = 0; ks < 2; ks++) {
            uint32_t af[4][4], bf[4][2];
            #pragma unroll
            for (int mi = 0; mi < 4; mi++)
                ldsm_x4(af[mi][0], af[mi][1], af[mi][2], af[mi][3],
                        sa_u + 2u * (a_lane_off + mi * 16 * H_ROWH + ks * 16));
            #pragma unroll
            for (int ni = 0; ni < 4; ni++)
                ldsm_x2(bf[ni][0], bf[ni][1],
                        sb_u + 2u * (b_lane_off + ni * 8 * H_ROWH + ks * 16));
            #pragma unroll
            for (int mi = 0; mi < 4; mi++)
                #pragma unroll
                for (int ni = 0; ni < 4; ni++)
                    mma_f16(acc[mi][ni], af[mi], bf[ni]);
        }
    }

    // Epilogue
    float* Cf = (float*)Cvoid;
    __half* Ch = (__half*)Cvoid;
    #pragma unroll
    for (int mi = 0; mi < 4; mi++) {
        const int r0 = m0 + mw + mi * 16 + g;
        #pragma unroll
        for (int ni = 0; ni < 4; ni++) {
            const int c0 = n0 + nw + ni * 8 + t4 * 2;
            float bb0 = 0.f, bb1 = 0.f;
            if (bias) { bb0 = bias[c0]; bb1 = bias[c0 + 1]; }
            float v0 = acc[mi][ni][0] + bb0;
            float v1 = acc[mi][ni][1] + bb1;
            float v2 = acc[mi][ni][2] + bb0;
            float v3 = acc[mi][ni][3] + bb1;
            if (resid) {
                const float* R0 = resid + (size_t)r0 * ldr + c0;
                const float* R1 = resid + (size_t)(r0 + 8) * ldr + c0;
                v0 += R0[0]; v1 += R0[1];
                v2 += R1[0]; v3 += R1[1];
            }
            if (relu) {
                v0 = fmaxf(v0, 0.f); v1 = fmaxf(v1, 0.f);
                v2 = fmaxf(v2, 0.f); v3 = fmaxf(v3, 0.f);
            }
            if (out_half) {
                *(__half2*)&Ch[(size_t)r0 * ldc + c0]       = __floats2half2_rn(v0, v1);
                *(__half2*)&Ch[(size_t)(r0 + 8) * ldc + c0] = __floats2half2_rn(v2, v3);
            } else {
                *(float2*)&Cf[(size_t)r0 * ldc + c0]       = make_float2(v0, v1);
                *(float2*)&Cf[(size_t)(r0 + 8) * ldc + c0] = make_float2(v2, v3);
            }
        }
    }
}

// ---------------------------------------------------------------------------
// Scores on tensor cores: S = scale * q k^T (fp16 in, fp32 out), causal.
// Above-diagonal tiles: NO work, NO writes (softmax never reads there).
// ---------------------------------------------------------------------------
__global__ void __launch_bounds__(256, 2)
scores_h(const __half* __restrict__ QKVh, float* __restrict__ S) {
    const int m0 = blockIdx.y * 128;
    const int n0 = blockIdx.x * 128;
    if (n0 > m0) return;   // skipped entirely

    extern __shared__ __align__(16) char sm_[];
    const uint32_t smem_u = smem_u32(sm_);

    const int z = blockIdx.z;
    const int bb = z >> 2, hh = z & 3;
    const __half* A = QKVh + (size_t)(bb * Tt) * NQKV + hh * HDd;   // q
    const __half* B = A + Dd;                                       // k
    float* Cs = S + (size_t)z * Tt * Tt;

    const int tid  = threadIdx.x;
    const int lane = tid & 31;
    const int wid  = tid >> 5;
    const int g  = lane >> 2;
    const int t4 = lane & 3;
    const int mw = (wid >> 2) * 64;
    const int nw = (wid & 3) * 32;

    const int c_row0 = tid >> 2;
    const int c_row1 = c_row0 + 64;
    const int c_off  = (tid & 3) * 8;

    auto issue = [&](int kt, int s) {
        const uint32_t sa = smem_u + s * H_STAGE_BYTES;
        const uint32_t sb = sa + H_TILE_BYTES;
        const __half* ap = A + (size_t)(m0) * NQKV + kt * 32 + c_off;
        const __half* bp = B + (size_t)(n0) * NQKV + kt * 32 + c_off;
        cp_async16(sa + (uint32_t)(c_row0 * H_ROWH + c_off) * 2,
                   ap + (size_t)c_row0 * NQKV);
        cp_async16(sa + (uint32_t)(c_row1 * H_ROWH + c_off) * 2,
                   ap + (size_t)c_row1 * NQKV);
        cp_async16(sb + (uint32_t)(c_row0 * H_ROWH + c_off) * 2,
                   bp + (size_t)c_row0 * NQKV);
        cp_async16(sb + (uint32_t)(c_row1 * H_ROWH + c_off) * 2,
                   bp + (size_t)c_row1 * NQKV);
        cp_commit();
    };

    const int lrow = lane & 15;
    const int lcol = (lane >> 4) * 8;
    const uint32_t a_lane_off = (uint32_t)((mw + lrow) * H_ROWH + lcol);
    const uint32_t b_lane_off =
        (uint32_t)((nw + (lane & 7)) * H_ROWH + ((lane >> 3) & 1) * 8);

    float acc[4][4][4];
    #pragma unroll
    for (int mi = 0; mi < 4; mi++)
        #pragma unroll
        for (int ni = 0; ni < 4; ni++)
            #pragma unroll
            for (int q = 0; q < 4; q++) acc[mi][ni][q] = 0.f;

    const int nk = HDd >> 5;   // 16
    issue(0, 0);
    issue(1, 1);
    issue(2, 2);
    issue(3, 3);

    for (int kt = 0; kt < nk; kt++) {
        const int cur = kt % H_STAGES;
        if (kt + 3 < nk)      cp_wait<3>();
        else if (kt + 2 < nk) cp_wait<2>();
        else if (kt + 1 < nk) cp_wait<1>();
        else                  cp_wait<0>();
        __syncthreads();
        if (kt + 4 < nk) issue(kt + 4, (kt + 4) % H_STAGES);

        const uint32_t sa_u = smem_u + cur * H_STAGE_BYTES;
        const uint32_t sb_u = sa_u + H_TILE_BYTES;
        #pragma unroll
        for (int ks = 0; ks < 2; ks++) {
            uint32_t af[4][4], bf[4][2];
            #pragma unroll
            for (int mi = 0; mi < 4; mi++)
                ldsm_x4(af[mi][0], af[mi][1], af[mi][2], af[mi][3],
                        sa_u + 2u * (a_lane_off + mi * 16 * H_ROWH + ks * 16));
            #pragma unroll
            for (int ni = 0; ni < 4; ni++)
                ldsm_x2(bf[ni][0], bf[ni][1],
                        sb_u + 2u * (b_lane_off + ni * 8 * H_ROWH + ks * 16));
            #pragma unroll
            for (int mi = 0; mi < 4; mi++)
                #pragma unroll
                for (int ni = 0; ni < 4; ni++)
                    mma_f16(acc[mi][ni], af[mi], bf[ni]);
        }
    }

    const float scale = 0.044194173824159216f;  // 1/sqrt(512)
    #pragma unroll
    for (int mi = 0; mi < 4; mi++) {
        const int r0 = m0 + mw + mi * 16 + g;
        #pragma unroll
        for (int ni = 0; ni < 4; ni++) {
            const int c0 = n0 + nw + ni * 8 + t4 * 2;
            float v0 = (c0     > r0)     ? -1e30f : acc[mi][ni][0] * scale;
            float v1 = (c0 + 1 > r0)     ? -1e30f : acc[mi][ni][1] * scale;
            float v2 = (c0     > r0 + 8) ? -1e30f : acc[mi][ni][2] * scale;
            float v3 = (c0 + 1 > r0 + 8) ? -1e30f : acc[mi][ni][3] * scale;
            *(float2*)&Cs[(size_t)r0 * Tt + c0]       = make_float2(v0, v1);
            *(float2*)&Cs[(size_t)(r0 + 8) * Tt + c0] = make_float2(v2, v3);
        }
    }
}

// ---------------------------------------------------------------------------
// ctx GEMM: C = probs @ V. A = probs fp16 [Tt][Tt] (per b,h). B = v read
// DIRECTLY from packed fp16 QKV in [k=s][n=c] layout (ldb = NQKV); B-frags
// via ldmatrix.x2.trans. Causal K-limit (exact: probs cols >= m0+128 are 0).
// ---------------------------------------------------------------------------
#define CB_ROWH 136                       // halves per B smem row (128 + 8)
#define CB_TILE_BYTES (32 * CB_ROWH * 2)  // 8704
#define C_STAGE_BYTES (H_TILE_BYTES + CB_TILE_BYTES)   // 18944
#define C_SMEM_BYTES (H_STAGES * C_STAGE_BYTES)        // 94720

__global__ void __launch_bounds__(256, 2)
ctx_hgemm(const __half* __restrict__ P,      // probs
          const __half* __restrict__ QKVh,
          __half* __restrict__ C) {          // ctx head-concat [BT][Dd]
    extern __shared__ __align__(16) char sm_[];
    const uint32_t smem_u = smem_u32(sm_);

    const int z = blockIdx.z;
    const int bb = z >> 2, hh = z & 3;
    const __half* A = P + (size_t)z * Tt * Tt;
    const __half* B = QKVh + (size_t)(bb * Tt) * NQKV + 4096 + hh * HDd; // v [s][c]
    __half* Cc = C + (size_t)(bb * Tt) * Dd + hh * HDd;

    const int m0 = blockIdx.y * 128;
    const int n0 = blockIdx.x * 128;
    const int tid  = threadIdx.x;
    const int lane = tid & 31;
    const int wid  = tid >> 5;
    const int g  = lane >> 2;
    const int t4 = lane & 3;
    const int mw = (wid >> 2) * 64;
    const int nw = (wid & 3) * 32;

    const int K = m0 + 128;         // causal: probs cols >= m0+128 are exactly 0

    const int c_row0 = tid >> 2;
    const int c_row1 = c_row0 + 64;
    const int c_off  = (tid & 3) * 8;
    const int b_row0 = tid >> 4;          // 0..15
    const int b_row1 = b_row0 + 16;
    const int b_c8   = (tid & 15) * 8;    // halves

    auto issue = [&](int kt, int s) {
        const uint32_t sa = smem_u + s * C_STAGE_BYTES;
        const uint32_t sb = sa + H_TILE_BYTES;
        const __half* ap = A + (size_t)(m0) * Tt + kt * 32 + c_off;
        cp_async16(sa + (uint32_t)(c_row0 * H_ROWH + c_off) * 2,
                   ap + (size_t)c_row0 * Tt);
        cp_async16(sa + (uint32_t)(c_row1 * H_ROWH + c_off) * 2,
                   ap + (size_t)c_row1 * Tt);
        const __half* bp = B + (size_t)(kt * 32) * NQKV + n0 + b_c8;
        cp_async16(sb + (uint32_t)(b_row0 * CB_ROWH + b_c8) * 2,
                   bp + (size_t)b_row0 * NQKV);
        cp_async16(sb + (uint32_t)(b_row1 * CB_ROWH + b_c8) * 2,
                   bp + (size_t)b_row1 * NQKV);
        cp_commit();
    };

    const int lrow = lane & 15;
    const int lcol = (lane >> 4) * 8;
    const uint32_t a_lane_off = (uint32_t)((mw + lrow) * H_ROWH + lcol);
    const uint32_t b_lane_row = (uint32_t)(lane & 15);   // rows for ldsm.x2.trans

    float acc[4][4][4];
    #pragma unroll
    for (int mi = 0; mi < 4; mi++)
        #pragma unroll
        for (int ni = 0; ni < 4; ni++)
            #pragma unroll
            for (int q = 0; q < 4; q++) acc[mi][ni][q] = 0.f;

    const int nk = K >> 5;   // 4..16
    issue(0, 0);
    issue(1, 1);
    issue(2, 2);
    issue(3, 3);

    for (int kt = 0; kt < nk; kt++) {
        const int cur = kt % H_STAGES;
        if (kt + 3 < nk)      cp_wait<3>();
        else if (kt + 2 < nk) cp_wait<2>();
        else if (kt + 1 < nk) cp_wait<1>();
        else                  cp_wait<0>();
        __syncthreads();
        if (kt + 4 < nk) issue(kt + 4, (kt + 4) % H_STAGES);

        const uint32_t sa_u = smem_u + cur * C_STAGE_BYTES;
        const uint32_t sb_u = sa_u + H_TILE_BYTES;
        #pragma unroll
        for (int ks = 0; ks < 2; ks++) {
            uint32_t af[4][4], bf[4][2];
            #pragma unroll
            for (int mi = 0; mi < 4; mi++)
                ldsm_x4(af[mi][0], af[mi][1], af[mi][2], af[mi][3],
                        sa_u + 2u * (a_lane_off + mi * 16 * H_ROWH + ks * 16));
            #pragma unroll
            for (int ni = 0; ni < 4; ni++)
                ldsm_x2t(bf[ni][0], bf[ni][1],
                         sb_u + 2u * ((ks * 16 + b_lane_row) * CB_ROWH
                                      + nw + ni * 8));
            #pragma unroll
            for (int mi = 0; mi < 4; mi++)
                #pragma unroll
                for (int ni = 0; ni < 4; ni++)
                    mma_f16(acc[mi][ni], af[mi], bf[ni]);
        }
    }

    #pragma unroll
    for (int mi = 0; mi < 4; mi++) {
        const int r0 = m0 + mw + mi * 16 + g;
        #pragma unroll
        for (int ni = 0; ni < 4; ni++) {
            const int c0 = n0 + nw + ni * 8 + t4 * 2;
            *(__half2*)&Cc[(size_t)r0 * Dd + c0] =
                __floats2half2_rn(acc[mi][ni][0], acc[mi][ni][1]);
            *(__half2*)&Cc[(size_t)(r0 + 8) * Dd + c0] =
                __floats2half2_rn(acc[mi][ni][2], acc[mi][ni][3]);
        }
    }
}

// ---------------------------------------------------------------------------
// Row softmax (fp32 in) -> fp16 probs. Causal: cols > i are never read
// (skipped score tiles hold garbage); probs there are written as exact 0.
// ---------------------------------------------------------------------------
__global__ void softmax_h(const float* __restrict__ S, __half* __restrict__ P) {
    int row = blockIdx.x;
    int i = row & (Tt - 1);        // position within sequence
    int t = threadIdx.x;
    const float4* p = (const float4*)(S + (size_t)row * Tt);
    float4 v;
    if (4 * t <= i) {
        v = p[t];   // elements with gj>i inside this float4 are -1e30 (masked
                    // by the diagonal score tile), never from a skipped tile
    } else {
        v = make_float4(-1e30f, -1e30f, -1e30f, -1e30f);
    }
    float m = fmaxf(fmaxf(v.x, v.y), fmaxf(v.z, v.w));
    #pragma unroll
    for (int o = 16; o; o >>= 1) m = fmaxf(m, __shfl_xor_sync(0xffffffffu, m, o));
    __shared__ float sm[4], ssum[4];
    int w = t >> 5;
    if ((t & 31) == 0) sm[w] = m;
    __syncthreads();
    m = fmaxf(fmaxf(sm[0], sm[1]), fmaxf(sm[2], sm[3]));
    v.x = expf(v.x - m); v.y = expf(v.y - m);
    v.z = expf(v.z - m); v.w = expf(v.w - m);
    float s = v.x + v.y + v.z + v.w;
    #pragma unroll
    for (int o = 16; o; o >>= 1) s += __shfl_xor_sync(0xffffffffu, s, o);
    if ((t & 31) == 0) ssum[w] = s;
    __syncthreads();
    s = ssum[0] + ssum[1] + ssum[2] + ssum[3];
    float inv = 1.f / s;
    __half2* ph = (__half2*)(P + (size_t)row * Tt);
    ph[2 * t]     = __floats2half2_rn(v.x * inv, v.y * inv);
    ph[2 * t + 1] = __floats2half2_rn(v.z * inv, v.w * inv);
}

// ---------------------------------------------------------------------------
// Host launcher
// ---------------------------------------------------------------------------
extern "C" void kernel_launch(void* const* d_in, const int* in_sizes, int n_in,
                              void* d_out, int out_size) {
    const float* x   = (const float*)d_in[0];
    const float* Wq  = (const float*)d_in[1];
    const float* Wk  = (const float*)d_in[2];
    const float* Wv  = (const float*)d_in[3];
    const float* Wo  = (const float*)d_in[4];
    const float* bo  = (const float*)d_in[5];
    const float* W1  = (const float*)d_in[6];
    const float* b1  = (const float*)d_in[7];
    const float* W2  = (const float*)d_in[8];
    const float* b2  = (const float*)d_in[9];
    const float* g1  = (const float*)d_in[10];
    const float* be1 = (const float*)d_in[11];
    const float* g2  = (const float*)d_in[12];
    const float* be2 = (const float*)d_in[13];
    float* out = (float*)d_out;

    __half *p_lnh, *p_wqkvh, *p_qkvh, *p_probs, *p_ctxh, *p_ffnh,
           *p_woth, *p_w1th, *p_w2th;
    float *p_sc;
    cudaGetSymbolAddress((void**)&p_lnh,   g_lnh);
    cudaGetSymbolAddress((void**)&p_wqkvh, g_wqkvh);
    cudaGetSymbolAddress((void**)&p_qkvh,  g_qkvh);
    cudaGetSymbolAddress((void**)&p_sc,    g_scores);
    cudaGetSymbolAddress((void**)&p_probs, g_probs);
    cudaGetSymbolAddress((void**)&p_ctxh,  g_ctxh);
    cudaGetSymbolAddress((void**)&p_ffnh,  g_ffnh);
    cudaGetSymbolAddress((void**)&p_woth,  g_woth);
    cudaGetSymbolAddress((void**)&p_w1th,  g_w1th);
    cudaGetSymbolAddress((void**)&p_w2th,  g_w2th);

    cudaFuncSetAttribute(hgemm, cudaFuncAttributeMaxDynamicSharedMemorySize,
                         H_SMEM_BYTES);
    cudaFuncSetAttribute(scores_h, cudaFuncAttributeMaxDynamicSharedMemorySize,
                         H_SMEM_BYTES);
    cudaFuncSetAttribute(ctx_hgemm, cudaFuncAttributeMaxDynamicSharedMemorySize,
                         C_SMEM_BYTES);

    // 0) weight transposes -> fp16 K-major [N][K]
    transpose_h<<<dim3(Dd / 32, Dd / 32), dim3(32, 8)>>>(Wo, p_woth, Dd, Dd);
    transpose_h<<<dim3(DFF / 32, Dd / 32), dim3(32, 8)>>>(W1, p_w1th, Dd, DFF);
    transpose_h<<<dim3(Dd / 32, DFF / 32), dim3(32, 8)>>>(W2, p_w2th, DFF, Dd);
    repack_qkv_t_h<<<dim3(HDd / 32, Dd / 32, 12), dim3(32, 8)>>>(Wq, Wk, Wv, p_wqkvh);

    // 1) h = LN(x) -> fp16
    ln_kernel_h<<<BT, 256>>>(x, g1, be1, p_lnh);

    // 2) QKV = h @ Wqkv^T -> fp16
    hgemm<<<dim3(NQKV / 128, BT / 128), 256, H_SMEM_BYTES>>>(
        p_lnh, Dd, p_wqkvh, Dd,
        p_qkvh, NQKV, Dd, nullptr, nullptr, 0, 0, 1);

    // 3) scores = scale * q k^T, causal (skipped tiles not written)
    scores_h<<<dim3(Tt / 128, Tt / 128, Bb * Hh), 256, H_SMEM_BYTES>>>(
        p_qkvh, p_sc);

    // 4) softmax -> fp16 probs (causal reads)
    softmax_h<<<Bb * Hh * Tt, 128>>>(p_sc, p_probs);

    // 5) ctx = probs @ v (v read from packed QKV via trans-ldmatrix)
    ctx_hgemm<<<dim3(HDd / 128, Tt / 128, Bb * Hh), 256, C_SMEM_BYTES>>>(
        p_probs, p_qkvh, p_ctxh);

    // 6) x2 = x + ctx @ Wo^T + bo -> d_out (fp32)
    hgemm<<<dim3(Dd / 128, BT / 128), 256, H_SMEM_BYTES>>>(
        p_ctxh, Dd, p_woth, Dd,
        out, Dd, Dd, bo, x, Dd, 0, 0);

    // 7) h2 = LN(x2) -> fp16
    ln_kernel_h<<<BT, 256>>>(out, g2, be2, p_lnh);

    // 8) u = relu(h2 @ W1^T + b1) -> fp16
    hgemm<<<dim3(DFF / 128, BT / 128), 256, H_SMEM_BYTES>>>(
        p_lnh, Dd, p_w1th, Dd,
        p_ffnh, DFF, Dd, b1, nullptr, 0, 1, 1);

    // 9) out = x2 + u @ W2^T + b2 (fp32, resid in place)
    hgemm<<<dim3(Dd / 128, BT / 128), 256, H_SMEM_BYTES>>>(
        p_ffnh, DFF, p_w2th, DFF,
        out, Dd, DFF, b2, out, Dd, 0, 0);
}

// round 16
// speedup vs baseline: 2.4547x; 1.1469x over previous
#include <cuda_runtime.h>
#include <cuda_fp16.h>
#include <math.h>
#include <stdint.h>

// Problem constants
#define Bb   16
#define Tt   512
#define Dd   2048
#define Hh   4
#define HDd  512
#define BT   8192          // B*T rows
#define NQKV 6144          // 3*D
#define DFF  8192          // 4*D
#define LNEPS 1e-5f

// ---------------------------------------------------------------------------
// Scratch (static __device__ arrays; no allocation allowed)
// ---------------------------------------------------------------------------
__device__ __align__(128) __half g_lnh[(size_t)BT * Dd];          // LN out fp16
__device__ __align__(128) __half g_wqkvh[(size_t)NQKV * Dd];      // [6144][2048] K-major
__device__ __align__(128) __half g_qkvh[(size_t)BT * NQKV];       // fp16 q,k,v
__device__ __align__(128) float  g_scores[(size_t)Bb * Hh * Tt * Tt];
__device__ __align__(128) __half g_probs[(size_t)Bb * Hh * Tt * Tt];
__device__ __align__(128) __half g_ctxh[(size_t)BT * Dd];
__device__ __align__(128) __half g_ffnh[(size_t)BT * DFF];
__device__ __align__(128) __half g_woth[(size_t)Dd * Dd];         // [2048][2048] K-major
__device__ __align__(128) __half g_w1th[(size_t)DFF * Dd];        // [8192][2048] K-major
__device__ __align__(128) __half g_w2th[(size_t)Dd * DFF];        // [2048][8192] K-major

// ---------------------------------------------------------------------------
// PTX helpers
// ---------------------------------------------------------------------------
__device__ __forceinline__ uint32_t smem_u32(const void* p) {
    uint32_t a;
    asm("{ .reg .u64 t; cvta.to.shared.u64 t, %1; cvt.u32.u64 %0, t; }"
        : "=r"(a) : "l"(p));
    return a;
}
__device__ __forceinline__ void cp_async16(uint32_t smem_dst, const void* gmem_src) {
    asm volatile("cp.async.cg.shared.global [%0], [%1], 16;\n" :: "r"(smem_dst), "l"(gmem_src));
}
__device__ __forceinline__ void cp_commit() {
    asm volatile("cp.async.commit_group;\n");
}
template<int N>
__device__ __forceinline__ void cp_wait() {
    asm volatile("cp.async.wait_group %0;\n" :: "n"(N));
}
// fp16 tensor-core mma: D(f32) += A(f16,m16k16,row) * B(f16,n8k16,col)
__device__ __forceinline__ void mma_f16(float* c, const uint32_t* a, const uint32_t* b) {
    asm volatile(
        "mma.sync.aligned.m16n8k16.row.col.f32.f16.f16.f32 "
        "{%0,%1,%2,%3}, {%4,%5,%6,%7}, {%8,%9}, {%0,%1,%2,%3};"
        : "+f"(c[0]), "+f"(c[1]), "+f"(c[2]), "+f"(c[3])
        : "r"(a[0]), "r"(a[1]), "r"(a[2]), "r"(a[3]), "r"(b[0]), "r"(b[1]));
}
// ldmatrix x4: one full m16k16 fp16 A fragment.
__device__ __forceinline__ void ldsm_x4(uint32_t& r0, uint32_t& r1,
                                        uint32_t& r2, uint32_t& r3,
                                        uint32_t addr) {
    asm volatile(
        "ldmatrix.sync.aligned.m8n8.x4.shared.b16 {%0,%1,%2,%3}, [%4];"
        : "=r"(r0), "=r"(r1), "=r"(r2), "=r"(r3) : "r"(addr));
}
// ldmatrix x2 (non-trans): one n8k16 fp16 B fragment from K-major [n][k] smem.
__device__ __forceinline__ void ldsm_x2(uint32_t& r0, uint32_t& r1, uint32_t addr) {
    asm volatile(
        "ldmatrix.sync.aligned.m8n8.x2.shared.b16 {%0,%1}, [%2];"
        : "=r"(r0), "=r"(r1) : "r"(addr));
}
// ldmatrix x2 transposed: one n8k16 fp16 B fragment from [k][n] row-major smem.
__device__ __forceinline__ void ldsm_x2t(uint32_t& r0, uint32_t& r1, uint32_t addr) {
    asm volatile(
        "ldmatrix.sync.aligned.m8n8.x2.trans.shared.b16 {%0,%1}, [%2];"
        : "=r"(r0), "=r"(r1) : "r"(addr));
}

// ---------------------------------------------------------------------------
// Weight transpose + fp16 convert:  out[N][K] = half(in[K][N])
// Tile 64(k) x 32(n), half2 stores. Grid (N/32, K/64), block (32,8).
// ---------------------------------------------------------------------------
__global__ void transpose_h(const float* __restrict__ in,
                            __half* __restrict__ out, int K, int N) {
    __shared__ float t[64][33];
    int n0 = blockIdx.x * 32, k0 = blockIdx.y * 64;
    int lx = threadIdx.x, ly = threadIdx.y;
    #pragma unroll
    for (int r = 0; r < 64; r += 8)
        t[r + ly][lx] = in[(size_t)(k0 + r + ly) * N + n0 + lx];
    __syncthreads();
    #pragma unroll
    for (int r = 0; r < 32; r += 8) {
        int row = r + ly;
        *(__half2*)&out[(size_t)(n0 + row) * K + k0 + 2 * lx] =
            __floats2half2_rn(t[2 * lx][row], t[2 * lx + 1][row]);
    }
}

// Repack+transpose Wq/Wk/Wv [H,D,HD] -> half [3D][D] K-major.
// Tile 64(k) x 32(c). Grid (HDd/32, Dd/64, 12), block (32,8).
__global__ void repack_qkv_t_h(const float* __restrict__ Wq,
                               const float* __restrict__ Wk,
                               const float* __restrict__ Wv,
                               __half* __restrict__ out) {
    __shared__ float t[64][33];
    int z = blockIdx.z;
    int sel = z >> 2, h = z & 3;
    const float* W = (sel == 0 ? Wq : sel == 1 ? Wk : Wv) + (size_t)h * Dd * HDd;
    int c0 = blockIdx.x * 32, k0 = blockIdx.y * 64;
    int lx = threadIdx.x, ly = threadIdx.y;
    #pragma unroll
    for (int r = 0; r < 64; r += 8)
        t[r + ly][lx] = W[(size_t)(k0 + r + ly) * HDd + c0 + lx];
    __syncthreads();
    int nbase = sel * 2048 + h * 512 + c0;
    #pragma unroll
    for (int r = 0; r < 32; r += 8) {
        int row = r + ly;
        *(__half2*)&out[(size_t)(nbase + row) * Dd + k0 + 2 * lx] =
            __floats2half2_rn(t[2 * lx][row], t[2 * lx + 1][row]);
    }
}

// ---------------------------------------------------------------------------
// LayerNorm: one block per row (D=2048), 256 threads. fp16 output.
// ---------------------------------------------------------------------------
__global__ void ln_kernel_h(const float* __restrict__ x,
                            const float* __restrict__ g,
                            const float* __restrict__ b,
                            __half* __restrict__ out) {
    int row = blockIdx.x;
    int t   = threadIdx.x;
    const float4* xr = (const float4*)(x + (size_t)row * Dd);
    float4 v0 = xr[t];
    float4 v1 = xr[t + 256];
    float s  = v0.x + v0.y + v0.z + v0.w + v1.x + v1.y + v1.z + v1.w;
    float sq = v0.x*v0.x + v0.y*v0.y + v0.z*v0.z + v0.w*v0.w
             + v1.x*v1.x + v1.y*v1.y + v1.z*v1.z + v1.w*v1.w;
    #pragma unroll
    for (int o = 16; o; o >>= 1) {
        s  += __shfl_xor_sync(0xffffffffu, s,  o);
        sq += __shfl_xor_sync(0xffffffffu, sq, o);
    }
    __shared__ float ss[8], ssq[8];
    int w = t >> 5;
    if ((t & 31) == 0) { ss[w] = s; ssq[w] = sq; }
    __syncthreads();
    float S = 0.f, SQ = 0.f;
    #pragma unroll
    for (int i = 0; i < 8; i++) { S += ss[i]; SQ += ssq[i]; }
    float mean = S * (1.f / Dd);
    float var  = SQ * (1.f / Dd) - mean * mean;
    float rstd = rsqrtf(var + LNEPS);

    const float4* gr = (const float4*)g;
    const float4* br = (const float4*)b;
    __half2* o2 = (__half2*)(out + (size_t)row * Dd);
    float4 gv = gr[t], bv = br[t];
    o2[2 * t]     = __floats2half2_rn((v0.x - mean) * rstd * gv.x + bv.x,
                                      (v0.y - mean) * rstd * gv.y + bv.y);
    o2[2 * t + 1] = __floats2half2_rn((v0.z - mean) * rstd * gv.z + bv.z,
                                      (v0.w - mean) * rstd * gv.w + bv.w);
    gv = gr[t + 256]; bv = br[t + 256];
    o2[2 * (t + 256)]     = __floats2half2_rn((v1.x - mean) * rstd * gv.x + bv.x,
                                              (v1.y - mean) * rstd * gv.y + bv.y);
    o2[2 * (t + 256) + 1] = __floats2half2_rn((v1.z - mean) * rstd * gv.z + bv.z,
                                              (v1.w - mean) * rstd * gv.w + bv.w);
}

// ---------------------------------------------------------------------------
// fp16 tensor-core GEMM: C[M,N] = A[M,K] @ Bt[N,K]^T (+bias)(+resid)(relu)
// A half [M][K] row-major (lda), Bt half [N][K] K-major (ldb).
// CTA 128x128, K-chunk 64 per stage, 3-stage cp.async (128-deep prefetch),
// 256 threads = 8 warps (2m x 4n), warp tile 64x32, mma.sync.m16n8k16.
// A-frags ldmatrix.x4, B-frags ldmatrix.x2. One __syncthreads per 64-K.
// out_half: 1 = write fp16 C, 0 = write fp32 C.
// ---------------------------------------------------------------------------
#define H_STAGES 3
#define H_ROWH 72                       // halves per smem row (64 + 8 pad)
#define H_TILE_BYTES (128 * H_ROWH * 2) // 18432 per operand
#define H_STAGE_BYTES (2 * H_TILE_BYTES)
#define H_SMEM_BYTES (H_STAGES * H_STAGE_BYTES)  // 110592

__global__ void __launch_bounds__(256, 2)
hgemm(const __half* __restrict__ A, int lda,
      const __half* __restrict__ B, int ldb,
      void* __restrict__ Cvoid, int ldc,
      int K,
      const float* __restrict__ bias,
      const float* __restrict__ resid, int ldr,
      int relu, int out_half) {
    extern __shared__ __align__(16) char sm_[];
    const uint32_t smem_u = smem_u32(sm_);

    const int m0 = blockIdx.y * 128;
    const int n0 = blockIdx.x * 128;
    const int tid  = threadIdx.x;
    const int lane = tid & 31;
    const int wid  = tid >> 5;
    const int g  = lane >> 2;        // groupID
    const int t4 = lane & 3;         // thread-in-group
    const int mw = (wid >> 2) * 64;  // warp m offset
    const int nw = (wid & 3) * 32;   // warp n offset

    // fill: tile = 128 rows x 64 halves = 1024 16B-chunks per operand; 4/thread
    const int c_row = tid >> 3;           // 0..31
    const int c_off = (tid & 7) * 8;      // halves

    auto issue = [&](int kt, int s) {
        const uint32_t sa = smem_u + s * H_STAGE_BYTES;
        const uint32_t sb = sa + H_TILE_BYTES;
        const __half* ap = A + (size_t)(m0) * lda + kt * 64 + c_off;
        const __half* bp = B + (size_t)(n0) * ldb + kt * 64 + c_off;
        #pragma unroll
        for (int p = 0; p < 4; p++) {
            int r = c_row + p * 32;
            cp_async16(sa + (uint32_t)(r * H_ROWH + c_off) * 2,
                       ap + (size_t)r * lda);
            cp_async16(sb + (uint32_t)(r * H_ROWH + c_off) * 2,
                       bp + (size_t)r * ldb);
        }
        cp_commit();
    };

    // ldmatrix per-lane offsets (halves)
    const int lrow = lane & 15;
    const int lcol = (lane >> 4) * 8;
    const uint32_t a_lane_off = (uint32_t)((mw + lrow) * H_ROWH + lcol);
    const uint32_t b_lane_off =
        (uint32_t)((nw + (lane & 7)) * H_ROWH + ((lane >> 3) & 1) * 8);

    float acc[4][4][4];
    #pragma unroll
    for (int mi = 0; mi < 4; mi++)
        #pragma unroll
        for (int ni = 0; ni < 4; ni++)
            #pragma unroll
            for (int q = 0; q < 4; q++) acc[mi][ni][q] = 0.f;

    const int nk = K >> 6;   // K-chunks of 64 (all call sites: nk >= 2)
    issue(0, 0);
    issue(1, 1);

    for (int kt = 0; kt < nk; kt++) {
        const int cur = kt % H_STAGES;
        if (kt + 1 < nk) cp_wait<1>();
        else             cp_wait<0>();
        __syncthreads();
        if (kt + 2 < nk) issue(kt + 2, (kt + 2) % H_STAGES);

        const uint32_t sa_u = smem_u + cur * H_STAGE_BYTES;
        const uint32_t sb_u = sa_u + H_TILE_BYTES;
        #pragma unroll
        for (int ks = 0; ks < 4; ks++) {
            uint32_t af[4][4], bf[4][2];
            #pragma unroll
            for (int mi = 0; mi < 4; mi++)
                ldsm_x4(af[mi][0], af[mi][1], af[mi][2], af[mi][3],
                        sa_u + 2u * (a_lane_off + mi * 16 * H_ROWH + ks * 16));
            #pragma unroll
            for (int ni = 0; ni < 4; ni++)
                ldsm_x2(bf[ni][0], bf[ni][1],
                        sb_u + 2u * (b_lane_off + ni * 8 * H_ROWH + ks * 16));
            #pragma unroll
            for (int mi = 0; mi < 4; mi++)
                #pragma unroll
                for (int ni = 0; ni < 4; ni++)
                    mma_f16(acc[mi][ni], af[mi], bf[ni]);
        }
    }

    // Epilogue
    float* Cf = (float*)Cvoid;
    __half* Ch = (__half*)Cvoid;
    #pragma unroll
    for (int mi = 0; mi < 4; mi++) {
        const int r0 = m0 + mw + mi * 16 + g;
        #pragma unroll
        for (int ni = 0; ni < 4; ni++) {
            const int c0 = n0 + nw + ni * 8 + t4 * 2;
            float bb0 = 0.f, bb1 = 0.f;
            if (bias) { bb0 = bias[c0]; bb1 = bias[c0 + 1]; }
            float v0 = acc[mi][ni][0] + bb0;
            float v1 = acc[mi][ni][1] + bb1;
            float v2 = acc[mi][ni][2] + bb0;
            float v3 = acc[mi][ni][3] + bb1;
            if (resid) {
                const float* R0 = resid + (size_t)r0 * ldr + c0;
                const float* R1 = resid + (size_t)(r0 + 8) * ldr + c0;
                v0 += R0[0]; v1 += R0[1];
                v2 += R1[0]; v3 += R1[1];
            }
            if (relu) {
                v0 = fmaxf(v0, 0.f); v1 = fmaxf(v1, 0.f);
                v2 = fmaxf(v2, 0.f); v3 = fmaxf(v3, 0.f);
            }
            if (out_half) {
                *(__half2*)&Ch[(size_t)r0 * ldc + c0]       = __floats2half2_rn(v0, v1);
                *(__half2*)&Ch[(size_t)(r0 + 8) * ldc + c0] = __floats2half2_rn(v2, v3);
            } else {
                *(float2*)&Cf[(size_t)r0 * ldc + c0]       = make_float2(v0, v1);
                *(float2*)&Cf[(size_t)(r0 + 8) * ldc + c0] = make_float2(v2, v3);
            }
        }
    }
}

// ---------------------------------------------------------------------------
// Scores on tensor cores: S = scale * q k^T (fp16 in, fp32 out), causal.
// Above-diagonal tiles: NO work, NO writes (softmax never reads there).
// ---------------------------------------------------------------------------
__global__ void __launch_bounds__(256, 2)
scores_h(const __half* __restrict__ QKVh, float* __restrict__ S) {
    const int m0 = blockIdx.y * 128;
    const int n0 = blockIdx.x * 128;
    if (n0 > m0) return;   // skipped entirely

    extern __shared__ __align__(16) char sm_[];
    const uint32_t smem_u = smem_u32(sm_);

    const int z = blockIdx.z;
    const int bb = z >> 2, hh = z & 3;
    const __half* A = QKVh + (size_t)(bb * Tt) * NQKV + hh * HDd;   // q
    const __half* B = A + Dd;                                       // k
    float* Cs = S + (size_t)z * Tt * Tt;

    const int tid  = threadIdx.x;
    const int lane = tid & 31;
    const int wid  = tid >> 5;
    const int g  = lane >> 2;
    const int t4 = lane & 3;
    const int mw = (wid >> 2) * 64;
    const int nw = (wid & 3) * 32;

    const int c_row = tid >> 3;
    const int c_off = (tid & 7) * 8;

    auto issue = [&](int kt, int s) {
        const uint32_t sa = smem_u + s * H_STAGE_BYTES;
        const uint32_t sb = sa + H_TILE_BYTES;
        const __half* ap = A + (size_t)(m0) * NQKV + kt * 64 + c_off;
        const __half* bp = B + (size_t)(n0) * NQKV + kt * 64 + c_off;
        #pragma unroll
        for (int p = 0; p < 4; p++) {
            int r = c_row + p * 32;
            cp_async16(sa + (uint32_t)(r * H_ROWH + c_off) * 2,
                       ap + (size_t)r * NQKV);
            cp_async16(sb + (uint32_t)(r * H_ROWH + c_off) * 2,
                       bp + (size_t)r * NQKV);
        }
        cp_commit();
    };

    const int lrow = lane & 15;
    const int lcol = (lane >> 4) * 8;
    const uint32_t a_lane_off = (uint32_t)((mw + lrow) * H_ROWH + lcol);
    const uint32_t b_lane_off =
        (uint32_t)((nw + (lane & 7)) * H_ROWH + ((lane >> 3) & 1) * 8);

    float acc[4][4][4];
    #pragma unroll
    for (int mi = 0; mi < 4; mi++)
        #pragma unroll
        for (int ni = 0; ni < 4; ni++)
            #pragma unroll
            for (int q = 0; q < 4; q++) acc[mi][ni][q] = 0.f;

    const int nk = HDd >> 6;   // 8
    issue(0, 0);
    issue(1, 1);

    for (int kt = 0; kt < nk; kt++) {
        const int cur = kt % H_STAGES;
        if (kt + 1 < nk) cp_wait<1>();
        else             cp_wait<0>();
        __syncthreads();
        if (kt + 2 < nk) issue(kt + 2, (kt + 2) % H_STAGES);

        const uint32_t sa_u = smem_u + cur * H_STAGE_BYTES;
        const uint32_t sb_u = sa_u + H_TILE_BYTES;
        #pragma unroll
        for (int ks = 0; ks < 4; ks++) {
            uint32_t af[4][4], bf[4][2];
            #pragma unroll
            for (int mi = 0; mi < 4; mi++)
                ldsm_x4(af[mi][0], af[mi][1], af[mi][2], af[mi][3],
                        sa_u + 2u * (a_lane_off + mi * 16 * H_ROWH + ks * 16));
            #pragma unroll
            for (int ni = 0; ni < 4; ni++)
                ldsm_x2(bf[ni][0], bf[ni][1],
                        sb_u + 2u * (b_lane_off + ni * 8 * H_ROWH + ks * 16));
            #pragma unroll
            for (int mi = 0; mi < 4; mi++)
                #pragma unroll
                for (int ni = 0; ni < 4; ni++)
                    mma_f16(acc[mi][ni], af[mi], bf[ni]);
        }
    }

    const float scale = 0.044194173824159216f;  // 1/sqrt(512)
    #pragma unroll
    for (int mi = 0; mi < 4; mi++) {
        const int r0 = m0 + mw + mi * 16 + g;
        #pragma unroll
        for (int ni = 0; ni < 4; ni++) {
            const int c0 = n0 + nw + ni * 8 + t4 * 2;
            float v0 = (c0     > r0)     ? -1e30f : acc[mi][ni][0] * scale;
            float v1 = (c0 + 1 > r0)     ? -1e30f : acc[mi][ni][1] * scale;
            float v2 = (c0     > r0 + 8) ? -1e30f : acc[mi][ni][2] * scale;
            float v3 = (c0 + 1 > r0 + 8) ? -1e30f : acc[mi][ni][3] * scale;
            *(float2*)&Cs[(size_t)r0 * Tt + c0]       = make_float2(v0, v1);
            *(float2*)&Cs[(size_t)(r0 + 8) * Tt + c0] = make_float2(v2, v3);
        }
    }
}

// ---------------------------------------------------------------------------
// ctx GEMM: C = probs @ V. A = probs fp16 [Tt][Tt] (per b,h). B = v read
// DIRECTLY from packed fp16 QKV in [k=s][n=c] layout (ldb = NQKV); B-frags
// via ldmatrix.x2.trans. Causal K-limit (exact: probs cols >= m0+128 are 0).
// K-chunk 64, 3 stages.
// ---------------------------------------------------------------------------
#define CB_ROWH 136                       // halves per B smem row (128 + 8)
#define CB_TILE_BYTES (64 * CB_ROWH * 2)  // 17408
#define C_STAGE_BYTES (H_TILE_BYTES + CB_TILE_BYTES)   // 35840
#define C_SMEM_BYTES (H_STAGES * C_STAGE_BYTES)        // 107520

__global__ void __launch_bounds__(256, 2)
ctx_hgemm(const __half* __restrict__ P,      // probs
          const __half* __restrict__ QKVh,
          __half* __restrict__ C) {          // ctx head-concat [BT][Dd]
    extern __shared__ __align__(16) char sm_[];
    const uint32_t smem_u = smem_u32(sm_);

    const int z = blockIdx.z;
    const int bb = z >> 2, hh = z & 3;
    const __half* A = P + (size_t)z * Tt * Tt;
    const __half* B = QKVh + (size_t)(bb * Tt) * NQKV + 4096 + hh * HDd; // v [s][c]
    __half* Cc = C + (size_t)(bb * Tt) * Dd + hh * HDd;

    const int m0 = blockIdx.y * 128;
    const int n0 = blockIdx.x * 128;
    const int tid  = threadIdx.x;
    const int lane = tid & 31;
    const int wid  = tid >> 5;
    const int g  = lane >> 2;
    const int t4 = lane & 3;
    const int mw = (wid >> 2) * 64;
    const int nw = (wid & 3) * 32;

    const int K = m0 + 128;         // causal: probs cols >= m0+128 are exactly 0

    // A fill: 128 rows x 64 halves, 4 chunks/thread
    const int c_row = tid >> 3;
    const int c_off = (tid & 7) * 8;
    // B fill: 64 k-rows x 128 n-halves = 1024 chunks, 4/thread
    const int b_row = tid >> 4;           // 0..15
    const int b_c8  = (tid & 15) * 8;     // halves

    auto issue = [&](int kt, int s) {
        const uint32_t sa = smem_u + s * C_STAGE_BYTES;
        const uint32_t sb = sa + H_TILE_BYTES;
        const __half* ap = A + (size_t)(m0) * Tt + kt * 64 + c_off;
        #pragma unroll
        for (int p = 0; p < 4; p++) {
            int r = c_row + p * 32;
            cp_async16(sa + (uint32_t)(r * H_ROWH + c_off) * 2,
                       ap + (size_t)r * Tt);
        }
        const __half* bp = B + (size_t)(kt * 64) * NQKV + n0 + b_c8;
        #pragma unroll
        for (int p = 0; p < 4; p++) {
            int r = b_row + p * 16;
            cp_async16(sb + (uint32_t)(r * CB_ROWH + b_c8) * 2,
                       bp + (size_t)r * NQKV);
        }
        cp_commit();
    };

    const int lrow = lane & 15;
    const int lcol = (lane >> 4) * 8;
    const uint32_t a_lane_off = (uint32_t)((mw + lrow) * H_ROWH + lcol);
    const uint32_t b_lane_row = (uint32_t)(lane & 15);   // rows for ldsm.x2.trans

    float acc[4][4][4];
    #pragma unroll
    for (int mi = 0; mi < 4; mi++)
        #pragma unroll
        for (int ni = 0; ni < 4; ni++)
            #pragma unroll
            for (int q = 0; q < 4; q++) acc[mi][ni][q] = 0.f;

    const int nk = K >> 6;   // 2..8
    issue(0, 0);
    issue(1, 1);

    for (int kt = 0; kt < nk; kt++) {
        const int cur = kt % H_STAGES;
        if (kt + 1 < nk) cp_wait<1>();
        else             cp_wait<0>();
        __syncthreads();
        if (kt + 2 < nk) issue(kt + 2, (kt + 2) % H_STAGES);

        const uint32_t sa_u = smem_u + cur * C_STAGE_BYTES;
        const uint32_t sb_u = sa_u + H_TILE_BYTES;
        #pragma unroll
        for (int ks = 0; ks < 4; ks++) {
            uint32_t af[4][4], bf[4][2];
            #pragma unroll
            for (int mi = 0; mi < 4; mi++)
                ldsm_x4(af[mi][0], af[mi][1], af[mi][2], af[mi][3],
                        sa_u + 2u * (a_lane_off + mi * 16 * H_ROWH + ks * 16));
            #pragma unroll
            for (int ni = 0; ni < 4; ni++)
                ldsm_x2t(bf[ni][0], bf[ni][1],
                         sb_u + 2u * ((ks * 16 + b_lane_row) * CB_ROWH
                                      + nw + ni * 8));
            #pragma unroll
            for (int mi = 0; mi < 4; mi++)
                #pragma unroll
                for (int ni = 0; ni < 4; ni++)
                    mma_f16(acc[mi][ni], af[mi], bf[ni]);
        }
    }

    #pragma unroll
    for (int mi = 0; mi < 4; mi++) {
        const int r0 = m0 + mw + mi * 16 + g;
        #pragma unroll
        for (int ni = 0; ni < 4; ni++) {
            const int c0 = n0 + nw + ni * 8 + t4 * 2;
            *(__half2*)&Cc[(size_t)r0 * Dd + c0] =
                __floats2half2_rn(acc[mi][ni][0], acc[mi][ni][1]);
            *(__half2*)&Cc[(size_t)(r0 + 8) * Dd + c0] =
                __floats2half2_rn(acc[mi][ni][2], acc[mi][ni][3]);
        }
    }
}

// ---------------------------------------------------------------------------
// Row softmax (fp32 in) -> fp16 probs. Causal: cols > i never read from
// scores (skipped tiles hold garbage); probs cols >= ((i/128)+1)*128 are
// never read by ctx (causal K-limit) and are NOT written.
// ---------------------------------------------------------------------------
__global__ void softmax_h(const float* __restrict__ S, __half* __restrict__ P) {
    int row = blockIdx.x;
    int i = row & (Tt - 1);        // position within sequence
    int t = threadIdx.x;
    const float4* p = (const float4*)(S + (size_t)row * Tt);
    float4 v;
    if (4 * t <= i) {
        v = p[t];
    } else {
        v = make_float4(-1e30f, -1e30f, -1e30f, -1e30f);
    }
    float m = fmaxf(fmaxf(v.x, v.y), fmaxf(v.z, v.w));
    #pragma unroll
    for (int o = 16; o; o >>= 1) m = fmaxf(m, __shfl_xor_sync(0xffffffffu, m, o));
    __shared__ float sm[4], ssum[4];
    int w = t >> 5;
    if ((t & 31) == 0) sm[w] = m;
    __syncthreads();
    m = fmaxf(fmaxf(sm[0], sm[1]), fmaxf(sm[2], sm[3]));
    v.x = expf(v.x - m); v.y = expf(v.y - m);
    v.z = expf(v.z - m); v.w = expf(v.w - m);
    float s = v.x + v.y + v.z + v.w;
    #pragma unroll
    for (int o = 16; o; o >>= 1) s += __shfl_xor_sync(0xffffffffu, s, o);
    if ((t & 31) == 0) ssum[w] = s;
    __syncthreads();
    s = ssum[0] + ssum[1] + ssum[2] + ssum[3];
    float inv = 1.f / s;
    const int lim4 = (((i >> 7) + 1) << 7) >> 2;   // threads with 4t < tile limit
    if (t < lim4) {
        __half2* ph = (__half2*)(P + (size_t)row * Tt);
        ph[2 * t]     = __floats2half2_rn(v.x * inv, v.y * inv);
        ph[2 * t + 1] = __floats2half2_rn(v.z * inv, v.w * inv);
    }
}

// ---------------------------------------------------------------------------
// Host launcher
// ---------------------------------------------------------------------------
extern "C" void kernel_launch(void* const* d_in, const int* in_sizes, int n_in,
                              void* d_out, int out_size) {
    const float* x   = (const float*)d_in[0];
    const float* Wq  = (const float*)d_in[1];
    const float* Wk  = (const float*)d_in[2];
    const float* Wv  = (const float*)d_in[3];
    const float* Wo  = (const float*)d_in[4];
    const float* bo  = (const float*)d_in[5];
    const float* W1  = (const float*)d_in[6];
    const float* b1  = (const float*)d_in[7];
    const float* W2  = (const float*)d_in[8];
    const float* b2  = (const float*)d_in[9];
    const float* g1  = (const float*)d_in[10];
    const float* be1 = (const float*)d_in[11];
    const float* g2  = (const float*)d_in[12];
    const float* be2 = (const float*)d_in[13];
    float* out = (float*)d_out;

    __half *p_lnh, *p_wqkvh, *p_qkvh, *p_probs, *p_ctxh, *p_ffnh,
           *p_woth, *p_w1th, *p_w2th;
    float *p_sc;
    cudaGetSymbolAddress((void**)&p_lnh,   g_lnh);
    cudaGetSymbolAddress((void**)&p_wqkvh, g_wqkvh);
    cudaGetSymbolAddress((void**)&p_qkvh,  g_qkvh);
    cudaGetSymbolAddress((void**)&p_sc,    g_scores);
    cudaGetSymbolAddress((void**)&p_probs, g_probs);
    cudaGetSymbolAddress((void**)&p_ctxh,  g_ctxh);
    cudaGetSymbolAddress((void**)&p_ffnh,  g_ffnh);
    cudaGetSymbolAddress((void**)&p_woth,  g_woth);
    cudaGetSymbolAddress((void**)&p_w1th,  g_w1th);
    cudaGetSymbolAddress((void**)&p_w2th,  g_w2th);

    cudaFuncSetAttribute(hgemm, cudaFuncAttributeMaxDynamicSharedMemorySize,
                         H_SMEM_BYTES);
    cudaFuncSetAttribute(scores_h, cudaFuncAttributeMaxDynamicSharedMemorySize,
                         H_SMEM_BYTES);
    cudaFuncSetAttribute(ctx_hgemm, cudaFuncAttributeMaxDynamicSharedMemorySize,
                         C_SMEM_BYTES);

    // 0) weight transposes -> fp16 K-major [N][K]
    transpose_h<<<dim3(Dd / 32, Dd / 64), dim3(32, 8)>>>(Wo, p_woth, Dd, Dd);
    transpose_h<<<dim3(DFF / 32, Dd / 64), dim3(32, 8)>>>(W1, p_w1th, Dd, DFF);
    transpose_h<<<dim3(Dd / 32, DFF / 64), dim3(32, 8)>>>(W2, p_w2th, DFF, Dd);
    repack_qkv_t_h<<<dim3(HDd / 32, Dd / 64, 12), dim3(32, 8)>>>(Wq, Wk, Wv, p_wqkvh);

    // 1) h = LN(x) -> fp16
    ln_kernel_h<<<BT, 256>>>(x, g1, be1, p_lnh);

    // 2) QKV = h @ Wqkv^T -> fp16
    hgemm<<<dim3(NQKV / 128, BT / 128), 256, H_SMEM_BYTES>>>(
        p_lnh, Dd, p_wqkvh, Dd,
        p_qkvh, NQKV, Dd, nullptr, nullptr, 0, 0, 1);

    // 3) scores = scale * q k^T, causal (skipped tiles not written)
    scores_h<<<dim3(Tt / 128, Tt / 128, Bb * Hh), 256, H_SMEM_BYTES>>>(
        p_qkvh, p_sc);

    // 4) softmax -> fp16 probs (causal reads + writes)
    softmax_h<<<Bb * Hh * Tt, 128>>>(p_sc, p_probs);

    // 5) ctx = probs @ v (v read from packed QKV via trans-ldmatrix)
    ctx_hgemm<<<dim3(HDd / 128, Tt / 128, Bb * Hh), 256, C_SMEM_BYTES>>>(
        p_probs, p_qkvh, p_ctxh);

    // 6) x2 = x + ctx @ Wo^T + bo -> d_out (fp32)
    hgemm<<<dim3(Dd / 128, BT / 128), 256, H_SMEM_BYTES>>>(
        p_ctxh, Dd, p_woth, Dd,
        out, Dd, Dd, bo, x, Dd, 0, 0);

    // 7) h2 = LN(x2) -> fp16
    ln_kernel_h<<<BT, 256>>>(out, g2, be2, p_lnh);

    // 8) u = relu(h2 @ W1^T + b1) -> fp16
    hgemm<<<dim3(DFF / 128, BT / 128), 256, H_SMEM_BYTES>>>(
        p_lnh, Dd, p_w1th, Dd,
        p_ffnh, DFF, Dd, b1, nullptr, 0, 1, 1);

    // 9) out = x2 + u @ W2^T + b2 (fp32, resid in place)
    hgemm<<<dim3(Dd / 128, BT / 128), 256, H_SMEM_BYTES>>>(
        p_ffnh, DFF, p_w2th, DFF,
        out, Dd, DFF, b2, out, Dd, 0, 0);
}